// round 1
// baseline (speedup 1.0000x reference)
#include <cuda_runtime.h>
#include <math.h>

#define M_TRAIN 4096
#define M_TEST  16384
#define DIN     128
#define HID     1024
#define NTREES  16
#define NINT    31
#define NLEAF   32
#define NCLS    10
#define NSPLIT  (NTREES*NINT)        /* 496 */
#define SW_ROWS (NTREES*NINT*DIN)    /* 63488 */
#define LF_ROWS (NTREES*NLEAF*NCLS)  /* 5120 */

/* ---------------- scratch (static device memory; no allocs) -------------- */
__device__ float g_C1[M_TRAIN*HID];        /* 16 MB: GEMM1 out -> H1 in-place */
__device__ float g_C2[M_TRAIN*HID];        /* 16 MB: GEMM2 out -> H2 in-place */
__device__ float g_part[64*HID];
__device__ float g_ctx[HID];
__device__ float g_sw[SW_ROWS];            /* split_w as [496][128] row-major */
__device__ float g_sb[NSPLIT];
__device__ float g_lf[LF_ROWS];
__device__ float g_tw[NTREES];
__device__ float g_W[LF_ROWS];             /* softmax(leaf)*tree_w folded */
__device__ float g_dec[NSPLIT*M_TEST];     /* 32.5 MB, TRANSPOSED [496][16384] */

/* --------------- tiled GEMM: C[M,N] = A[M,K] @ B[N,K]^T + bias ----------- */
/* EPI 0: plain row-major store.  EPI 1: sigmoid, store transposed C[N][M].  */
template<int EPI>
__global__ void gemm_bias(const float* __restrict__ A, const float* __restrict__ B,
                          const float* __restrict__ bias, float* __restrict__ C,
                          int M, int N, int K)
{
    __shared__ float As[16][68];
    __shared__ float Bs[16][68];
    const int tid = threadIdx.x;
    const int m0 = blockIdx.y * 64, n0 = blockIdx.x * 64;
    const int lr = tid >> 2;           /* 0..63 */
    const int lc = (tid & 3) * 4;      /* 0,4,8,12 */
    const int ty = tid >> 4, tx = tid & 15;

    float acc[4][4];
#pragma unroll
    for (int i = 0; i < 4; i++)
#pragma unroll
        for (int j = 0; j < 4; j++) acc[i][j] = 0.f;

    for (int k0 = 0; k0 < K; k0 += 16) {
        float4 av = *(const float4*)&A[(size_t)(m0 + lr) * K + k0 + lc];
        As[lc+0][lr] = av.x; As[lc+1][lr] = av.y;
        As[lc+2][lr] = av.z; As[lc+3][lr] = av.w;

        float4 bv = make_float4(0.f, 0.f, 0.f, 0.f);
        if (n0 + lr < N)
            bv = *(const float4*)&B[(size_t)(n0 + lr) * K + k0 + lc];
        Bs[lc+0][lr] = bv.x; Bs[lc+1][lr] = bv.y;
        Bs[lc+2][lr] = bv.z; Bs[lc+3][lr] = bv.w;
        __syncthreads();

#pragma unroll
        for (int k = 0; k < 16; k++) {
            float a[4], b[4];
#pragma unroll
            for (int i = 0; i < 4; i++) a[i] = As[k][ty*4 + i];
#pragma unroll
            for (int j = 0; j < 4; j++) b[j] = Bs[k][tx*4 + j];
#pragma unroll
            for (int i = 0; i < 4; i++)
#pragma unroll
                for (int j = 0; j < 4; j++) acc[i][j] += a[i] * b[j];
        }
        __syncthreads();
    }

#pragma unroll
    for (int i = 0; i < 4; i++) {
        int row = m0 + ty*4 + i;
#pragma unroll
        for (int j = 0; j < 4; j++) {
            int col = n0 + tx*4 + j;
            if (col < N) {
                float v = acc[i][j] + bias[col];
                if (EPI == 0) {
                    C[(size_t)row * N + col] = v;
                } else {
                    C[(size_t)col * M + row] = 1.f / (1.f + expf(-v));
                }
            }
        }
    }
}

/* --------------------- per-row LayerNorm + ReLU, in-place ---------------- */
__global__ void ln_relu_kernel(float* __restrict__ X, const float* __restrict__ g,
                               const float* __restrict__ b)
{
    const int row = blockIdx.x;
    const int tid = threadIdx.x;
    float* x = X + (size_t)row * HID;
    float v[4], s = 0.f, sq = 0.f;
#pragma unroll
    for (int i = 0; i < 4; i++) {
        v[i] = x[tid + 256*i];
        s += v[i]; sq += v[i]*v[i];
    }
    __shared__ float rs[256], rq[256];
    rs[tid] = s; rq[tid] = sq; __syncthreads();
    for (int o = 128; o > 0; o >>= 1) {
        if (tid < o) { rs[tid] += rs[tid+o]; rq[tid] += rq[tid+o]; }
        __syncthreads();
    }
    float mean = rs[0] * (1.f/HID);
    float var  = rq[0] * (1.f/HID) - mean*mean;
    float inv  = rsqrtf(var + 1e-5f);
#pragma unroll
    for (int i = 0; i < 4; i++) {
        int c = tid + 256*i;
        float y = (v[i] - mean) * inv * g[c] + b[c];
        x[c] = fmaxf(y, 0.f);
    }
}

/* --------------------- column mean over rows -> ctx ---------------------- */
__global__ void col_partial(const float* __restrict__ X, float* __restrict__ part)
{
    int col   = blockIdx.x * 256 + threadIdx.x;
    int chunk = blockIdx.y;
    float s = 0.f;
    int r0 = chunk * 64;
    for (int r = r0; r < r0 + 64; r++) s += X[(size_t)r * HID + col];
    part[(size_t)chunk * HID + col] = s;
}
__global__ void col_final(const float* __restrict__ part, float* __restrict__ ctx)
{
    int col = blockIdx.x * 256 + threadIdx.x;
    float s = 0.f;
    for (int c = 0; c < 64; c++) s += part[(size_t)c * HID + col];
    ctx[col] = s * (1.f / M_TRAIN);
}

/* ------------------ hypernet matvec: out = W @ ctx + bias ---------------- */
__global__ void matvec(const float* __restrict__ W, const float* __restrict__ bias,
                       const float* __restrict__ ctx, float* __restrict__ out, int rows)
{
    int gw   = (blockIdx.x * blockDim.x + threadIdx.x) >> 5;
    int lane = threadIdx.x & 31;
    if (gw >= rows) return;
    const float* w = W + (size_t)gw * HID;
    float s = 0.f;
#pragma unroll 8
    for (int i = lane; i < HID; i += 32) s += w[i] * ctx[i];
#pragma unroll
    for (int o = 16; o; o >>= 1) s += __shfl_xor_sync(0xffffffffu, s, o);
    if (lane == 0) out[gw] = s + bias[gw];
}

/* ---- fold tree_w softmax + leaf softmax into one table W[t,l,c] --------- */
__global__ void make_W(const float* __restrict__ tw, const float* __restrict__ lf,
                       float* __restrict__ Wout)
{
    __shared__ float tws[NTREES];
    int tid = threadIdx.x;
    if (tid == 0) {
        float mx = -1e30f;
        for (int i = 0; i < NTREES; i++) mx = fmaxf(mx, tw[i]);
        float e[NTREES], s = 0.f;
        for (int i = 0; i < NTREES; i++) { e[i] = expf(tw[i] - mx); s += e[i]; }
        for (int i = 0; i < NTREES; i++) tws[i] = e[i] / s;
    }
    __syncthreads();
    if (tid < NTREES * NLEAF) {
        const float* L = lf + tid * NCLS;
        float mx = -1e30f;
        for (int c = 0; c < NCLS; c++) mx = fmaxf(mx, L[c]);
        float e[NCLS], s = 0.f;
        for (int c = 0; c < NCLS; c++) { e[c] = expf(L[c] - mx); s += e[c]; }
        float scale = tws[tid >> 5] / s;
        for (int c = 0; c < NCLS; c++) Wout[tid * NCLS + c] = e[c] * scale;
    }
}

/* ------------- soft tree routing + class combine, thread per row --------- */
__global__ void route_kernel(const float* __restrict__ dec, const float* __restrict__ W,
                             float* __restrict__ out)
{
    __shared__ float Ws[LF_ROWS];
    int tid = threadIdx.x;
    for (int i = tid; i < LF_ROWS; i += 256) Ws[i] = W[i];
    __syncthreads();
    int b = blockIdx.x * 256 + tid;
    float acc[NCLS];
#pragma unroll
    for (int c = 0; c < NCLS; c++) acc[c] = 0.f;

    for (int t = 0; t < NTREES; t++) {
        float d[NINT];
#pragma unroll
        for (int n = 0; n < NINT; n++)
            d[n] = dec[(size_t)(t*NINT + n) * M_TEST + b];
#pragma unroll
        for (int l = 0; l < NLEAF; l++) {
            float p = 1.f;
#pragma unroll
            for (int dd = 0; dd < 5; dd++) {
                int node = (1 << dd) - 1 + (l >> (5 - dd));
                int go   = (l >> (4 - dd)) & 1;
                p *= go ? d[node] : (1.f - d[node]);
            }
            const float* w = &Ws[(t*NLEAF + l) * NCLS];
#pragma unroll
            for (int c = 0; c < NCLS; c++) acc[c] += p * w[c];
        }
    }
#pragma unroll
    for (int c = 0; c < NCLS; c++) out[(size_t)b * NCLS + c] = acc[c];
}

/* ------------------------------- launch ---------------------------------- */
extern "C" void kernel_launch(void* const* d_in, const int* in_sizes, int n_in,
                              void* d_out, int out_size)
{
    const float* X_train = (const float*)d_in[0];
    const float* X_test  = (const float*)d_in[1];
    const float* enc_w1  = (const float*)d_in[2];
    const float* enc_b1  = (const float*)d_in[3];
    const float* ln1_g   = (const float*)d_in[4];
    const float* ln1_b   = (const float*)d_in[5];
    const float* enc_w2  = (const float*)d_in[6];
    const float* enc_b2  = (const float*)d_in[7];
    const float* ln2_g   = (const float*)d_in[8];
    const float* ln2_b   = (const float*)d_in[9];
    const float* sw_w    = (const float*)d_in[10];
    const float* sw_b    = (const float*)d_in[11];
    const float* sb_w    = (const float*)d_in[12];
    const float* sb_b    = (const float*)d_in[13];
    const float* lf_w    = (const float*)d_in[14];
    const float* lf_b    = (const float*)d_in[15];
    const float* tw_w    = (const float*)d_in[16];
    const float* tw_b    = (const float*)d_in[17];

    float *C1, *C2, *part, *ctx, *sw, *sb, *lf, *tw, *W, *dec;
    cudaGetSymbolAddress((void**)&C1,   g_C1);
    cudaGetSymbolAddress((void**)&C2,   g_C2);
    cudaGetSymbolAddress((void**)&part, g_part);
    cudaGetSymbolAddress((void**)&ctx,  g_ctx);
    cudaGetSymbolAddress((void**)&sw,   g_sw);
    cudaGetSymbolAddress((void**)&sb,   g_sb);
    cudaGetSymbolAddress((void**)&lf,   g_lf);
    cudaGetSymbolAddress((void**)&tw,   g_tw);
    cudaGetSymbolAddress((void**)&W,    g_W);
    cudaGetSymbolAddress((void**)&dec,  g_dec);

    /* encoder */
    gemm_bias<0><<<dim3(HID/64, M_TRAIN/64), 256>>>(X_train, enc_w1, enc_b1, C1,
                                                    M_TRAIN, HID, DIN);
    ln_relu_kernel<<<M_TRAIN, 256>>>(C1, ln1_g, ln1_b);
    gemm_bias<0><<<dim3(HID/64, M_TRAIN/64), 256>>>(C1, enc_w2, enc_b2, C2,
                                                    M_TRAIN, HID, HID);
    ln_relu_kernel<<<M_TRAIN, 256>>>(C2, ln2_g, ln2_b);

    /* ctx = mean over rows */
    col_partial<<<dim3(HID/256, 64), 256>>>(C2, part);
    col_final<<<HID/256, 256>>>(part, ctx);

    /* hypernet matvecs (HBM-bound; 260 MB dominant stream) */
    matvec<<<(SW_ROWS*32 + 255)/256, 256>>>(sw_w, sw_b, ctx, sw, SW_ROWS);
    matvec<<<(NSPLIT*32 + 255)/256, 256>>>(sb_w, sb_b, ctx, sb, NSPLIT);
    matvec<<<(LF_ROWS*32 + 255)/256, 256>>>(lf_w, lf_b, ctx, lf, LF_ROWS);
    matvec<<<(NTREES*32 + 255)/256, 256>>>(tw_w, tw_b, ctx, tw, NTREES);

    /* dec = sigmoid(X_test @ split_w^T + split_b), stored transposed */
    gemm_bias<1><<<dim3((NSPLIT + 63)/64, M_TEST/64), 256>>>(X_test, sw, sb, dec,
                                                             M_TEST, NSPLIT, DIN);

    /* fold softmaxes, then route */
    make_W<<<1, 512>>>(tw, lf, W);
    route_kernel<<<M_TEST/256, 256>>>(dec, W, (float*)d_out);
}

// round 2
// speedup vs baseline: 1.4387x; 1.4387x over previous
#include <cuda_runtime.h>
#include <cuda_bf16.h>
#include <math.h>

#define M_TRAIN 4096
#define M_TEST  16384
#define DIN     128
#define HID     1024
#define NTREES  16
#define NINT    31
#define NLEAF   32
#define NCLS    10
#define NSPLIT  (NTREES*NINT)        /* 496 */
#define SW_ROWS (NTREES*NINT*DIN)    /* 63488 */
#define LF_ROWS (NTREES*NLEAF*NCLS)  /* 5120 */

/* ---------------- scratch (static device memory; no allocs) -------------- */
__device__ float g_C1[M_TRAIN*HID];          /* GEMM1 out (float) */
__device__ float g_C2[M_TRAIN*HID];          /* GEMM2 out -> H2 in-place */
__device__ __nv_bfloat16 g_H1h[M_TRAIN*HID]; /* H1 split hi */
__device__ __nv_bfloat16 g_H1l[M_TRAIN*HID]; /* H1 split lo */
__device__ __nv_bfloat16 g_Xtrh[M_TRAIN*DIN], g_Xtrl[M_TRAIN*DIN];
__device__ __nv_bfloat16 g_W1h[HID*DIN],     g_W1l[HID*DIN];
__device__ __nv_bfloat16 g_W2h[HID*HID],     g_W2l[HID*HID];
__device__ __nv_bfloat16 g_Xteh[M_TEST*DIN], g_Xtel[M_TEST*DIN];
__device__ __nv_bfloat16 g_SWh[SW_ROWS],     g_SWl[SW_ROWS];
__device__ float g_part[64*HID];
__device__ float g_ctx[HID];
__device__ float g_sw[SW_ROWS];
__device__ float g_sb[NSPLIT];
__device__ float g_lf[LF_ROWS];
__device__ float g_tw[NTREES];
__device__ float g_W[LF_ROWS];
__device__ float g_dec[NSPLIT*M_TEST];       /* TRANSPOSED [496][16384] */

/* ------------------------ split fp32 -> bf16 hi/lo ----------------------- */
__global__ void split_f32(const float* __restrict__ x, __nv_bfloat16* __restrict__ hi,
                          __nv_bfloat16* __restrict__ lo, int n4)
{
    int i = blockIdx.x * blockDim.x + threadIdx.x;
    if (i >= n4) return;
    float4 v = ((const float4*)x)[i];
    __nv_bfloat16 h0 = __float2bfloat16(v.x);
    __nv_bfloat16 h1 = __float2bfloat16(v.y);
    __nv_bfloat16 h2 = __float2bfloat16(v.z);
    __nv_bfloat16 h3 = __float2bfloat16(v.w);
    __nv_bfloat16 l0 = __float2bfloat16(v.x - __bfloat162float(h0));
    __nv_bfloat16 l1 = __float2bfloat16(v.y - __bfloat162float(h1));
    __nv_bfloat16 l2 = __float2bfloat16(v.z - __bfloat162float(h2));
    __nv_bfloat16 l3 = __float2bfloat16(v.w - __bfloat162float(h3));
    ((__nv_bfloat162*)hi)[i*2]   = __halves2bfloat162(h0, h1);
    ((__nv_bfloat162*)hi)[i*2+1] = __halves2bfloat162(h2, h3);
    ((__nv_bfloat162*)lo)[i*2]   = __halves2bfloat162(l0, l1);
    ((__nv_bfloat162*)lo)[i*2+1] = __halves2bfloat162(l2, l3);
}

/* -------------------------- bf16x3 mma helper ---------------------------- */
__device__ __forceinline__ void mma_bf16(float c[4], unsigned a0, unsigned a1,
                                         unsigned a2, unsigned a3,
                                         unsigned b0, unsigned b1)
{
    asm volatile(
        "mma.sync.aligned.m16n8k16.row.col.f32.bf16.bf16.f32 "
        "{%0,%1,%2,%3}, {%4,%5,%6,%7}, {%8,%9}, {%0,%1,%2,%3};"
        : "+f"(c[0]), "+f"(c[1]), "+f"(c[2]), "+f"(c[3])
        : "r"(a0), "r"(a1), "r"(a2), "r"(a3), "r"(b0), "r"(b1));
}

/* ----------------- tensor-core GEMM: C = A @ B^T + bias ------------------ */
/* A[M,K], B[N,K] given as split bf16 (hi/lo). fp32 accumulate via 3 mmas.   */
/* EPI 0: C[row*N+col] = acc + bias[col]                                     */
/* EPI 1: C[col*M+row] = sigmoid(acc + bias[col])  (transposed, smem-staged) */
#define BM 128
#define BN 128
#define BK 32
#define PITCH 20    /* u32 (bf16x2 pair) pitch; 80B rows, 16B aligned        */

template<int EPI>
__global__ void __launch_bounds__(256) gemm_tc(
    const __nv_bfloat16* __restrict__ Ah, const __nv_bfloat16* __restrict__ Al,
    const __nv_bfloat16* __restrict__ Bh, const __nv_bfloat16* __restrict__ Bl,
    const float* __restrict__ bias, float* __restrict__ C,
    int M, int N, int K)
{
    union Smem {
        struct { unsigned ah[BM][PITCH], al[BM][PITCH], bh[BN][PITCH], bl[BN][PITCH]; } t;
        float trans[32][132];
    };
    __shared__ Smem sm;

    const int tid  = threadIdx.x;
    const int warp = tid >> 5, lane = tid & 31;
    const int g = lane >> 2, t = lane & 3;
    const int wm = warp & 1, wn = warp >> 1;     /* warp grid 2(m) x 4(n)     */
    const int m0 = blockIdx.y * BM, n0 = blockIdx.x * BN;

    float c[4][4][4];
#pragma unroll
    for (int i = 0; i < 4; i++)
#pragma unroll
        for (int j = 0; j < 4; j++)
#pragma unroll
            for (int r = 0; r < 4; r++) c[i][j][r] = 0.f;

    const int lrow = tid >> 1;          /* 0..127 */
    const int ke   = (tid & 1) * 16;    /* bf16 elem offset 0 or 16 */

    for (int k0 = 0; k0 < K; k0 += BK) {
        /* load A tile (128x32 bf16, hi+lo) */
        {
            const size_t aoff = (size_t)(m0 + lrow) * K + k0 + ke;
            uint4 vh0 = *(const uint4*)(Ah + aoff);
            uint4 vh1 = *(const uint4*)(Ah + aoff + 8);
            uint4 vl0 = *(const uint4*)(Al + aoff);
            uint4 vl1 = *(const uint4*)(Al + aoff + 8);
            *(uint4*)&sm.t.ah[lrow][ke/2]     = vh0;
            *(uint4*)&sm.t.ah[lrow][ke/2 + 4] = vh1;
            *(uint4*)&sm.t.al[lrow][ke/2]     = vl0;
            *(uint4*)&sm.t.al[lrow][ke/2 + 4] = vl1;
        }
        /* load B tile with N guard */
        {
            uint4 z = make_uint4(0,0,0,0);
            uint4 vh0 = z, vh1 = z, vl0 = z, vl1 = z;
            if (n0 + lrow < N) {
                const size_t boff = (size_t)(n0 + lrow) * K + k0 + ke;
                vh0 = *(const uint4*)(Bh + boff);
                vh1 = *(const uint4*)(Bh + boff + 8);
                vl0 = *(const uint4*)(Bl + boff);
                vl1 = *(const uint4*)(Bl + boff + 8);
            }
            *(uint4*)&sm.t.bh[lrow][ke/2]     = vh0;
            *(uint4*)&sm.t.bh[lrow][ke/2 + 4] = vh1;
            *(uint4*)&sm.t.bl[lrow][ke/2]     = vl0;
            *(uint4*)&sm.t.bl[lrow][ke/2 + 4] = vl1;
        }
        __syncthreads();

#pragma unroll
        for (int s = 0; s < 2; s++) {        /* two k16 steps per BK=32 */
            const int kp = s * 8;
            unsigned ahf[4][4], alf[4][4], bhf[4][2], blf[4][2];
#pragma unroll
            for (int i = 0; i < 4; i++) {
                int r0 = wm*64 + i*16 + g;
                ahf[i][0] = sm.t.ah[r0  ][kp + t];
                ahf[i][1] = sm.t.ah[r0+8][kp + t];
                ahf[i][2] = sm.t.ah[r0  ][kp + t + 4];
                ahf[i][3] = sm.t.ah[r0+8][kp + t + 4];
                alf[i][0] = sm.t.al[r0  ][kp + t];
                alf[i][1] = sm.t.al[r0+8][kp + t];
                alf[i][2] = sm.t.al[r0  ][kp + t + 4];
                alf[i][3] = sm.t.al[r0+8][kp + t + 4];
            }
#pragma unroll
            for (int j = 0; j < 4; j++) {
                int rn = wn*32 + j*8 + g;
                bhf[j][0] = sm.t.bh[rn][kp + t];
                bhf[j][1] = sm.t.bh[rn][kp + t + 4];
                blf[j][0] = sm.t.bl[rn][kp + t];
                blf[j][1] = sm.t.bl[rn][kp + t + 4];
            }
#pragma unroll
            for (int i = 0; i < 4; i++)
#pragma unroll
                for (int j = 0; j < 4; j++) {
                    mma_bf16(c[i][j], ahf[i][0],ahf[i][1],ahf[i][2],ahf[i][3],
                             bhf[j][0], bhf[j][1]);
                    mma_bf16(c[i][j], ahf[i][0],ahf[i][1],ahf[i][2],ahf[i][3],
                             blf[j][0], blf[j][1]);
                    mma_bf16(c[i][j], alf[i][0],alf[i][1],alf[i][2],alf[i][3],
                             bhf[j][0], bhf[j][1]);
                }
        }
        __syncthreads();
    }

    if (EPI == 0) {
        /* plain store (N divisible by 128 for encoder GEMMs) */
#pragma unroll
        for (int i = 0; i < 4; i++) {
            int r0 = m0 + wm*64 + i*16 + g;
#pragma unroll
            for (int j = 0; j < 4; j++) {
                int col = n0 + wn*32 + j*8 + 2*t;
                float b0 = bias[col], b1 = bias[col+1];
                float2 v0 = make_float2(c[i][j][0] + b0, c[i][j][1] + b1);
                float2 v1 = make_float2(c[i][j][2] + b0, c[i][j][3] + b1);
                *(float2*)&C[(size_t)r0      * N + col] = v0;
                *(float2*)&C[(size_t)(r0+8)  * N + col] = v1;
            }
        }
    } else {
        /* sigmoid + transposed store via smem staging (32-col chunks) */
#pragma unroll
        for (int chunk = 0; chunk < 4; chunk++) {
            __syncthreads();
            if (wn == chunk) {
#pragma unroll
                for (int i = 0; i < 4; i++) {
                    int mm = wm*64 + i*16 + g;
#pragma unroll
                    for (int j = 0; j < 4; j++) {
                        int nn  = j*8 + 2*t;
                        int col = n0 + chunk*32 + nn;
                        float b0 = (col     < N) ? bias[col]   : 0.f;
                        float b1 = (col + 1 < N) ? bias[col+1] : 0.f;
                        float v0 = c[i][j][0] + b0, v1 = c[i][j][1] + b1;
                        float v2 = c[i][j][2] + b0, v3 = c[i][j][3] + b1;
                        sm.trans[nn  ][mm  ] = 1.f / (1.f + __expf(-v0));
                        sm.trans[nn+1][mm  ] = 1.f / (1.f + __expf(-v1));
                        sm.trans[nn  ][mm+8] = 1.f / (1.f + __expf(-v2));
                        sm.trans[nn+1][mm+8] = 1.f / (1.f + __expf(-v3));
                    }
                }
            }
            __syncthreads();
#pragma unroll
            for (int p = 0; p < 4; p++) {
                int idx  = tid + p*256;
                int rowb = idx >> 5;
                int mc   = (idx & 31) * 4;
                int ngl  = n0 + chunk*32 + rowb;
                if (ngl < N)
                    *(float4*)&C[(size_t)ngl * M + m0 + mc] =
                        *(float4*)&sm.trans[rowb][mc];
            }
        }
    }
}

/* ------------- LayerNorm + ReLU; SPLIT=1 emits bf16 hi/lo ---------------- */
template<int SPLIT>
__global__ void ln_relu(const float* __restrict__ X, float* __restrict__ Y,
                        __nv_bfloat16* __restrict__ Yh, __nv_bfloat16* __restrict__ Yl,
                        const float* __restrict__ gg, const float* __restrict__ bb)
{
    const int row = blockIdx.x, tid = threadIdx.x;
    const float4 v = ((const float4*)(X + (size_t)row * HID))[tid];
    float s = v.x + v.y + v.z + v.w;
    float q = v.x*v.x + v.y*v.y + v.z*v.z + v.w*v.w;
#pragma unroll
    for (int o = 16; o; o >>= 1) {
        s += __shfl_xor_sync(0xffffffffu, s, o);
        q += __shfl_xor_sync(0xffffffffu, q, o);
    }
    __shared__ float ss[8], qs[8];
    if ((tid & 31) == 0) { ss[tid >> 5] = s; qs[tid >> 5] = q; }
    __syncthreads();
    s = ss[0]+ss[1]+ss[2]+ss[3]+ss[4]+ss[5]+ss[6]+ss[7];
    q = qs[0]+qs[1]+qs[2]+qs[3]+qs[4]+qs[5]+qs[6]+qs[7];
    float mean = s * (1.f/HID);
    float inv  = rsqrtf(q * (1.f/HID) - mean*mean + 1e-5f);
    float4 gv = ((const float4*)gg)[tid];
    float4 bv = ((const float4*)bb)[tid];
    float4 y;
    y.x = fmaxf((v.x - mean)*inv*gv.x + bv.x, 0.f);
    y.y = fmaxf((v.y - mean)*inv*gv.y + bv.y, 0.f);
    y.z = fmaxf((v.z - mean)*inv*gv.z + bv.z, 0.f);
    y.w = fmaxf((v.w - mean)*inv*gv.w + bv.w, 0.f);
    if (SPLIT) {
        __nv_bfloat16 h0=__float2bfloat16(y.x), h1=__float2bfloat16(y.y);
        __nv_bfloat16 h2=__float2bfloat16(y.z), h3=__float2bfloat16(y.w);
        __nv_bfloat16 l0=__float2bfloat16(y.x-__bfloat162float(h0));
        __nv_bfloat16 l1=__float2bfloat16(y.y-__bfloat162float(h1));
        __nv_bfloat16 l2=__float2bfloat16(y.z-__bfloat162float(h2));
        __nv_bfloat16 l3=__float2bfloat16(y.w-__bfloat162float(h3));
        __nv_bfloat162* ph = (__nv_bfloat162*)(Yh + (size_t)row * HID);
        __nv_bfloat162* pl = (__nv_bfloat162*)(Yl + (size_t)row * HID);
        ph[tid*2]   = __halves2bfloat162(h0, h1);
        ph[tid*2+1] = __halves2bfloat162(h2, h3);
        pl[tid*2]   = __halves2bfloat162(l0, l1);
        pl[tid*2+1] = __halves2bfloat162(l2, l3);
    } else {
        ((float4*)(Y + (size_t)row * HID))[tid] = y;
    }
}

/* --------------------- column mean over rows -> ctx ---------------------- */
__global__ void col_partial(const float* __restrict__ X, float* __restrict__ part)
{
    int col   = blockIdx.x * 256 + threadIdx.x;
    int chunk = blockIdx.y;
    float s = 0.f;
    int r0 = chunk * 64;
    for (int r = r0; r < r0 + 64; r++) s += X[(size_t)r * HID + col];
    part[(size_t)chunk * HID + col] = s;
}
__global__ void col_final(const float* __restrict__ part, float* __restrict__ ctx)
{
    int col = blockIdx.x * 256 + threadIdx.x;
    float s = 0.f;
    for (int c = 0; c < 64; c++) s += part[(size_t)c * HID + col];
    ctx[col] = s * (1.f / M_TRAIN);
}

/* ------------------ hypernet matvec: out = W @ ctx + bias ---------------- */
__global__ void matvec(const float* __restrict__ W, const float* __restrict__ bias,
                       const float* __restrict__ ctx, float* __restrict__ out, int rows)
{
    int gw   = (blockIdx.x * blockDim.x + threadIdx.x) >> 5;
    int lane = threadIdx.x & 31;
    if (gw >= rows) return;
    const float4* w4 = (const float4*)(W + (size_t)gw * HID);
    const float4* c4 = (const float4*)ctx;
    float s = 0.f;
#pragma unroll
    for (int i = 0; i < 8; i++) {
        float4 a = w4[lane + 32*i];
        float4 c = __ldg(&c4[lane + 32*i]);
        s += a.x*c.x + a.y*c.y + a.z*c.z + a.w*c.w;
    }
#pragma unroll
    for (int o = 16; o; o >>= 1) s += __shfl_xor_sync(0xffffffffu, s, o);
    if (lane == 0) out[gw] = s + bias[gw];
}

/* ---- fold tree_w softmax + leaf softmax into one table W[t,l,c] --------- */
__global__ void make_W(const float* __restrict__ tw, const float* __restrict__ lf,
                       float* __restrict__ Wout)
{
    __shared__ float tws[NTREES];
    int tid = threadIdx.x;
    if (tid == 0) {
        float mx = -1e30f;
        for (int i = 0; i < NTREES; i++) mx = fmaxf(mx, tw[i]);
        float e[NTREES], s = 0.f;
        for (int i = 0; i < NTREES; i++) { e[i] = expf(tw[i] - mx); s += e[i]; }
        for (int i = 0; i < NTREES; i++) tws[i] = e[i] / s;
    }
    __syncthreads();
    if (tid < NTREES * NLEAF) {
        const float* L = lf + tid * NCLS;
        float mx = -1e30f;
        for (int c = 0; c < NCLS; c++) mx = fmaxf(mx, L[c]);
        float e[NCLS], s = 0.f;
        for (int c = 0; c < NCLS; c++) { e[c] = expf(L[c] - mx); s += e[c]; }
        float scale = tws[tid >> 5] / s;
        for (int c = 0; c < NCLS; c++) Wout[tid * NCLS + c] = e[c] * scale;
    }
}

/* ------------- soft tree routing + class combine, thread per row --------- */
__global__ void route_kernel(const float* __restrict__ dec, const float* __restrict__ W,
                             float* __restrict__ out)
{
    __shared__ float Ws[LF_ROWS];
    int tid = threadIdx.x;
    for (int i = tid; i < LF_ROWS; i += 256) Ws[i] = W[i];
    __syncthreads();
    int b = blockIdx.x * 256 + tid;
    float acc[NCLS];
#pragma unroll
    for (int c = 0; c < NCLS; c++) acc[c] = 0.f;

    for (int t = 0; t < NTREES; t++) {
        float d[NINT];
#pragma unroll
        for (int n = 0; n < NINT; n++)
            d[n] = dec[(size_t)(t*NINT + n) * M_TEST + b];
#pragma unroll
        for (int l = 0; l < NLEAF; l++) {
            float p = 1.f;
#pragma unroll
            for (int dd = 0; dd < 5; dd++) {
                int node = (1 << dd) - 1 + (l >> (5 - dd));
                int go   = (l >> (4 - dd)) & 1;
                p *= go ? d[node] : (1.f - d[node]);
            }
            const float* w = &Ws[(t*NLEAF + l) * NCLS];
#pragma unroll
            for (int c = 0; c < NCLS; c++) acc[c] += p * w[c];
        }
    }
#pragma unroll
    for (int c = 0; c < NCLS; c++) out[(size_t)b * NCLS + c] = acc[c];
}

/* ------------------------------- launch ---------------------------------- */
extern "C" void kernel_launch(void* const* d_in, const int* in_sizes, int n_in,
                              void* d_out, int out_size)
{
    const float* X_train = (const float*)d_in[0];
    const float* X_test  = (const float*)d_in[1];
    const float* enc_w1  = (const float*)d_in[2];
    const float* enc_b1  = (const float*)d_in[3];
    const float* ln1_g   = (const float*)d_in[4];
    const float* ln1_b   = (const float*)d_in[5];
    const float* enc_w2  = (const float*)d_in[6];
    const float* enc_b2  = (const float*)d_in[7];
    const float* ln2_g   = (const float*)d_in[8];
    const float* ln2_b   = (const float*)d_in[9];
    const float* sw_w    = (const float*)d_in[10];
    const float* sw_b    = (const float*)d_in[11];
    const float* sb_w    = (const float*)d_in[12];
    const float* sb_b    = (const float*)d_in[13];
    const float* lf_w    = (const float*)d_in[14];
    const float* lf_b    = (const float*)d_in[15];
    const float* tw_w    = (const float*)d_in[16];
    const float* tw_b    = (const float*)d_in[17];

    float *C1, *C2, *part, *ctx, *sw, *sb, *lf, *tw, *W, *dec;
    __nv_bfloat16 *H1h, *H1l, *Xtrh, *Xtrl, *W1h, *W1l, *W2h, *W2l, *Xteh, *Xtel, *SWh, *SWl;
    cudaGetSymbolAddress((void**)&C1,   g_C1);
    cudaGetSymbolAddress((void**)&C2,   g_C2);
    cudaGetSymbolAddress((void**)&H1h,  g_H1h);
    cudaGetSymbolAddress((void**)&H1l,  g_H1l);
    cudaGetSymbolAddress((void**)&Xtrh, g_Xtrh);
    cudaGetSymbolAddress((void**)&Xtrl, g_Xtrl);
    cudaGetSymbolAddress((void**)&W1h,  g_W1h);
    cudaGetSymbolAddress((void**)&W1l,  g_W1l);
    cudaGetSymbolAddress((void**)&W2h,  g_W2h);
    cudaGetSymbolAddress((void**)&W2l,  g_W2l);
    cudaGetSymbolAddress((void**)&Xteh, g_Xteh);
    cudaGetSymbolAddress((void**)&Xtel, g_Xtel);
    cudaGetSymbolAddress((void**)&SWh,  g_SWh);
    cudaGetSymbolAddress((void**)&SWl,  g_SWl);
    cudaGetSymbolAddress((void**)&part, g_part);
    cudaGetSymbolAddress((void**)&ctx,  g_ctx);
    cudaGetSymbolAddress((void**)&sw,   g_sw);
    cudaGetSymbolAddress((void**)&sb,   g_sb);
    cudaGetSymbolAddress((void**)&lf,   g_lf);
    cudaGetSymbolAddress((void**)&tw,   g_tw);
    cudaGetSymbolAddress((void**)&W,    g_W);
    cudaGetSymbolAddress((void**)&dec,  g_dec);

    /* pre-split static inputs to bf16 hi/lo */
    split_f32<<<(M_TRAIN*DIN/4 + 255)/256, 256>>>(X_train, Xtrh, Xtrl, M_TRAIN*DIN/4);
    split_f32<<<(HID*DIN/4     + 255)/256, 256>>>(enc_w1,  W1h,  W1l,  HID*DIN/4);
    split_f32<<<(HID*HID/4     + 255)/256, 256>>>(enc_w2,  W2h,  W2l,  HID*HID/4);
    split_f32<<<(M_TEST*DIN/4  + 255)/256, 256>>>(X_test,  Xteh, Xtel, M_TEST*DIN/4);

    /* encoder */
    gemm_tc<0><<<dim3(HID/BN, M_TRAIN/BM), 256>>>(Xtrh, Xtrl, W1h, W1l, enc_b1, C1,
                                                  M_TRAIN, HID, DIN);
    ln_relu<1><<<M_TRAIN, 256>>>(C1, nullptr, H1h, H1l, ln1_g, ln1_b);
    gemm_tc<0><<<dim3(HID/BN, M_TRAIN/BM), 256>>>(H1h, H1l, W2h, W2l, enc_b2, C2,
                                                  M_TRAIN, HID, HID);
    ln_relu<0><<<M_TRAIN, 256>>>(C2, C2, nullptr, nullptr, ln2_g, ln2_b);

    /* ctx = mean over rows */
    col_partial<<<dim3(HID/256, 64), 256>>>(C2, part);
    col_final<<<HID/256, 256>>>(part, ctx);

    /* hypernet matvecs (HBM-bound 260 MB stream) */
    matvec<<<(SW_ROWS*32 + 255)/256, 256>>>(sw_w, sw_b, ctx, sw, SW_ROWS);
    matvec<<<(NSPLIT*32 + 255)/256, 256>>>(sb_w, sb_b, ctx, sb, NSPLIT);
    matvec<<<(LF_ROWS*32 + 255)/256, 256>>>(lf_w, lf_b, ctx, lf, LF_ROWS);
    matvec<<<(NTREES*32 + 255)/256, 256>>>(tw_w, tw_b, ctx, tw, NTREES);

    /* split sw, then dec = sigmoid(X_test @ sw^T + sb), stored transposed */
    split_f32<<<(SW_ROWS/4 + 255)/256, 256>>>(sw, SWh, SWl, SW_ROWS/4);
    gemm_tc<1><<<dim3((NSPLIT + BN - 1)/BN, M_TEST/BM), 256>>>(Xteh, Xtel, SWh, SWl,
                                                               sb, dec,
                                                               M_TEST, NSPLIT, DIN);

    /* fold softmaxes, then route */
    make_W<<<1, 512>>>(tw, lf, W);
    route_kernel<<<M_TEST/256, 256>>>(dec, W, (float*)d_out);
}

// round 3
// speedup vs baseline: 1.5921x; 1.1067x over previous
#include <cuda_runtime.h>
#include <cuda_bf16.h>
#include <math.h>
#include <stdint.h>

#define M_TRAIN 4096
#define M_TEST  16384
#define DIN     128
#define HID     1024
#define NTREES  16
#define NINT    31
#define NLEAF   32
#define NCLS    10
#define NSPLIT  (NTREES*NINT)        /* 496 */
#define SW_ROWS (NTREES*NINT*DIN)    /* 63488 */
#define LF_ROWS (NTREES*NLEAF*NCLS)  /* 5120 */

/* ---------------- scratch (static device memory; no allocs) -------------- */
__device__ float g_C1[M_TRAIN*HID];
__device__ float g_C2[M_TRAIN*HID];
__device__ __nv_bfloat16 g_H1h[M_TRAIN*HID];
__device__ __nv_bfloat16 g_H1l[M_TRAIN*HID];
__device__ __nv_bfloat16 g_Xtrh[M_TRAIN*DIN], g_Xtrl[M_TRAIN*DIN];
__device__ __nv_bfloat16 g_W1h[HID*DIN],     g_W1l[HID*DIN];
__device__ __nv_bfloat16 g_W2h[HID*HID],     g_W2l[HID*HID];
__device__ __nv_bfloat16 g_Xteh[M_TEST*DIN], g_Xtel[M_TEST*DIN];
__device__ __nv_bfloat16 g_SWh[SW_ROWS],     g_SWl[SW_ROWS];
__device__ float g_part[64*HID];
__device__ float g_ctx[HID];
__device__ float g_sw[SW_ROWS];
__device__ float g_sb[NSPLIT];
__device__ float g_lf[LF_ROWS];
__device__ float g_tw[NTREES];
__device__ float g_W[LF_ROWS];
__device__ float g_dec[NSPLIT*M_TEST];       /* TRANSPOSED [496][16384] */

/* ------------------------------ PTX helpers ------------------------------ */
__device__ __forceinline__ uint32_t cvta_sm(const void* p) {
    return (uint32_t)__cvta_generic_to_shared(p);
}
__device__ __forceinline__ void cp16(uint32_t dst, const void* src, int sz) {
    asm volatile("cp.async.cg.shared.global [%0], [%1], 16, %2;\n"
                 :: "r"(dst), "l"(src), "r"(sz));
}
__device__ __forceinline__ void cp_commit() {
    asm volatile("cp.async.commit_group;\n");
}
__device__ __forceinline__ void ldsm4(unsigned& r0, unsigned& r1,
                                      unsigned& r2, unsigned& r3, uint32_t a) {
    asm volatile("ldmatrix.sync.aligned.m8n8.x4.shared.b16 {%0,%1,%2,%3}, [%4];"
                 : "=r"(r0), "=r"(r1), "=r"(r2), "=r"(r3) : "r"(a));
}
__device__ __forceinline__ void mma_bf16(float c[4], unsigned a0, unsigned a1,
                                         unsigned a2, unsigned a3,
                                         unsigned b0, unsigned b1)
{
    asm volatile(
        "mma.sync.aligned.m16n8k16.row.col.f32.bf16.bf16.f32 "
        "{%0,%1,%2,%3}, {%4,%5,%6,%7}, {%8,%9}, {%0,%1,%2,%3};"
        : "+f"(c[0]), "+f"(c[1]), "+f"(c[2]), "+f"(c[3])
        : "r"(a0), "r"(a1), "r"(a2), "r"(a3), "r"(b0), "r"(b1));
}
/* swizzled byte offset inside a 128x32-bf16 tile (64B rows, conflict-free
   for both 16B cp.async stores and ldmatrix 16B reads) */
__device__ __forceinline__ uint32_t swz(int r, int hb) {
    return (uint32_t)(r*64 + ((hb ^ ((r>>1)&3)) << 4));
}

/* ------------------------ split fp32 -> bf16 hi/lo ----------------------- */
__global__ void split_f32(const float* __restrict__ x, __nv_bfloat16* __restrict__ hi,
                          __nv_bfloat16* __restrict__ lo, int n4)
{
    int i0 = blockIdx.x * (blockDim.x * 4) + threadIdx.x;
    float4 v[4];
    bool ok[4];
#pragma unroll
    for (int u = 0; u < 4; u++) {
        int i = i0 + u*256;
        ok[u] = (i < n4);
        if (ok[u]) v[u] = ((const float4*)x)[i];
    }
#pragma unroll
    for (int u = 0; u < 4; u++) {
        if (!ok[u]) continue;
        int i = i0 + u*256;
        __nv_bfloat16 h0=__float2bfloat16(v[u].x), h1=__float2bfloat16(v[u].y);
        __nv_bfloat16 h2=__float2bfloat16(v[u].z), h3=__float2bfloat16(v[u].w);
        __nv_bfloat16 l0=__float2bfloat16(v[u].x-__bfloat162float(h0));
        __nv_bfloat16 l1=__float2bfloat16(v[u].y-__bfloat162float(h1));
        __nv_bfloat16 l2=__float2bfloat16(v[u].z-__bfloat162float(h2));
        __nv_bfloat16 l3=__float2bfloat16(v[u].w-__bfloat162float(h3));
        ((__nv_bfloat162*)hi)[i*2]   = __halves2bfloat162(h0, h1);
        ((__nv_bfloat162*)hi)[i*2+1] = __halves2bfloat162(h2, h3);
        ((__nv_bfloat162*)lo)[i*2]   = __halves2bfloat162(l0, l1);
        ((__nv_bfloat162*)lo)[i*2+1] = __halves2bfloat162(l2, l3);
    }
}

/* ----------------- tensor-core GEMM: C = A @ B^T + bias ------------------ */
/* 128x128 CTA tile, BK=32, 2-stage cp.async pipeline, ldmatrix fragments.   */
/* Stage layout (32KB): Ah@0  Al@8K  Bh@16K  Bl@24K                          */
#define STAGE 32768

template<int EPI>
__global__ void __launch_bounds__(256, 2) gemm_tc(
    const __nv_bfloat16* __restrict__ Ah, const __nv_bfloat16* __restrict__ Al,
    const __nv_bfloat16* __restrict__ Bh, const __nv_bfloat16* __restrict__ Bl,
    const float* __restrict__ bias, float* __restrict__ C,
    int M, int N, int K)
{
    extern __shared__ char dynsm[];
    const uint32_t smem = cvta_sm(dynsm);
    const int tid = threadIdx.x, lane = tid & 31, warp = tid >> 5;
    const int g = lane >> 2, t = lane & 3;
    const int wm = warp & 1, wn = warp >> 1;
    const int m0 = blockIdx.y * 128, n0 = blockIdx.x * 128;

    float c[4][4][4];
#pragma unroll
    for (int i = 0; i < 4; i++)
#pragma unroll
        for (int j = 0; j < 4; j++)
#pragma unroll
            for (int r = 0; r < 4; r++) c[i][j][r] = 0.f;

    const int kIters = K >> 5;

    auto load_stage = [&](int buf, int k0) {
        uint32_t sb = smem + buf * STAGE;
#pragma unroll
        for (int cc = 0; cc < 2; cc++) {
            int ch = tid + cc*256;
            int r = ch >> 2, hb = ch & 3;
            uint32_t so = swz(r, hb);
            size_t ga = (size_t)(m0 + r) * K + k0 + hb*8;
            cp16(sb + so,         Ah + ga, 16);
            cp16(sb + 8192 + so,  Al + ga, 16);
            int bn = n0 + r;
            int sz = (bn < N) ? 16 : 0;
            size_t gb = (size_t)(sz ? bn : 0) * K + k0 + hb*8;
            cp16(sb + 16384 + so, Bh + gb, sz);
            cp16(sb + 24576 + so, Bl + gb, sz);
        }
    };

    auto compute = [&](int buf) {
        uint32_t sb = smem + buf * STAGE;
        const int rl = lane & 15;
        const int hx = lane >> 4;
#pragma unroll
        for (int s = 0; s < 2; s++) {
            const int hb = s*2 + hx;
            /* B fragments for the warp's 32 columns */
            unsigned bh[4][2], bl[4][2];
#pragma unroll
            for (int j2 = 0; j2 < 2; j2++) {
                int row = wn*32 + j2*16 + rl;
                uint32_t off = swz(row, hb);
                unsigned r0, r1, r2, r3;
                ldsm4(r0, r1, r2, r3, sb + 16384 + off);
                bh[j2*2][0]=r0; bh[j2*2][1]=r2; bh[j2*2+1][0]=r1; bh[j2*2+1][1]=r3;
                ldsm4(r0, r1, r2, r3, sb + 24576 + off);
                bl[j2*2][0]=r0; bl[j2*2][1]=r2; bl[j2*2+1][0]=r1; bl[j2*2+1][1]=r3;
            }
            /* A fragments per m16 tile, immediately consumed */
#pragma unroll
            for (int i = 0; i < 4; i++) {
                int row = wm*64 + i*16 + rl;
                uint32_t off = swz(row, hb);
                unsigned a0,a1,a2,a3, q0,q1,q2,q3;
                ldsm4(a0,a1,a2,a3, sb + off);
                ldsm4(q0,q1,q2,q3, sb + 8192 + off);
#pragma unroll
                for (int j = 0; j < 4; j++) {
                    mma_bf16(c[i][j], a0,a1,a2,a3, bh[j][0], bh[j][1]);
                    mma_bf16(c[i][j], a0,a1,a2,a3, bl[j][0], bl[j][1]);
                    mma_bf16(c[i][j], q0,q1,q2,q3, bh[j][0], bh[j][1]);
                }
            }
        }
    };

    load_stage(0, 0);
    cp_commit();
    for (int it = 0; it < kIters; it++) {
        if (it + 1 < kIters) {
            load_stage((it+1) & 1, (it+1)*32);
            cp_commit();
            asm volatile("cp.async.wait_group 1;\n");
        } else {
            asm volatile("cp.async.wait_group 0;\n");
        }
        __syncthreads();
        compute(it & 1);
        __syncthreads();
    }

    if (EPI == 0) {
#pragma unroll
        for (int i = 0; i < 4; i++) {
            int r0 = m0 + wm*64 + i*16 + g;
#pragma unroll
            for (int j = 0; j < 4; j++) {
                int col = n0 + wn*32 + j*8 + 2*t;
                float b0 = bias[col], b1 = bias[col+1];
                float2 v0 = make_float2(c[i][j][0] + b0, c[i][j][1] + b1);
                float2 v1 = make_float2(c[i][j][2] + b0, c[i][j][3] + b1);
                *(float2*)&C[(size_t)r0     * N + col] = v0;
                *(float2*)&C[(size_t)(r0+8) * N + col] = v1;
            }
        }
    } else {
        float (*trans)[132] = reinterpret_cast<float(*)[132]>(dynsm);
#pragma unroll
        for (int chunk = 0; chunk < 4; chunk++) {
            __syncthreads();
            if (wn == chunk) {
#pragma unroll
                for (int i = 0; i < 4; i++) {
                    int mm = wm*64 + i*16 + g;
#pragma unroll
                    for (int j = 0; j < 4; j++) {
                        int nn  = j*8 + 2*t;
                        int col = n0 + chunk*32 + nn;
                        float b0 = (col     < N) ? bias[col]   : 0.f;
                        float b1 = (col + 1 < N) ? bias[col+1] : 0.f;
                        float v0 = c[i][j][0] + b0, v1 = c[i][j][1] + b1;
                        float v2 = c[i][j][2] + b0, v3 = c[i][j][3] + b1;
                        trans[nn  ][mm  ] = 1.f / (1.f + __expf(-v0));
                        trans[nn+1][mm  ] = 1.f / (1.f + __expf(-v1));
                        trans[nn  ][mm+8] = 1.f / (1.f + __expf(-v2));
                        trans[nn+1][mm+8] = 1.f / (1.f + __expf(-v3));
                    }
                }
            }
            __syncthreads();
#pragma unroll
            for (int p = 0; p < 4; p++) {
                int idx  = tid + p*256;
                int rowb = idx >> 5;
                int mc   = (idx & 31) * 4;
                int ngl  = n0 + chunk*32 + rowb;
                if (ngl < N)
                    *(float4*)&C[(size_t)ngl * M + m0 + mc] =
                        *(float4*)&trans[rowb][mc];
            }
        }
    }
}

/* ------------- LayerNorm + ReLU; SPLIT=1 emits bf16 hi/lo ---------------- */
template<int SPLIT>
__global__ void ln_relu(const float* __restrict__ X, float* __restrict__ Y,
                        __nv_bfloat16* __restrict__ Yh, __nv_bfloat16* __restrict__ Yl,
                        const float* __restrict__ gg, const float* __restrict__ bb)
{
    const int row = blockIdx.x, tid = threadIdx.x;
    const float4 v = ((const float4*)(X + (size_t)row * HID))[tid];
    float s = v.x + v.y + v.z + v.w;
    float q = v.x*v.x + v.y*v.y + v.z*v.z + v.w*v.w;
#pragma unroll
    for (int o = 16; o; o >>= 1) {
        s += __shfl_xor_sync(0xffffffffu, s, o);
        q += __shfl_xor_sync(0xffffffffu, q, o);
    }
    __shared__ float ss[8], qs[8];
    if ((tid & 31) == 0) { ss[tid >> 5] = s; qs[tid >> 5] = q; }
    __syncthreads();
    s = ss[0]+ss[1]+ss[2]+ss[3]+ss[4]+ss[5]+ss[6]+ss[7];
    q = qs[0]+qs[1]+qs[2]+qs[3]+qs[4]+qs[5]+qs[6]+qs[7];
    float mean = s * (1.f/HID);
    float inv  = rsqrtf(q * (1.f/HID) - mean*mean + 1e-5f);
    float4 gv = ((const float4*)gg)[tid];
    float4 bv = ((const float4*)bb)[tid];
    float4 y;
    y.x = fmaxf((v.x - mean)*inv*gv.x + bv.x, 0.f);
    y.y = fmaxf((v.y - mean)*inv*gv.y + bv.y, 0.f);
    y.z = fmaxf((v.z - mean)*inv*gv.z + bv.z, 0.f);
    y.w = fmaxf((v.w - mean)*inv*gv.w + bv.w, 0.f);
    if (SPLIT) {
        __nv_bfloat16 h0=__float2bfloat16(y.x), h1=__float2bfloat16(y.y);
        __nv_bfloat16 h2=__float2bfloat16(y.z), h3=__float2bfloat16(y.w);
        __nv_bfloat16 l0=__float2bfloat16(y.x-__bfloat162float(h0));
        __nv_bfloat16 l1=__float2bfloat16(y.y-__bfloat162float(h1));
        __nv_bfloat16 l2=__float2bfloat16(y.z-__bfloat162float(h2));
        __nv_bfloat16 l3=__float2bfloat16(y.w-__bfloat162float(h3));
        __nv_bfloat162* ph = (__nv_bfloat162*)(Yh + (size_t)row * HID);
        __nv_bfloat162* pl = (__nv_bfloat162*)(Yl + (size_t)row * HID);
        ph[tid*2]   = __halves2bfloat162(h0, h1);
        ph[tid*2+1] = __halves2bfloat162(h2, h3);
        pl[tid*2]   = __halves2bfloat162(l0, l1);
        pl[tid*2+1] = __halves2bfloat162(l2, l3);
    } else {
        ((float4*)(Y + (size_t)row * HID))[tid] = y;
    }
}

/* --------------------- column mean over rows -> ctx ---------------------- */
__global__ void col_partial(const float* __restrict__ X, float* __restrict__ part)
{
    int col   = blockIdx.x * 256 + threadIdx.x;
    int chunk = blockIdx.y;
    float s = 0.f;
    int r0 = chunk * 64;
    for (int r = r0; r < r0 + 64; r++) s += X[(size_t)r * HID + col];
    part[(size_t)chunk * HID + col] = s;
}
__global__ void col_final(const float* __restrict__ part, float* __restrict__ ctx)
{
    int col = blockIdx.x * 256 + threadIdx.x;
    float s = 0.f;
    for (int c = 0; c < 64; c++) s += part[(size_t)c * HID + col];
    ctx[col] = s * (1.f / M_TRAIN);
}

/* ------------------ hypernet matvec: out = W @ ctx + bias ---------------- */
__global__ void matvec(const float* __restrict__ W, const float* __restrict__ bias,
                       const float* __restrict__ ctx, float* __restrict__ out, int rows)
{
    int gw   = (blockIdx.x * blockDim.x + threadIdx.x) >> 5;
    int lane = threadIdx.x & 31;
    if (gw >= rows) return;
    const float4* w4 = (const float4*)(W + (size_t)gw * HID);
    const float4* c4 = (const float4*)ctx;
    float s = 0.f;
#pragma unroll
    for (int i = 0; i < 8; i++) {
        float4 a = w4[lane + 32*i];
        float4 c = __ldg(&c4[lane + 32*i]);
        s += a.x*c.x + a.y*c.y + a.z*c.z + a.w*c.w;
    }
#pragma unroll
    for (int o = 16; o; o >>= 1) s += __shfl_xor_sync(0xffffffffu, s, o);
    if (lane == 0) out[gw] = s + bias[gw];
}

/* ---- fold tree_w softmax + leaf softmax into one table W[t,l,c] --------- */
__global__ void make_W(const float* __restrict__ tw, const float* __restrict__ lf,
                       float* __restrict__ Wout)
{
    __shared__ float tws[NTREES];
    int tid = threadIdx.x;
    if (tid == 0) {
        float mx = -1e30f;
        for (int i = 0; i < NTREES; i++) mx = fmaxf(mx, tw[i]);
        float e[NTREES], s = 0.f;
        for (int i = 0; i < NTREES; i++) { e[i] = expf(tw[i] - mx); s += e[i]; }
        for (int i = 0; i < NTREES; i++) tws[i] = e[i] / s;
    }
    __syncthreads();
    if (tid < NTREES * NLEAF) {
        const float* L = lf + tid * NCLS;
        float mx = -1e30f;
        for (int c = 0; c < NCLS; c++) mx = fmaxf(mx, L[c]);
        float e[NCLS], s = 0.f;
        for (int c = 0; c < NCLS; c++) { e[c] = expf(L[c] - mx); s += e[c]; }
        float scale = tws[tid >> 5] / s;
        for (int c = 0; c < NCLS; c++) Wout[tid * NCLS + c] = e[c] * scale;
    }
}

/* ------------- soft tree routing + class combine, thread per row --------- */
__global__ void route_kernel(const float* __restrict__ dec, const float* __restrict__ W,
                             float* __restrict__ out)
{
    __shared__ float Ws[LF_ROWS];
    int tid = threadIdx.x;
    for (int i = tid; i < LF_ROWS; i += 256) Ws[i] = W[i];
    __syncthreads();
    int b = blockIdx.x * 256 + tid;
    float acc[NCLS];
#pragma unroll
    for (int c = 0; c < NCLS; c++) acc[c] = 0.f;

    for (int t = 0; t < NTREES; t++) {
        float d[NINT];
#pragma unroll
        for (int n = 0; n < NINT; n++)
            d[n] = dec[(size_t)(t*NINT + n) * M_TEST + b];
#pragma unroll
        for (int l = 0; l < NLEAF; l++) {
            float p = 1.f;
#pragma unroll
            for (int dd = 0; dd < 5; dd++) {
                int node = (1 << dd) - 1 + (l >> (5 - dd));
                int go   = (l >> (4 - dd)) & 1;
                p *= go ? d[node] : (1.f - d[node]);
            }
            const float* w = &Ws[(t*NLEAF + l) * NCLS];
#pragma unroll
            for (int c = 0; c < NCLS; c++) acc[c] += p * w[c];
        }
    }
#pragma unroll
    for (int c = 0; c < NCLS; c++) out[(size_t)b * NCLS + c] = acc[c];
}

/* ------------------------------- launch ---------------------------------- */
extern "C" void kernel_launch(void* const* d_in, const int* in_sizes, int n_in,
                              void* d_out, int out_size)
{
    const float* X_train = (const float*)d_in[0];
    const float* X_test  = (const float*)d_in[1];
    const float* enc_w1  = (const float*)d_in[2];
    const float* enc_b1  = (const float*)d_in[3];
    const float* ln1_g   = (const float*)d_in[4];
    const float* ln1_b   = (const float*)d_in[5];
    const float* enc_w2  = (const float*)d_in[6];
    const float* enc_b2  = (const float*)d_in[7];
    const float* ln2_g   = (const float*)d_in[8];
    const float* ln2_b   = (const float*)d_in[9];
    const float* sw_w    = (const float*)d_in[10];
    const float* sw_b    = (const float*)d_in[11];
    const float* sb_w    = (const float*)d_in[12];
    const float* sb_b    = (const float*)d_in[13];
    const float* lf_w    = (const float*)d_in[14];
    const float* lf_b    = (const float*)d_in[15];
    const float* tw_w    = (const float*)d_in[16];
    const float* tw_b    = (const float*)d_in[17];

    float *C1, *C2, *part, *ctx, *sw, *sb, *lf, *tw, *W, *dec;
    __nv_bfloat16 *H1h, *H1l, *Xtrh, *Xtrl, *W1h, *W1l, *W2h, *W2l, *Xteh, *Xtel, *SWh, *SWl;
    cudaGetSymbolAddress((void**)&C1,   g_C1);
    cudaGetSymbolAddress((void**)&C2,   g_C2);
    cudaGetSymbolAddress((void**)&H1h,  g_H1h);
    cudaGetSymbolAddress((void**)&H1l,  g_H1l);
    cudaGetSymbolAddress((void**)&Xtrh, g_Xtrh);
    cudaGetSymbolAddress((void**)&Xtrl, g_Xtrl);
    cudaGetSymbolAddress((void**)&W1h,  g_W1h);
    cudaGetSymbolAddress((void**)&W1l,  g_W1l);
    cudaGetSymbolAddress((void**)&W2h,  g_W2h);
    cudaGetSymbolAddress((void**)&W2l,  g_W2l);
    cudaGetSymbolAddress((void**)&Xteh, g_Xteh);
    cudaGetSymbolAddress((void**)&Xtel, g_Xtel);
    cudaGetSymbolAddress((void**)&SWh,  g_SWh);
    cudaGetSymbolAddress((void**)&SWl,  g_SWl);
    cudaGetSymbolAddress((void**)&part, g_part);
    cudaGetSymbolAddress((void**)&ctx,  g_ctx);
    cudaGetSymbolAddress((void**)&sw,   g_sw);
    cudaGetSymbolAddress((void**)&sb,   g_sb);
    cudaGetSymbolAddress((void**)&lf,   g_lf);
    cudaGetSymbolAddress((void**)&tw,   g_tw);
    cudaGetSymbolAddress((void**)&W,    g_W);
    cudaGetSymbolAddress((void**)&dec,  g_dec);

    cudaFuncSetAttribute((const void*)gemm_tc<0>,
                         cudaFuncAttributeMaxDynamicSharedMemorySize, 2*STAGE);
    cudaFuncSetAttribute((const void*)gemm_tc<1>,
                         cudaFuncAttributeMaxDynamicSharedMemorySize, 2*STAGE);

    /* pre-split static inputs to bf16 hi/lo (grid-stride x4 for MLP) */
    split_f32<<<(M_TRAIN*DIN/4 + 1023)/1024, 256>>>(X_train, Xtrh, Xtrl, M_TRAIN*DIN/4);
    split_f32<<<(HID*DIN/4     + 1023)/1024, 256>>>(enc_w1,  W1h,  W1l,  HID*DIN/4);
    split_f32<<<(HID*HID/4     + 1023)/1024, 256>>>(enc_w2,  W2h,  W2l,  HID*HID/4);
    split_f32<<<(M_TEST*DIN/4  + 1023)/1024, 256>>>(X_test,  Xteh, Xtel, M_TEST*DIN/4);

    /* encoder */
    gemm_tc<0><<<dim3(HID/128, M_TRAIN/128), 256, 2*STAGE>>>(
        Xtrh, Xtrl, W1h, W1l, enc_b1, C1, M_TRAIN, HID, DIN);
    ln_relu<1><<<M_TRAIN, 256>>>(C1, nullptr, H1h, H1l, ln1_g, ln1_b);
    gemm_tc<0><<<dim3(HID/128, M_TRAIN/128), 256, 2*STAGE>>>(
        H1h, H1l, W2h, W2l, enc_b2, C2, M_TRAIN, HID, HID);
    ln_relu<0><<<M_TRAIN, 256>>>(C2, C2, nullptr, nullptr, ln2_g, ln2_b);

    /* ctx = mean over rows */
    col_partial<<<dim3(HID/256, 64), 256>>>(C2, part);
    col_final<<<HID/256, 256>>>(part, ctx);

    /* hypernet matvecs (HBM-bound 260 MB stream) */
    matvec<<<(SW_ROWS*32 + 255)/256, 256>>>(sw_w, sw_b, ctx, sw, SW_ROWS);
    matvec<<<(NSPLIT*32 + 255)/256, 256>>>(sb_w, sb_b, ctx, sb, NSPLIT);
    matvec<<<(LF_ROWS*32 + 255)/256, 256>>>(lf_w, lf_b, ctx, lf, LF_ROWS);
    matvec<<<(NTREES*32 + 255)/256, 256>>>(tw_w, tw_b, ctx, tw, NTREES);

    /* split sw, then dec = sigmoid(X_test @ sw^T + sb), stored transposed */
    split_f32<<<(SW_ROWS/4 + 1023)/1024, 256>>>(sw, SWh, SWl, SW_ROWS/4);
    gemm_tc<1><<<dim3((NSPLIT + 127)/128, M_TEST/128), 256, 2*STAGE>>>(
        Xteh, Xtel, SWh, SWl, sb, dec, M_TEST, NSPLIT, DIN);

    /* fold softmaxes, then route */
    make_W<<<1, 512>>>(tw, lf, W);
    route_kernel<<<M_TEST/256, 256>>>(dec, W, (float*)d_out);
}

// round 5
// speedup vs baseline: 1.6002x; 1.0051x over previous
#include <cuda_runtime.h>
#include <cuda_bf16.h>
#include <math.h>
#include <stdint.h>

typedef __nv_bfloat16 bf16;

#define M_TRAIN 4096
#define M_TEST  16384
#define DIN     128
#define HID     1024
#define NTREES  16
#define NINT    31
#define NLEAF   32
#define NCLS    10
#define NSPLIT  (NTREES*NINT)        /* 496 */
#define SW_ROWS (NTREES*NINT*DIN)    /* 63488 */
#define LF_ROWS (NTREES*NLEAF*NCLS)  /* 5120 */

/* ---------------- scratch (static device memory; no allocs) -------------- */
__device__ float g_C1[M_TRAIN*HID];
__device__ float g_C2[M_TRAIN*HID];
__device__ bf16 g_H1h[M_TRAIN*HID];
__device__ bf16 g_H1l[M_TRAIN*HID];
__device__ bf16 g_Xtrh[M_TRAIN*DIN], g_Xtrl[M_TRAIN*DIN];
__device__ bf16 g_W1h[HID*DIN],     g_W1l[HID*DIN];
__device__ bf16 g_W2h[HID*HID],     g_W2l[HID*HID];
__device__ bf16 g_Xteh[M_TEST*DIN], g_Xtel[M_TEST*DIN];
__device__ bf16 g_SWh[SW_ROWS],     g_SWl[SW_ROWS];
__device__ float g_part[64*HID];
__device__ float g_ctx[HID];
__device__ float g_sb[NSPLIT];
__device__ float g_lf[LF_ROWS];
__device__ float g_tw[NTREES];
__device__ float g_W[LF_ROWS];
__device__ float g_dec[NSPLIT*M_TEST];       /* TRANSPOSED [496][16384] */

/* ------------------------------ PTX helpers ------------------------------ */
__device__ __forceinline__ uint32_t cvta_sm(const void* p) {
    return (uint32_t)__cvta_generic_to_shared(p);
}
__device__ __forceinline__ void cp16(uint32_t dst, const void* src, int sz) {
    asm volatile("cp.async.cg.shared.global [%0], [%1], 16, %2;\n"
                 :: "r"(dst), "l"(src), "r"(sz));
}
__device__ __forceinline__ void cp_commit() {
    asm volatile("cp.async.commit_group;\n");
}
__device__ __forceinline__ void ldsm4(unsigned& r0, unsigned& r1,
                                      unsigned& r2, unsigned& r3, uint32_t a) {
    asm volatile("ldmatrix.sync.aligned.m8n8.x4.shared.b16 {%0,%1,%2,%3}, [%4];"
                 : "=r"(r0), "=r"(r1), "=r"(r2), "=r"(r3) : "r"(a));
}
__device__ __forceinline__ void mma_bf16(float c[4], unsigned a0, unsigned a1,
                                         unsigned a2, unsigned a3,
                                         unsigned b0, unsigned b1)
{
    asm volatile(
        "mma.sync.aligned.m16n8k16.row.col.f32.bf16.bf16.f32 "
        "{%0,%1,%2,%3}, {%4,%5,%6,%7}, {%8,%9}, {%0,%1,%2,%3};"
        : "+f"(c[0]), "+f"(c[1]), "+f"(c[2]), "+f"(c[3])
        : "r"(a0), "r"(a1), "r"(a2), "r"(a3), "r"(b0), "r"(b1));
}
/* swizzled byte offset inside a 128x32-bf16 tile */
__device__ __forceinline__ uint32_t swz(int r, int hb) {
    return (uint32_t)(r*64 + ((hb ^ ((r>>1)&3)) << 4));
}

/* ------------------------ split fp32 -> bf16 hi/lo ----------------------- */
__global__ void split_f32(const float* __restrict__ x, bf16* __restrict__ hi,
                          bf16* __restrict__ lo, int n4)
{
    int i0 = blockIdx.x * (blockDim.x * 4) + threadIdx.x;
    float4 v[4];
    bool ok[4];
#pragma unroll
    for (int u = 0; u < 4; u++) {
        int i = i0 + u*256;
        ok[u] = (i < n4);
        if (ok[u]) v[u] = ((const float4*)x)[i];
    }
#pragma unroll
    for (int u = 0; u < 4; u++) {
        if (!ok[u]) continue;
        int i = i0 + u*256;
        bf16 h0=__float2bfloat16(v[u].x), h1=__float2bfloat16(v[u].y);
        bf16 h2=__float2bfloat16(v[u].z), h3=__float2bfloat16(v[u].w);
        bf16 l0=__float2bfloat16(v[u].x-__bfloat162float(h0));
        bf16 l1=__float2bfloat16(v[u].y-__bfloat162float(h1));
        bf16 l2=__float2bfloat16(v[u].z-__bfloat162float(h2));
        bf16 l3=__float2bfloat16(v[u].w-__bfloat162float(h3));
        ((__nv_bfloat162*)hi)[i*2]   = __halves2bfloat162(h0, h1);
        ((__nv_bfloat162*)hi)[i*2+1] = __halves2bfloat162(h2, h3);
        ((__nv_bfloat162*)lo)[i*2]   = __halves2bfloat162(l0, l1);
        ((__nv_bfloat162*)lo)[i*2+1] = __halves2bfloat162(l2, l3);
    }
}

/* ----------------- tensor-core GEMM: C = A @ B^T + bias ------------------ */
/* 128x128 CTA tile, BK=32, 3-stage cp.async pipeline, ldmatrix fragments.   */
#define STAGE 32768
#define NSTG  3

template<int EPI>
__global__ void __launch_bounds__(256, 2) gemm_tc(
    const bf16* __restrict__ Ah, const bf16* __restrict__ Al,
    const bf16* __restrict__ Bh, const bf16* __restrict__ Bl,
    const float* __restrict__ bias, float* __restrict__ C,
    int M, int N, int K)
{
    extern __shared__ char dynsm[];
    const uint32_t smem = cvta_sm(dynsm);
    const int tid = threadIdx.x, lane = tid & 31, warp = tid >> 5;
    const int g = lane >> 2, t = lane & 3;
    const int wm = warp & 1, wn = warp >> 1;
    const int m0 = blockIdx.y * 128, n0 = blockIdx.x * 128;

    float c[4][4][4];
#pragma unroll
    for (int i = 0; i < 4; i++)
#pragma unroll
        for (int j = 0; j < 4; j++)
#pragma unroll
            for (int r = 0; r < 4; r++) c[i][j][r] = 0.f;

    const int kIters = K >> 5;

    auto load_stage = [&](int buf, int k0) {
        uint32_t sb = smem + buf * STAGE;
#pragma unroll
        for (int cc = 0; cc < 2; cc++) {
            int ch = tid + cc*256;
            int r = ch >> 2, hb = ch & 3;
            uint32_t so = swz(r, hb);
            size_t ga = (size_t)(m0 + r) * K + k0 + hb*8;
            cp16(sb + so,         Ah + ga, 16);
            cp16(sb + 8192 + so,  Al + ga, 16);
            int bn = n0 + r;
            int sz = (bn < N) ? 16 : 0;
            size_t gb = (size_t)(sz ? bn : 0) * K + k0 + hb*8;
            cp16(sb + 16384 + so, Bh + gb, sz);
            cp16(sb + 24576 + so, Bl + gb, sz);
        }
    };

    auto compute = [&](int buf) {
        uint32_t sb = smem + buf * STAGE;
        const int rl = lane & 15;
        const int hx = lane >> 4;
#pragma unroll
        for (int s = 0; s < 2; s++) {
            const int hb = s*2 + hx;
            unsigned bh[4][2], bl[4][2];
#pragma unroll
            for (int j2 = 0; j2 < 2; j2++) {
                int row = wn*32 + j2*16 + rl;
                uint32_t off = swz(row, hb);
                unsigned r0, r1, r2, r3;
                ldsm4(r0, r1, r2, r3, sb + 16384 + off);
                bh[j2*2][0]=r0; bh[j2*2][1]=r2; bh[j2*2+1][0]=r1; bh[j2*2+1][1]=r3;
                ldsm4(r0, r1, r2, r3, sb + 24576 + off);
                bl[j2*2][0]=r0; bl[j2*2][1]=r2; bl[j2*2+1][0]=r1; bl[j2*2+1][1]=r3;
            }
#pragma unroll
            for (int i = 0; i < 4; i++) {
                int row = wm*64 + i*16 + rl;
                uint32_t off = swz(row, hb);
                unsigned a0,a1,a2,a3, q0,q1,q2,q3;
                ldsm4(a0,a1,a2,a3, sb + off);
                ldsm4(q0,q1,q2,q3, sb + 8192 + off);
#pragma unroll
                for (int j = 0; j < 4; j++) {
                    mma_bf16(c[i][j], a0,a1,a2,a3, bh[j][0], bh[j][1]);
                    mma_bf16(c[i][j], a0,a1,a2,a3, bl[j][0], bl[j][1]);
                    mma_bf16(c[i][j], q0,q1,q2,q3, bh[j][0], bh[j][1]);
                }
            }
        }
    };

    /* 3-stage pipeline: ~2 compute periods of in-flight latency per load */
    load_stage(0, 0);
    cp_commit();
    load_stage(1, 32);
    cp_commit();
    for (int it = 0; it < kIters; it++) {
        if (it + 1 < kIters)
            asm volatile("cp.async.wait_group 1;\n" ::: "memory");
        else
            asm volatile("cp.async.wait_group 0;\n" ::: "memory");
        __syncthreads();
        compute(it % NSTG);
        __syncthreads();
        if (it + 2 < kIters) {
            load_stage((it+2) % NSTG, (it+2)*32);
            cp_commit();
        }
    }

    if (EPI == 0) {
#pragma unroll
        for (int i = 0; i < 4; i++) {
            int r0 = m0 + wm*64 + i*16 + g;
#pragma unroll
            for (int j = 0; j < 4; j++) {
                int col = n0 + wn*32 + j*8 + 2*t;
                float b0 = bias[col], b1 = bias[col+1];
                float2 v0 = make_float2(c[i][j][0] + b0, c[i][j][1] + b1);
                float2 v1 = make_float2(c[i][j][2] + b0, c[i][j][3] + b1);
                *(float2*)&C[(size_t)r0     * N + col] = v0;
                *(float2*)&C[(size_t)(r0+8) * N + col] = v1;
            }
        }
    } else {
        float (*trans)[132] = reinterpret_cast<float(*)[132]>(dynsm);
#pragma unroll
        for (int chunk = 0; chunk < 4; chunk++) {
            __syncthreads();
            if (wn == chunk) {
#pragma unroll
                for (int i = 0; i < 4; i++) {
                    int mm = wm*64 + i*16 + g;
#pragma unroll
                    for (int j = 0; j < 4; j++) {
                        int nn  = j*8 + 2*t;
                        int col = n0 + chunk*32 + nn;
                        float b0 = (col     < N) ? bias[col]   : 0.f;
                        float b1 = (col + 1 < N) ? bias[col+1] : 0.f;
                        float v0 = c[i][j][0] + b0, v1 = c[i][j][1] + b1;
                        float v2 = c[i][j][2] + b0, v3 = c[i][j][3] + b1;
                        trans[nn  ][mm  ] = 1.f / (1.f + __expf(-v0));
                        trans[nn+1][mm  ] = 1.f / (1.f + __expf(-v1));
                        trans[nn  ][mm+8] = 1.f / (1.f + __expf(-v2));
                        trans[nn+1][mm+8] = 1.f / (1.f + __expf(-v3));
                    }
                }
            }
            __syncthreads();
#pragma unroll
            for (int p = 0; p < 4; p++) {
                int idx  = tid + p*256;
                int rowb = idx >> 5;
                int mc   = (idx & 31) * 4;
                int ngl  = n0 + chunk*32 + rowb;
                if (ngl < N)
                    *(float4*)&C[(size_t)ngl * M_TEST + m0 + mc] =
                        *(float4*)&trans[rowb][mc];
            }
        }
    }
}

/* ------------- LayerNorm + ReLU; SPLIT=1 emits bf16 hi/lo ---------------- */
template<int SPLIT>
__global__ void ln_relu(const float* __restrict__ X, float* __restrict__ Y,
                        bf16* __restrict__ Yh, bf16* __restrict__ Yl,
                        const float* __restrict__ gg, const float* __restrict__ bb)
{
    const int row = blockIdx.x, tid = threadIdx.x;
    const float4 v = ((const float4*)(X + (size_t)row * HID))[tid];
    float s = v.x + v.y + v.z + v.w;
    float q = v.x*v.x + v.y*v.y + v.z*v.z + v.w*v.w;
#pragma unroll
    for (int o = 16; o; o >>= 1) {
        s += __shfl_xor_sync(0xffffffffu, s, o);
        q += __shfl_xor_sync(0xffffffffu, q, o);
    }
    __shared__ float ss[8], qs[8];
    if ((tid & 31) == 0) { ss[tid >> 5] = s; qs[tid >> 5] = q; }
    __syncthreads();
    s = ss[0]+ss[1]+ss[2]+ss[3]+ss[4]+ss[5]+ss[6]+ss[7];
    q = qs[0]+qs[1]+qs[2]+qs[3]+qs[4]+qs[5]+qs[6]+qs[7];
    float mean = s * (1.f/HID);
    float inv  = rsqrtf(q * (1.f/HID) - mean*mean + 1e-5f);
    float4 gv = ((const float4*)gg)[tid];
    float4 bv = ((const float4*)bb)[tid];
    float4 y;
    y.x = fmaxf((v.x - mean)*inv*gv.x + bv.x, 0.f);
    y.y = fmaxf((v.y - mean)*inv*gv.y + bv.y, 0.f);
    y.z = fmaxf((v.z - mean)*inv*gv.z + bv.z, 0.f);
    y.w = fmaxf((v.w - mean)*inv*gv.w + bv.w, 0.f);
    if (SPLIT) {
        bf16 h0=__float2bfloat16(y.x), h1=__float2bfloat16(y.y);
        bf16 h2=__float2bfloat16(y.z), h3=__float2bfloat16(y.w);
        bf16 l0=__float2bfloat16(y.x-__bfloat162float(h0));
        bf16 l1=__float2bfloat16(y.y-__bfloat162float(h1));
        bf16 l2=__float2bfloat16(y.z-__bfloat162float(h2));
        bf16 l3=__float2bfloat16(y.w-__bfloat162float(h3));
        __nv_bfloat162* ph = (__nv_bfloat162*)(Yh + (size_t)row * HID);
        __nv_bfloat162* pl = (__nv_bfloat162*)(Yl + (size_t)row * HID);
        ph[tid*2]   = __halves2bfloat162(h0, h1);
        ph[tid*2+1] = __halves2bfloat162(h2, h3);
        pl[tid*2]   = __halves2bfloat162(l0, l1);
        pl[tid*2+1] = __halves2bfloat162(l2, l3);
    } else {
        ((float4*)(Y + (size_t)row * HID))[tid] = y;
    }
}

/* --------------------- column mean over rows -> ctx ---------------------- */
__global__ void col_partial(const float* __restrict__ X, float* __restrict__ part)
{
    int col   = blockIdx.x * 256 + threadIdx.x;
    int chunk = blockIdx.y;
    float s = 0.f;
    int r0 = chunk * 64;
    for (int r = r0; r < r0 + 64; r++) s += X[(size_t)r * HID + col];
    part[(size_t)chunk * HID + col] = s;
}
__global__ void col_final(const float* __restrict__ part, float* __restrict__ ctx)
{
    int col = blockIdx.x * 256 + threadIdx.x;
    float s = 0.f;
    for (int c = 0; c < 64; c++) s += part[(size_t)c * HID + col];
    ctx[col] = s * (1.f / M_TRAIN);
}

/* ------------------ hypernet matvec: out = W @ ctx + bias ---------------- */
__global__ void matvec(const float* __restrict__ W, const float* __restrict__ bias,
                       const float* __restrict__ ctx, float* __restrict__ out, int rows)
{
    int gw   = (blockIdx.x * blockDim.x + threadIdx.x) >> 5;
    int lane = threadIdx.x & 31;
    if (gw >= rows) return;
    const float4* w4 = (const float4*)(W + (size_t)gw * HID);
    const float4* c4 = (const float4*)ctx;
    float s = 0.f;
#pragma unroll
    for (int i = 0; i < 8; i++) {
        float4 a = w4[lane + 32*i];
        float4 c = __ldg(&c4[lane + 32*i]);
        s += a.x*c.x + a.y*c.y + a.z*c.z + a.w*c.w;
    }
#pragma unroll
    for (int o = 16; o; o >>= 1) s += __shfl_xor_sync(0xffffffffu, s, o);
    if (lane == 0) out[gw] = s + bias[gw];
}

/* ---- matvec emitting split bf16 hi/lo directly (for split_w) ------------ */
__global__ void matvec_split(const float* __restrict__ W, const float* __restrict__ bias,
                             const float* __restrict__ ctx,
                             bf16* __restrict__ oh, bf16* __restrict__ ol, int rows)
{
    int gw   = (blockIdx.x * blockDim.x + threadIdx.x) >> 5;
    int lane = threadIdx.x & 31;
    if (gw >= rows) return;
    const float4* w4 = (const float4*)(W + (size_t)gw * HID);
    const float4* c4 = (const float4*)ctx;
    float s = 0.f;
#pragma unroll
    for (int i = 0; i < 8; i++) {
        float4 a = w4[lane + 32*i];
        float4 c = __ldg(&c4[lane + 32*i]);
        s += a.x*c.x + a.y*c.y + a.z*c.z + a.w*c.w;
    }
#pragma unroll
    for (int o = 16; o; o >>= 1) s += __shfl_xor_sync(0xffffffffu, s, o);
    if (lane == 0) {
        float v = s + bias[gw];
        bf16 h = __float2bfloat16(v);
        oh[gw] = h;
        ol[gw] = __float2bfloat16(v - __bfloat162float(h));
    }
}

/* ---- fold tree_w softmax + leaf softmax into one table W[t,l,c] --------- */
__global__ void make_W(const float* __restrict__ tw, const float* __restrict__ lf,
                       float* __restrict__ Wout)
{
    __shared__ float tws[NTREES];
    int tid = threadIdx.x;
    if (tid == 0) {
        float mx = -1e30f;
        for (int i = 0; i < NTREES; i++) mx = fmaxf(mx, tw[i]);
        float e[NTREES], s = 0.f;
        for (int i = 0; i < NTREES; i++) { e[i] = expf(tw[i] - mx); s += e[i]; }
        for (int i = 0; i < NTREES; i++) tws[i] = e[i] / s;
    }
    __syncthreads();
    if (tid < NTREES * NLEAF) {
        const float* L = lf + tid * NCLS;
        float mx = -1e30f;
        for (int c = 0; c < NCLS; c++) mx = fmaxf(mx, L[c]);
        float e[NCLS], s = 0.f;
        for (int c = 0; c < NCLS; c++) { e[c] = expf(L[c] - mx); s += e[c]; }
        float scale = tws[tid >> 5] / s;
        for (int c = 0; c < NCLS; c++) Wout[tid * NCLS + c] = e[c] * scale;
    }
}

/* ------------- soft tree routing + class combine, thread per row --------- */
__global__ void route_kernel(const float* __restrict__ dec, const float* __restrict__ W,
                             float* __restrict__ out)
{
    __shared__ float Ws[LF_ROWS];
    int tid = threadIdx.x;
    for (int i = tid; i < LF_ROWS; i += 256) Ws[i] = W[i];
    __syncthreads();
    int b = blockIdx.x * 256 + tid;
    float acc[NCLS];
#pragma unroll
    for (int c = 0; c < NCLS; c++) acc[c] = 0.f;

    for (int t = 0; t < NTREES; t++) {
        float d[NINT];
#pragma unroll
        for (int n = 0; n < NINT; n++)
            d[n] = dec[(size_t)(t*NINT + n) * M_TEST + b];
#pragma unroll
        for (int l = 0; l < NLEAF; l++) {
            float p = 1.f;
#pragma unroll
            for (int dd = 0; dd < 5; dd++) {
                int node = (1 << dd) - 1 + (l >> (5 - dd));
                int go   = (l >> (4 - dd)) & 1;
                p *= go ? d[node] : (1.f - d[node]);
            }
            const float* w = &Ws[(t*NLEAF + l) * NCLS];
#pragma unroll
            for (int c = 0; c < NCLS; c++) acc[c] += p * w[c];
        }
    }
#pragma unroll
    for (int c = 0; c < NCLS; c++) out[(size_t)b * NCLS + c] = acc[c];
}

/* ------------------------------- launch ---------------------------------- */
extern "C" void kernel_launch(void* const* d_in, const int* in_sizes, int n_in,
                              void* d_out, int out_size)
{
    const float* X_train = (const float*)d_in[0];
    const float* X_test  = (const float*)d_in[1];
    const float* enc_w1  = (const float*)d_in[2];
    const float* enc_b1  = (const float*)d_in[3];
    const float* ln1_g   = (const float*)d_in[4];
    const float* ln1_b   = (const float*)d_in[5];
    const float* enc_w2  = (const float*)d_in[6];
    const float* enc_b2  = (const float*)d_in[7];
    const float* ln2_g   = (const float*)d_in[8];
    const float* ln2_b   = (const float*)d_in[9];
    const float* sw_w    = (const float*)d_in[10];
    const float* sw_b    = (const float*)d_in[11];
    const float* sb_w    = (const float*)d_in[12];
    const float* sb_b    = (const float*)d_in[13];
    const float* lf_w    = (const float*)d_in[14];
    const float* lf_b    = (const float*)d_in[15];
    const float* tw_w    = (const float*)d_in[16];
    const float* tw_b    = (const float*)d_in[17];

    float *C1, *C2, *part, *ctx, *sb, *lf, *tw, *W, *dec;
    bf16 *H1h, *H1l, *Xtrh, *Xtrl, *W1h, *W1l, *W2h, *W2l, *Xteh, *Xtel, *SWh, *SWl;
    cudaGetSymbolAddress((void**)&C1,   g_C1);
    cudaGetSymbolAddress((void**)&C2,   g_C2);
    cudaGetSymbolAddress((void**)&H1h,  g_H1h);
    cudaGetSymbolAddress((void**)&H1l,  g_H1l);
    cudaGetSymbolAddress((void**)&Xtrh, g_Xtrh);
    cudaGetSymbolAddress((void**)&Xtrl, g_Xtrl);
    cudaGetSymbolAddress((void**)&W1h,  g_W1h);
    cudaGetSymbolAddress((void**)&W1l,  g_W1l);
    cudaGetSymbolAddress((void**)&W2h,  g_W2h);
    cudaGetSymbolAddress((void**)&W2l,  g_W2l);
    cudaGetSymbolAddress((void**)&Xteh, g_Xteh);
    cudaGetSymbolAddress((void**)&Xtel, g_Xtel);
    cudaGetSymbolAddress((void**)&SWh,  g_SWh);
    cudaGetSymbolAddress((void**)&SWl,  g_SWl);
    cudaGetSymbolAddress((void**)&part, g_part);
    cudaGetSymbolAddress((void**)&ctx,  g_ctx);
    cudaGetSymbolAddress((void**)&sb,   g_sb);
    cudaGetSymbolAddress((void**)&lf,   g_lf);
    cudaGetSymbolAddress((void**)&tw,   g_tw);
    cudaGetSymbolAddress((void**)&W,    g_W);
    cudaGetSymbolAddress((void**)&dec,  g_dec);

    cudaFuncSetAttribute((const void*)gemm_tc<0>,
                         cudaFuncAttributeMaxDynamicSharedMemorySize, NSTG*STAGE);
    cudaFuncSetAttribute((const void*)gemm_tc<1>,
                         cudaFuncAttributeMaxDynamicSharedMemorySize, NSTG*STAGE);

    /* pre-split static inputs to bf16 hi/lo */
    split_f32<<<(M_TRAIN*DIN/4 + 1023)/1024, 256>>>(X_train, Xtrh, Xtrl, M_TRAIN*DIN/4);
    split_f32<<<(HID*DIN/4     + 1023)/1024, 256>>>(enc_w1,  W1h,  W1l,  HID*DIN/4);
    split_f32<<<(HID*HID/4     + 1023)/1024, 256>>>(enc_w2,  W2h,  W2l,  HID*HID/4);
    split_f32<<<(M_TEST*DIN/4  + 1023)/1024, 256>>>(X_test,  Xteh, Xtel, M_TEST*DIN/4);

    /* encoder */
    gemm_tc<0><<<dim3(HID/128, M_TRAIN/128), 256, NSTG*STAGE>>>(
        Xtrh, Xtrl, W1h, W1l, enc_b1, C1, M_TRAIN, HID, DIN);
    ln_relu<1><<<M_TRAIN, 256>>>(C1, nullptr, H1h, H1l, ln1_g, ln1_b);
    gemm_tc<0><<<dim3(HID/128, M_TRAIN/128), 256, NSTG*STAGE>>>(
        H1h, H1l, W2h, W2l, enc_b2, C2, M_TRAIN, HID, HID);
    ln_relu<0><<<M_TRAIN, 256>>>(C2, C2, nullptr, nullptr, ln2_g, ln2_b);

    /* ctx = mean over rows */
    col_partial<<<dim3(HID/256, 64), 256>>>(C2, part);
    col_final<<<HID/256, 256>>>(part, ctx);

    /* hypernet matvecs; sw emits split bf16 directly */
    matvec_split<<<(SW_ROWS*32 + 255)/256, 256>>>(sw_w, sw_b, ctx, SWh, SWl, SW_ROWS);
    matvec<<<(NSPLIT*32 + 255)/256, 256>>>(sb_w, sb_b, ctx, sb, NSPLIT);
    matvec<<<(LF_ROWS*32 + 255)/256, 256>>>(lf_w, lf_b, ctx, lf, LF_ROWS);
    matvec<<<(NTREES*32 + 255)/256, 256>>>(tw_w, tw_b, ctx, tw, NTREES);

    /* dec = sigmoid(X_test @ split_w^T + sb), stored transposed */
    gemm_tc<1><<<dim3((NSPLIT + 127)/128, M_TEST/128), 256, NSTG*STAGE>>>(
        Xteh, Xtel, SWh, SWl, sb, dec, M_TEST, NSPLIT, DIN);

    /* fold softmaxes, then route */
    make_W<<<1, 512>>>(tw, lf, W);
    route_kernel<<<M_TEST/256, 256>>>(dec, W, (float*)d_out);
}

// round 6
// speedup vs baseline: 1.7764x; 1.1101x over previous
#include <cuda_runtime.h>
#include <cuda_bf16.h>
#include <math.h>
#include <stdint.h>

typedef __nv_bfloat16 bf16;

#define M_TRAIN 4096
#define M_TEST  16384
#define DIN     128
#define HID     1024
#define NTREES  16
#define NINT    31
#define NLEAF   32
#define NCLS    10
#define NSPLIT  (NTREES*NINT)        /* 496 */
#define SW_ROWS (NTREES*NINT*DIN)    /* 63488 */
#define LF_ROWS (NTREES*NLEAF*NCLS)  /* 5120 */

/* ---------------- scratch (static device memory; no allocs) -------------- */
__device__ float g_C1[M_TRAIN*HID];
__device__ float g_C2[M_TRAIN*HID];
__device__ bf16 g_H1h[M_TRAIN*HID];
__device__ bf16 g_Xtrh[M_TRAIN*DIN];
__device__ bf16 g_W1h[HID*DIN],     g_W1l[HID*DIN];
__device__ bf16 g_W2h[HID*HID],     g_W2l[HID*HID];
__device__ bf16 g_Xteh[M_TEST*DIN], g_Xtel[M_TEST*DIN];
__device__ bf16 g_SWh[SW_ROWS],     g_SWl[SW_ROWS];
__device__ float g_part[64*HID];
__device__ float g_ctx[HID];
__device__ float g_sb[NSPLIT];
__device__ float g_lf[LF_ROWS];
__device__ float g_tw[NTREES];
__device__ float g_W[LF_ROWS];
__device__ float g_dec[NSPLIT*M_TEST];       /* TRANSPOSED [496][16384] */

/* ------------------------------ PTX helpers ------------------------------ */
__device__ __forceinline__ uint32_t cvta_sm(const void* p) {
    return (uint32_t)__cvta_generic_to_shared(p);
}
__device__ __forceinline__ void cp16(uint32_t dst, const void* src, int sz) {
    asm volatile("cp.async.cg.shared.global [%0], [%1], 16, %2;\n"
                 :: "r"(dst), "l"(src), "r"(sz));
}
__device__ __forceinline__ void cp_commit() {
    asm volatile("cp.async.commit_group;\n");
}
__device__ __forceinline__ void ldsm4(unsigned& r0, unsigned& r1,
                                      unsigned& r2, unsigned& r3, uint32_t a) {
    asm volatile("ldmatrix.sync.aligned.m8n8.x4.shared.b16 {%0,%1,%2,%3}, [%4];"
                 : "=r"(r0), "=r"(r1), "=r"(r2), "=r"(r3) : "r"(a));
}
__device__ __forceinline__ void mma_bf16(float c[4], unsigned a0, unsigned a1,
                                         unsigned a2, unsigned a3,
                                         unsigned b0, unsigned b1)
{
    asm volatile(
        "mma.sync.aligned.m16n8k16.row.col.f32.bf16.bf16.f32 "
        "{%0,%1,%2,%3}, {%4,%5,%6,%7}, {%8,%9}, {%0,%1,%2,%3};"
        : "+f"(c[0]), "+f"(c[1]), "+f"(c[2]), "+f"(c[3])
        : "r"(a0), "r"(a1), "r"(a2), "r"(a3), "r"(b0), "r"(b1));
}
/* swizzled byte offset inside a (rows x 32) bf16 tile, 64B rows */
__device__ __forceinline__ uint32_t swz(int r, int hb) {
    return (uint32_t)(r*64 + ((hb ^ ((r>>1)&3)) << 4));
}

/* --------------- split fp32 -> bf16 hi (and optionally lo) --------------- */
template<int WLO>
__global__ void split_f32(const float* __restrict__ x, bf16* __restrict__ hi,
                          bf16* __restrict__ lo, int n4)
{
    int i0 = blockIdx.x * (blockDim.x * 4) + threadIdx.x;
    float4 v[4];
    bool ok[4];
#pragma unroll
    for (int u = 0; u < 4; u++) {
        int i = i0 + u*256;
        ok[u] = (i < n4);
        if (ok[u]) v[u] = ((const float4*)x)[i];
    }
#pragma unroll
    for (int u = 0; u < 4; u++) {
        if (!ok[u]) continue;
        int i = i0 + u*256;
        bf16 h0=__float2bfloat16(v[u].x), h1=__float2bfloat16(v[u].y);
        bf16 h2=__float2bfloat16(v[u].z), h3=__float2bfloat16(v[u].w);
        ((__nv_bfloat162*)hi)[i*2]   = __halves2bfloat162(h0, h1);
        ((__nv_bfloat162*)hi)[i*2+1] = __halves2bfloat162(h2, h3);
        if (WLO) {
            bf16 l0=__float2bfloat16(v[u].x-__bfloat162float(h0));
            bf16 l1=__float2bfloat16(v[u].y-__bfloat162float(h1));
            bf16 l2=__float2bfloat16(v[u].z-__bfloat162float(h2));
            bf16 l3=__float2bfloat16(v[u].w-__bfloat162float(h3));
            ((__nv_bfloat162*)lo)[i*2]   = __halves2bfloat162(l0, l1);
            ((__nv_bfloat162*)lo)[i*2+1] = __halves2bfloat162(l2, l3);
        }
    }
}

/* ------- encoder GEMM: C = A @ B^T + bias, A bf16-hi, B split (2 MMA) ---- */
/* CTA tile 256(M) x 128(N), warp tile 64x64, BK=32, 3-stage cp.async.      */
/* Stage 32KB: Ah@0 (16K), Bh@16K (8K), Bl@24K (8K).                        */
#define ESTAGE 32768
#define ENSTG  3

__global__ void __launch_bounds__(256, 1) gemm_enc(
    const bf16* __restrict__ Ah,
    const bf16* __restrict__ Bh, const bf16* __restrict__ Bl,
    const float* __restrict__ bias, float* __restrict__ C,
    int M, int N, int K)
{
    extern __shared__ char dynsm[];
    const uint32_t smem = cvta_sm(dynsm);
    const int tid = threadIdx.x, lane = tid & 31, warp = tid >> 5;
    const int g = lane >> 2, t = lane & 3;
    const int wm = warp & 3, wn = warp >> 2;      /* 4(m) x 2(n) warps */
    const int m0 = blockIdx.y * 256, n0 = blockIdx.x * 128;

    float c[4][8][4];
#pragma unroll
    for (int i = 0; i < 4; i++)
#pragma unroll
        for (int j = 0; j < 8; j++)
#pragma unroll
            for (int r = 0; r < 4; r++) c[i][j][r] = 0.f;

    const int kIters = K >> 5;

    auto load_stage = [&](int buf, int k0) {
        uint32_t sb = smem + buf * ESTAGE;
        /* A: 256 rows x 64B = 1024 cp16 -> 4/thread */
#pragma unroll
        for (int x = 0; x < 4; x++) {
            int ch = tid + x*256;
            int r = ch >> 2, hb = ch & 3;
            cp16(sb + swz(r, hb), Ah + (size_t)(m0 + r) * K + k0 + hb*8, 16);
        }
        /* B: 128 rows x 64B, hi+lo: 512 each -> 2+2/thread */
#pragma unroll
        for (int x = 0; x < 2; x++) {
            int ch = tid + x*256;
            int r = ch >> 2, hb = ch & 3;
            uint32_t so = swz(r, hb);
            size_t gb = (size_t)(n0 + r) * K + k0 + hb*8;
            cp16(sb + 16384 + so, Bh + gb, 16);
            cp16(sb + 24576 + so, Bl + gb, 16);
        }
    };

    auto compute = [&](int buf) {
        uint32_t sb = smem + buf * ESTAGE;
        const int rl = lane & 15;
        const int hx = lane >> 4;
#pragma unroll
        for (int s = 0; s < 2; s++) {
            const int hb = s*2 + hx;
            /* B fragments: warp's 64 columns, hi+lo */
            unsigned bh[8][2], bl[8][2];
#pragma unroll
            for (int j2 = 0; j2 < 4; j2++) {
                int row = wn*64 + j2*16 + rl;
                uint32_t off = swz(row, hb);
                unsigned r0, r1, r2, r3;
                ldsm4(r0, r1, r2, r3, sb + 16384 + off);
                bh[j2*2][0]=r0; bh[j2*2][1]=r2; bh[j2*2+1][0]=r1; bh[j2*2+1][1]=r3;
                ldsm4(r0, r1, r2, r3, sb + 24576 + off);
                bl[j2*2][0]=r0; bl[j2*2][1]=r2; bl[j2*2+1][0]=r1; bl[j2*2+1][1]=r3;
            }
#pragma unroll
            for (int i = 0; i < 4; i++) {
                int row = wm*64 + i*16 + rl;
                unsigned a0,a1,a2,a3;
                ldsm4(a0,a1,a2,a3, sb + swz(row, hb));
#pragma unroll
                for (int j = 0; j < 8; j++) {
                    mma_bf16(c[i][j], a0,a1,a2,a3, bh[j][0], bh[j][1]);
                    mma_bf16(c[i][j], a0,a1,a2,a3, bl[j][0], bl[j][1]);
                }
            }
        }
    };

    load_stage(0, 0);
    cp_commit();
    load_stage(1, 32);
    cp_commit();
    for (int it = 0; it < kIters; it++) {
        if (it + 1 < kIters)
            asm volatile("cp.async.wait_group 1;\n" ::: "memory");
        else
            asm volatile("cp.async.wait_group 0;\n" ::: "memory");
        __syncthreads();
        compute(it % ENSTG);
        __syncthreads();
        if (it + 2 < kIters) {
            load_stage((it+2) % ENSTG, (it+2)*32);
            cp_commit();
        }
    }

#pragma unroll
    for (int i = 0; i < 4; i++) {
        int r0 = m0 + wm*64 + i*16 + g;
#pragma unroll
        for (int j = 0; j < 8; j++) {
            int col = n0 + wn*64 + j*8 + 2*t;
            float b0 = bias[col], b1 = bias[col+1];
            float2 v0 = make_float2(c[i][j][0] + b0, c[i][j][1] + b1);
            float2 v1 = make_float2(c[i][j][2] + b0, c[i][j][3] + b1);
            *(float2*)&C[(size_t)r0     * N + col] = v0;
            *(float2*)&C[(size_t)(r0+8) * N + col] = v1;
        }
    }
}

/* --------- dec GEMM (full bf16x3): sigmoid + transposed store ------------ */
#define STAGE 32768
#define NSTG  3

__global__ void __launch_bounds__(256, 2) gemm_dec(
    const bf16* __restrict__ Ah, const bf16* __restrict__ Al,
    const bf16* __restrict__ Bh, const bf16* __restrict__ Bl,
    const float* __restrict__ bias, float* __restrict__ C,
    int M, int N, int K)
{
    extern __shared__ char dynsm[];
    const uint32_t smem = cvta_sm(dynsm);
    const int tid = threadIdx.x, lane = tid & 31, warp = tid >> 5;
    const int g = lane >> 2, t = lane & 3;
    const int wm = warp & 1, wn = warp >> 1;
    const int m0 = blockIdx.y * 128, n0 = blockIdx.x * 128;

    float c[4][4][4];
#pragma unroll
    for (int i = 0; i < 4; i++)
#pragma unroll
        for (int j = 0; j < 4; j++)
#pragma unroll
            for (int r = 0; r < 4; r++) c[i][j][r] = 0.f;

    const int kIters = K >> 5;

    auto load_stage = [&](int buf, int k0) {
        uint32_t sb = smem + buf * STAGE;
#pragma unroll
        for (int cc = 0; cc < 2; cc++) {
            int ch = tid + cc*256;
            int r = ch >> 2, hb = ch & 3;
            uint32_t so = swz(r, hb);
            size_t ga = (size_t)(m0 + r) * K + k0 + hb*8;
            cp16(sb + so,         Ah + ga, 16);
            cp16(sb + 8192 + so,  Al + ga, 16);
            int bn = n0 + r;
            int sz = (bn < N) ? 16 : 0;
            size_t gb = (size_t)(sz ? bn : 0) * K + k0 + hb*8;
            cp16(sb + 16384 + so, Bh + gb, sz);
            cp16(sb + 24576 + so, Bl + gb, sz);
        }
    };

    auto compute = [&](int buf) {
        uint32_t sb = smem + buf * STAGE;
        const int rl = lane & 15;
        const int hx = lane >> 4;
#pragma unroll
        for (int s = 0; s < 2; s++) {
            const int hb = s*2 + hx;
            unsigned bh[4][2], bl[4][2];
#pragma unroll
            for (int j2 = 0; j2 < 2; j2++) {
                int row = wn*32 + j2*16 + rl;
                uint32_t off = swz(row, hb);
                unsigned r0, r1, r2, r3;
                ldsm4(r0, r1, r2, r3, sb + 16384 + off);
                bh[j2*2][0]=r0; bh[j2*2][1]=r2; bh[j2*2+1][0]=r1; bh[j2*2+1][1]=r3;
                ldsm4(r0, r1, r2, r3, sb + 24576 + off);
                bl[j2*2][0]=r0; bl[j2*2][1]=r2; bl[j2*2+1][0]=r1; bl[j2*2+1][1]=r3;
            }
#pragma unroll
            for (int i = 0; i < 4; i++) {
                int row = wm*64 + i*16 + rl;
                uint32_t off = swz(row, hb);
                unsigned a0,a1,a2,a3, q0,q1,q2,q3;
                ldsm4(a0,a1,a2,a3, sb + off);
                ldsm4(q0,q1,q2,q3, sb + 8192 + off);
#pragma unroll
                for (int j = 0; j < 4; j++) {
                    mma_bf16(c[i][j], a0,a1,a2,a3, bh[j][0], bh[j][1]);
                    mma_bf16(c[i][j], a0,a1,a2,a3, bl[j][0], bl[j][1]);
                    mma_bf16(c[i][j], q0,q1,q2,q3, bh[j][0], bh[j][1]);
                }
            }
        }
    };

    load_stage(0, 0);
    cp_commit();
    load_stage(1, 32);
    cp_commit();
    for (int it = 0; it < kIters; it++) {
        if (it + 1 < kIters)
            asm volatile("cp.async.wait_group 1;\n" ::: "memory");
        else
            asm volatile("cp.async.wait_group 0;\n" ::: "memory");
        __syncthreads();
        compute(it % NSTG);
        __syncthreads();
        if (it + 2 < kIters) {
            load_stage((it+2) % NSTG, (it+2)*32);
            cp_commit();
        }
    }

    /* sigmoid + transposed store via smem staging */
    float (*trans)[132] = reinterpret_cast<float(*)[132]>(dynsm);
#pragma unroll
    for (int chunk = 0; chunk < 4; chunk++) {
        __syncthreads();
        if (wn == chunk) {
#pragma unroll
            for (int i = 0; i < 4; i++) {
                int mm = wm*64 + i*16 + g;
#pragma unroll
                for (int j = 0; j < 4; j++) {
                    int nn  = j*8 + 2*t;
                    int col = n0 + chunk*32 + nn;
                    float b0 = (col     < N) ? bias[col]   : 0.f;
                    float b1 = (col + 1 < N) ? bias[col+1] : 0.f;
                    float v0 = c[i][j][0] + b0, v1 = c[i][j][1] + b1;
                    float v2 = c[i][j][2] + b0, v3 = c[i][j][3] + b1;
                    trans[nn  ][mm  ] = 1.f / (1.f + __expf(-v0));
                    trans[nn+1][mm  ] = 1.f / (1.f + __expf(-v1));
                    trans[nn  ][mm+8] = 1.f / (1.f + __expf(-v2));
                    trans[nn+1][mm+8] = 1.f / (1.f + __expf(-v3));
                }
            }
        }
        __syncthreads();
#pragma unroll
        for (int p = 0; p < 4; p++) {
            int idx  = tid + p*256;
            int rowb = idx >> 5;
            int mc   = (idx & 31) * 4;
            int ngl  = n0 + chunk*32 + rowb;
            if (ngl < N)
                *(float4*)&C[(size_t)ngl * M_TEST + m0 + mc] =
                    *(float4*)&trans[rowb][mc];
        }
    }
}

/* ------------- LayerNorm + ReLU; SPLIT=1 emits bf16 hi only -------------- */
template<int SPLIT>
__global__ void ln_relu(const float* __restrict__ X, float* __restrict__ Y,
                        bf16* __restrict__ Yh,
                        const float* __restrict__ gg, const float* __restrict__ bb)
{
    const int row = blockIdx.x, tid = threadIdx.x;
    const float4 v = ((const float4*)(X + (size_t)row * HID))[tid];
    float s = v.x + v.y + v.z + v.w;
    float q = v.x*v.x + v.y*v.y + v.z*v.z + v.w*v.w;
#pragma unroll
    for (int o = 16; o; o >>= 1) {
        s += __shfl_xor_sync(0xffffffffu, s, o);
        q += __shfl_xor_sync(0xffffffffu, q, o);
    }
    __shared__ float ss[8], qs[8];
    if ((tid & 31) == 0) { ss[tid >> 5] = s; qs[tid >> 5] = q; }
    __syncthreads();
    s = ss[0]+ss[1]+ss[2]+ss[3]+ss[4]+ss[5]+ss[6]+ss[7];
    q = qs[0]+qs[1]+qs[2]+qs[3]+qs[4]+qs[5]+qs[6]+qs[7];
    float mean = s * (1.f/HID);
    float inv  = rsqrtf(q * (1.f/HID) - mean*mean + 1e-5f);
    float4 gv = ((const float4*)gg)[tid];
    float4 bv = ((const float4*)bb)[tid];
    float4 y;
    y.x = fmaxf((v.x - mean)*inv*gv.x + bv.x, 0.f);
    y.y = fmaxf((v.y - mean)*inv*gv.y + bv.y, 0.f);
    y.z = fmaxf((v.z - mean)*inv*gv.z + bv.z, 0.f);
    y.w = fmaxf((v.w - mean)*inv*gv.w + bv.w, 0.f);
    if (SPLIT) {
        __nv_bfloat162* ph = (__nv_bfloat162*)(Yh + (size_t)row * HID);
        ph[tid*2]   = __halves2bfloat162(__float2bfloat16(y.x), __float2bfloat16(y.y));
        ph[tid*2+1] = __halves2bfloat162(__float2bfloat16(y.z), __float2bfloat16(y.w));
    } else {
        ((float4*)(Y + (size_t)row * HID))[tid] = y;
    }
}

/* --------------------- column mean over rows -> ctx ---------------------- */
__global__ void col_partial(const float* __restrict__ X, float* __restrict__ part)
{
    int col   = blockIdx.x * 256 + threadIdx.x;
    int chunk = blockIdx.y;
    float s = 0.f;
    int r0 = chunk * 64;
    for (int r = r0; r < r0 + 64; r++) s += X[(size_t)r * HID + col];
    part[(size_t)chunk * HID + col] = s;
}
__global__ void col_final(const float* __restrict__ part, float* __restrict__ ctx)
{
    int col = blockIdx.x * 256 + threadIdx.x;
    float s = 0.f;
    for (int c = 0; c < 64; c++) s += part[(size_t)c * HID + col];
    ctx[col] = s * (1.f / M_TRAIN);
}

/* ------------------ hypernet matvec: out = W @ ctx + bias ---------------- */
__global__ void matvec(const float* __restrict__ W, const float* __restrict__ bias,
                       const float* __restrict__ ctx, float* __restrict__ out, int rows)
{
    int gw   = (blockIdx.x * blockDim.x + threadIdx.x) >> 5;
    int lane = threadIdx.x & 31;
    if (gw >= rows) return;
    const float4* w4 = (const float4*)(W + (size_t)gw * HID);
    const float4* c4 = (const float4*)ctx;
    float s = 0.f;
#pragma unroll
    for (int i = 0; i < 8; i++) {
        float4 a = w4[lane + 32*i];
        float4 c = __ldg(&c4[lane + 32*i]);
        s += a.x*c.x + a.y*c.y + a.z*c.z + a.w*c.w;
    }
#pragma unroll
    for (int o = 16; o; o >>= 1) s += __shfl_xor_sync(0xffffffffu, s, o);
    if (lane == 0) out[gw] = s + bias[gw];
}

/* ---- matvec emitting split bf16 hi/lo directly (for split_w) ------------ */
__global__ void matvec_split(const float* __restrict__ W, const float* __restrict__ bias,
                             const float* __restrict__ ctx,
                             bf16* __restrict__ oh, bf16* __restrict__ ol, int rows)
{
    int gw   = (blockIdx.x * blockDim.x + threadIdx.x) >> 5;
    int lane = threadIdx.x & 31;
    if (gw >= rows) return;
    const float4* w4 = (const float4*)(W + (size_t)gw * HID);
    const float4* c4 = (const float4*)ctx;
    float s = 0.f;
#pragma unroll
    for (int i = 0; i < 8; i++) {
        float4 a = w4[lane + 32*i];
        float4 c = __ldg(&c4[lane + 32*i]);
        s += a.x*c.x + a.y*c.y + a.z*c.z + a.w*c.w;
    }
#pragma unroll
    for (int o = 16; o; o >>= 1) s += __shfl_xor_sync(0xffffffffu, s, o);
    if (lane == 0) {
        float v = s + bias[gw];
        bf16 h = __float2bfloat16(v);
        oh[gw] = h;
        ol[gw] = __float2bfloat16(v - __bfloat162float(h));
    }
}

/* ---- fold tree_w softmax + leaf softmax into one table W[t,l,c] --------- */
__global__ void make_W(const float* __restrict__ tw, const float* __restrict__ lf,
                       float* __restrict__ Wout)
{
    __shared__ float tws[NTREES];
    int tid = threadIdx.x;
    if (tid == 0) {
        float mx = -1e30f;
        for (int i = 0; i < NTREES; i++) mx = fmaxf(mx, tw[i]);
        float e[NTREES], s = 0.f;
        for (int i = 0; i < NTREES; i++) { e[i] = expf(tw[i] - mx); s += e[i]; }
        for (int i = 0; i < NTREES; i++) tws[i] = e[i] / s;
    }
    __syncthreads();
    if (tid < NTREES * NLEAF) {
        const float* L = lf + tid * NCLS;
        float mx = -1e30f;
        for (int c = 0; c < NCLS; c++) mx = fmaxf(mx, L[c]);
        float e[NCLS], s = 0.f;
        for (int c = 0; c < NCLS; c++) { e[c] = expf(L[c] - mx); s += e[c]; }
        float scale = tws[tid >> 5] / s;
        for (int c = 0; c < NCLS; c++) Wout[tid * NCLS + c] = e[c] * scale;
    }
}

/* ------------- soft tree routing + class combine, thread per row --------- */
__global__ void route_kernel(const float* __restrict__ dec, const float* __restrict__ W,
                             float* __restrict__ out)
{
    __shared__ float Ws[LF_ROWS];
    int tid = threadIdx.x;
    for (int i = tid; i < LF_ROWS; i += 256) Ws[i] = W[i];
    __syncthreads();
    int b = blockIdx.x * 256 + tid;
    float acc[NCLS];
#pragma unroll
    for (int c = 0; c < NCLS; c++) acc[c] = 0.f;

    for (int t = 0; t < NTREES; t++) {
        float d[NINT];
#pragma unroll
        for (int n = 0; n < NINT; n++)
            d[n] = dec[(size_t)(t*NINT + n) * M_TEST + b];
#pragma unroll
        for (int l = 0; l < NLEAF; l++) {
            float p = 1.f;
#pragma unroll
            for (int dd = 0; dd < 5; dd++) {
                int node = (1 << dd) - 1 + (l >> (5 - dd));
                int go   = (l >> (4 - dd)) & 1;
                p *= go ? d[node] : (1.f - d[node]);
            }
            const float* w = &Ws[(t*NLEAF + l) * NCLS];
#pragma unroll
            for (int c = 0; c < NCLS; c++) acc[c] += p * w[c];
        }
    }
#pragma unroll
    for (int c = 0; c < NCLS; c++) out[(size_t)b * NCLS + c] = acc[c];
}

/* ------------------------------- launch ---------------------------------- */
extern "C" void kernel_launch(void* const* d_in, const int* in_sizes, int n_in,
                              void* d_out, int out_size)
{
    const float* X_train = (const float*)d_in[0];
    const float* X_test  = (const float*)d_in[1];
    const float* enc_w1  = (const float*)d_in[2];
    const float* enc_b1  = (const float*)d_in[3];
    const float* ln1_g   = (const float*)d_in[4];
    const float* ln1_b   = (const float*)d_in[5];
    const float* enc_w2  = (const float*)d_in[6];
    const float* enc_b2  = (const float*)d_in[7];
    const float* ln2_g   = (const float*)d_in[8];
    const float* ln2_b   = (const float*)d_in[9];
    const float* sw_w    = (const float*)d_in[10];
    const float* sw_b    = (const float*)d_in[11];
    const float* sb_w    = (const float*)d_in[12];
    const float* sb_b    = (const float*)d_in[13];
    const float* lf_w    = (const float*)d_in[14];
    const float* lf_b    = (const float*)d_in[15];
    const float* tw_w    = (const float*)d_in[16];
    const float* tw_b    = (const float*)d_in[17];

    float *C1, *C2, *part, *ctx, *sb, *lf, *tw, *W, *dec;
    bf16 *H1h, *Xtrh, *W1h, *W1l, *W2h, *W2l, *Xteh, *Xtel, *SWh, *SWl;
    cudaGetSymbolAddress((void**)&C1,   g_C1);
    cudaGetSymbolAddress((void**)&C2,   g_C2);
    cudaGetSymbolAddress((void**)&H1h,  g_H1h);
    cudaGetSymbolAddress((void**)&Xtrh, g_Xtrh);
    cudaGetSymbolAddress((void**)&W1h,  g_W1h);
    cudaGetSymbolAddress((void**)&W1l,  g_W1l);
    cudaGetSymbolAddress((void**)&W2h,  g_W2h);
    cudaGetSymbolAddress((void**)&W2l,  g_W2l);
    cudaGetSymbolAddress((void**)&Xteh, g_Xteh);
    cudaGetSymbolAddress((void**)&Xtel, g_Xtel);
    cudaGetSymbolAddress((void**)&SWh,  g_SWh);
    cudaGetSymbolAddress((void**)&SWl,  g_SWl);
    cudaGetSymbolAddress((void**)&part, g_part);
    cudaGetSymbolAddress((void**)&ctx,  g_ctx);
    cudaGetSymbolAddress((void**)&sb,   g_sb);
    cudaGetSymbolAddress((void**)&lf,   g_lf);
    cudaGetSymbolAddress((void**)&tw,   g_tw);
    cudaGetSymbolAddress((void**)&W,    g_W);
    cudaGetSymbolAddress((void**)&dec,  g_dec);

    cudaFuncSetAttribute((const void*)gemm_enc,
                         cudaFuncAttributeMaxDynamicSharedMemorySize, ENSTG*ESTAGE);
    cudaFuncSetAttribute((const void*)gemm_dec,
                         cudaFuncAttributeMaxDynamicSharedMemorySize, NSTG*STAGE);

    /* pre-split inputs: X_train hi-only; weights and X_test hi+lo */
    split_f32<0><<<(M_TRAIN*DIN/4 + 1023)/1024, 256>>>(X_train, Xtrh, nullptr, M_TRAIN*DIN/4);
    split_f32<1><<<(HID*DIN/4     + 1023)/1024, 256>>>(enc_w1,  W1h,  W1l,  HID*DIN/4);
    split_f32<1><<<(HID*HID/4     + 1023)/1024, 256>>>(enc_w2,  W2h,  W2l,  HID*HID/4);
    split_f32<1><<<(M_TEST*DIN/4  + 1023)/1024, 256>>>(X_test,  Xteh, Xtel, M_TEST*DIN/4);

    /* encoder (2-term bf16 GEMMs, 256x128 tiles) */
    gemm_enc<<<dim3(HID/128, M_TRAIN/256), 256, ENSTG*ESTAGE>>>(
        Xtrh, W1h, W1l, enc_b1, C1, M_TRAIN, HID, DIN);
    ln_relu<1><<<M_TRAIN, 256>>>(C1, nullptr, H1h, ln1_g, ln1_b);
    gemm_enc<<<dim3(HID/128, M_TRAIN/256), 256, ENSTG*ESTAGE>>>(
        H1h, W2h, W2l, enc_b2, C2, M_TRAIN, HID, HID);
    ln_relu<0><<<M_TRAIN, 256>>>(C2, C2, nullptr, ln2_g, ln2_b);

    /* ctx = mean over rows */
    col_partial<<<dim3(HID/256, 64), 256>>>(C2, part);
    col_final<<<HID/256, 256>>>(part, ctx);

    /* hypernet matvecs; sw emits split bf16 directly */
    matvec_split<<<(SW_ROWS*32 + 255)/256, 256>>>(sw_w, sw_b, ctx, SWh, SWl, SW_ROWS);
    matvec<<<(NSPLIT*32 + 255)/256, 256>>>(sb_w, sb_b, ctx, sb, NSPLIT);
    matvec<<<(LF_ROWS*32 + 255)/256, 256>>>(lf_w, lf_b, ctx, lf, LF_ROWS);
    matvec<<<(NTREES*32 + 255)/256, 256>>>(tw_w, tw_b, ctx, tw, NTREES);

    /* dec = sigmoid(X_test @ split_w^T + sb), full bf16x3, stored transposed */
    gemm_dec<<<dim3((NSPLIT + 127)/128, M_TEST/128), 256, NSTG*STAGE>>>(
        Xteh, Xtel, SWh, SWl, sb, dec, M_TEST, NSPLIT, DIN);

    /* fold softmaxes, then route */
    make_W<<<1, 512>>>(tw, lf, W);
    route_kernel<<<M_TEST/256, 256>>>(dec, W, (float*)d_out);
}

// round 7
// speedup vs baseline: 1.7792x; 1.0016x over previous
#include <cuda_runtime.h>
#include <cuda_bf16.h>
#include <math.h>
#include <stdint.h>

typedef __nv_bfloat16 bf16;

#define M_TRAIN 4096
#define M_TEST  16384
#define DIN     128
#define HID     1024
#define NTREES  16
#define NINT    31
#define NLEAF   32
#define NCLS    10
#define NSPLIT  (NTREES*NINT)        /* 496 */
#define SW_ROWS (NTREES*NINT*DIN)    /* 63488 */
#define LF_ROWS (NTREES*NLEAF*NCLS)  /* 5120 */

/* ---------------- scratch (static device memory; no allocs) -------------- */
__device__ float g_C1[M_TRAIN*HID];
__device__ float g_C2[M_TRAIN*HID];
__device__ bf16 g_H1h[M_TRAIN*HID];
__device__ bf16 g_Xtrh[M_TRAIN*DIN];
__device__ bf16 g_W1h[HID*DIN],     g_W1l[HID*DIN];
__device__ bf16 g_W2h[HID*HID],     g_W2l[HID*HID];
__device__ bf16 g_Xteh[M_TEST*DIN], g_Xtel[M_TEST*DIN];
__device__ bf16 g_SWh[SW_ROWS],     g_SWl[SW_ROWS];
__device__ float g_part[64*HID];
__device__ float g_ctx[HID];
__device__ float g_sb[NSPLIT];
__device__ float g_lf[LF_ROWS];
__device__ float g_tw[NTREES];
__device__ float g_W[LF_ROWS];
__device__ float g_dec[NSPLIT*M_TEST];       /* TRANSPOSED [496][16384] */

/* ------------------------------ PTX helpers ------------------------------ */
__device__ __forceinline__ uint32_t cvta_sm(const void* p) {
    return (uint32_t)__cvta_generic_to_shared(p);
}
__device__ __forceinline__ void cp16(uint32_t dst, const void* src, int sz) {
    asm volatile("cp.async.cg.shared.global [%0], [%1], 16, %2;\n"
                 :: "r"(dst), "l"(src), "r"(sz));
}
__device__ __forceinline__ void cp_commit() {
    asm volatile("cp.async.commit_group;\n");
}
__device__ __forceinline__ void ldsm4(unsigned& r0, unsigned& r1,
                                      unsigned& r2, unsigned& r3, uint32_t a) {
    asm volatile("ldmatrix.sync.aligned.m8n8.x4.shared.b16 {%0,%1,%2,%3}, [%4];"
                 : "=r"(r0), "=r"(r1), "=r"(r2), "=r"(r3) : "r"(a));
}
__device__ __forceinline__ void mma_bf16(float c[4], unsigned a0, unsigned a1,
                                         unsigned a2, unsigned a3,
                                         unsigned b0, unsigned b1)
{
    asm volatile(
        "mma.sync.aligned.m16n8k16.row.col.f32.bf16.bf16.f32 "
        "{%0,%1,%2,%3}, {%4,%5,%6,%7}, {%8,%9}, {%0,%1,%2,%3};"
        : "+f"(c[0]), "+f"(c[1]), "+f"(c[2]), "+f"(c[3])
        : "r"(a0), "r"(a1), "r"(a2), "r"(a3), "r"(b0), "r"(b1));
}
/* swizzled byte offset inside a (rows x 32) bf16 tile, 64B rows */
__device__ __forceinline__ uint32_t swz(int r, int hb) {
    return (uint32_t)(r*64 + ((hb ^ ((r>>1)&3)) << 4));
}

/* --------------- split fp32 -> bf16 hi (and optionally lo) --------------- */
template<int WLO>
__global__ void split_f32(const float* __restrict__ x, bf16* __restrict__ hi,
                          bf16* __restrict__ lo, int n4)
{
    int i0 = blockIdx.x * (blockDim.x * 4) + threadIdx.x;
    float4 v[4];
    bool ok[4];
#pragma unroll
    for (int u = 0; u < 4; u++) {
        int i = i0 + u*256;
        ok[u] = (i < n4);
        if (ok[u]) v[u] = ((const float4*)x)[i];
    }
#pragma unroll
    for (int u = 0; u < 4; u++) {
        if (!ok[u]) continue;
        int i = i0 + u*256;
        bf16 h0=__float2bfloat16(v[u].x), h1=__float2bfloat16(v[u].y);
        bf16 h2=__float2bfloat16(v[u].z), h3=__float2bfloat16(v[u].w);
        ((__nv_bfloat162*)hi)[i*2]   = __halves2bfloat162(h0, h1);
        ((__nv_bfloat162*)hi)[i*2+1] = __halves2bfloat162(h2, h3);
        if (WLO) {
            bf16 l0=__float2bfloat16(v[u].x-__bfloat162float(h0));
            bf16 l1=__float2bfloat16(v[u].y-__bfloat162float(h1));
            bf16 l2=__float2bfloat16(v[u].z-__bfloat162float(h2));
            bf16 l3=__float2bfloat16(v[u].w-__bfloat162float(h3));
            ((__nv_bfloat162*)lo)[i*2]   = __halves2bfloat162(l0, l1);
            ((__nv_bfloat162*)lo)[i*2+1] = __halves2bfloat162(l2, l3);
        }
    }
}

/* ------- encoder GEMM: C = A @ B^T + bias, A bf16-hi, B split (2 MMA) ---- */
/* CTA tile 256(M) x 128(N), warp tile 64x64, BK=32, 3-stage cp.async.      */
/* Stage 32KB: Ah@0 (16K), Bh@16K (8K), Bl@24K (8K).                        */
#define ESTAGE 32768
#define ENSTG  3

__global__ void __launch_bounds__(256, 1) gemm_enc(
    const bf16* __restrict__ Ah,
    const bf16* __restrict__ Bh, const bf16* __restrict__ Bl,
    const float* __restrict__ bias, float* __restrict__ C,
    int M, int N, int K)
{
    extern __shared__ char dynsm[];
    const uint32_t smem = cvta_sm(dynsm);
    const int tid = threadIdx.x, lane = tid & 31, warp = tid >> 5;
    const int g = lane >> 2, t = lane & 3;
    const int wm = warp & 3, wn = warp >> 2;      /* 4(m) x 2(n) warps */
    const int m0 = blockIdx.y * 256, n0 = blockIdx.x * 128;

    float c[4][8][4];
#pragma unroll
    for (int i = 0; i < 4; i++)
#pragma unroll
        for (int j = 0; j < 8; j++)
#pragma unroll
            for (int r = 0; r < 4; r++) c[i][j][r] = 0.f;

    const int kIters = K >> 5;

    auto load_stage = [&](int buf, int k0) {
        uint32_t sb = smem + buf * ESTAGE;
        /* A: 256 rows x 64B = 1024 cp16 -> 4/thread */
#pragma unroll
        for (int x = 0; x < 4; x++) {
            int ch = tid + x*256;
            int r = ch >> 2, hb = ch & 3;
            cp16(sb + swz(r, hb), Ah + (size_t)(m0 + r) * K + k0 + hb*8, 16);
        }
        /* B: 128 rows x 64B, hi+lo: 512 each -> 2+2/thread */
#pragma unroll
        for (int x = 0; x < 2; x++) {
            int ch = tid + x*256;
            int r = ch >> 2, hb = ch & 3;
            uint32_t so = swz(r, hb);
            size_t gb = (size_t)(n0 + r) * K + k0 + hb*8;
            cp16(sb + 16384 + so, Bh + gb, 16);
            cp16(sb + 24576 + so, Bl + gb, 16);
        }
    };

    auto compute = [&](int buf) {
        uint32_t sb = smem + buf * ESTAGE;
        const int rl = lane & 15;
        const int hx = lane >> 4;
#pragma unroll
        for (int s = 0; s < 2; s++) {
            const int hb = s*2 + hx;
            /* B fragments: warp's 64 columns, hi+lo */
            unsigned bh[8][2], bl[8][2];
#pragma unroll
            for (int j2 = 0; j2 < 4; j2++) {
                int row = wn*64 + j2*16 + rl;
                uint32_t off = swz(row, hb);
                unsigned r0, r1, r2, r3;
                ldsm4(r0, r1, r2, r3, sb + 16384 + off);
                bh[j2*2][0]=r0; bh[j2*2][1]=r2; bh[j2*2+1][0]=r1; bh[j2*2+1][1]=r3;
                ldsm4(r0, r1, r2, r3, sb + 24576 + off);
                bl[j2*2][0]=r0; bl[j2*2][1]=r2; bl[j2*2+1][0]=r1; bl[j2*2+1][1]=r3;
            }
#pragma unroll
            for (int i = 0; i < 4; i++) {
                int row = wm*64 + i*16 + rl;
                unsigned a0,a1,a2,a3;
                ldsm4(a0,a1,a2,a3, sb + swz(row, hb));
#pragma unroll
                for (int j = 0; j < 8; j++) {
                    mma_bf16(c[i][j], a0,a1,a2,a3, bh[j][0], bh[j][1]);
                    mma_bf16(c[i][j], a0,a1,a2,a3, bl[j][0], bl[j][1]);
                }
            }
        }
    };

    load_stage(0, 0);
    cp_commit();
    load_stage(1, 32);
    cp_commit();
    for (int it = 0; it < kIters; it++) {
        if (it + 1 < kIters)
            asm volatile("cp.async.wait_group 1;\n" ::: "memory");
        else
            asm volatile("cp.async.wait_group 0;\n" ::: "memory");
        __syncthreads();
        compute(it % ENSTG);
        __syncthreads();
        if (it + 2 < kIters) {
            load_stage((it+2) % ENSTG, (it+2)*32);
            cp_commit();
        }
    }

#pragma unroll
    for (int i = 0; i < 4; i++) {
        int r0 = m0 + wm*64 + i*16 + g;
#pragma unroll
        for (int j = 0; j < 8; j++) {
            int col = n0 + wn*64 + j*8 + 2*t;
            float b0 = bias[col], b1 = bias[col+1];
            float2 v0 = make_float2(c[i][j][0] + b0, c[i][j][1] + b1);
            float2 v1 = make_float2(c[i][j][2] + b0, c[i][j][3] + b1);
            *(float2*)&C[(size_t)r0     * N + col] = v0;
            *(float2*)&C[(size_t)(r0+8) * N + col] = v1;
        }
    }
}

/* --------- dec GEMM (full bf16x3): sigmoid + transposed store ------------ */
#define STAGE 32768
#define NSTG  3

__global__ void __launch_bounds__(256, 2) gemm_dec(
    const bf16* __restrict__ Ah, const bf16* __restrict__ Al,
    const bf16* __restrict__ Bh, const bf16* __restrict__ Bl,
    const float* __restrict__ bias, float* __restrict__ C,
    int M, int N, int K)
{
    extern __shared__ char dynsm[];
    const uint32_t smem = cvta_sm(dynsm);
    const int tid = threadIdx.x, lane = tid & 31, warp = tid >> 5;
    const int g = lane >> 2, t = lane & 3;
    const int wm = warp & 1, wn = warp >> 1;
    const int m0 = blockIdx.y * 128, n0 = blockIdx.x * 128;

    float c[4][4][4];
#pragma unroll
    for (int i = 0; i < 4; i++)
#pragma unroll
        for (int j = 0; j < 4; j++)
#pragma unroll
            for (int r = 0; r < 4; r++) c[i][j][r] = 0.f;

    const int kIters = K >> 5;

    auto load_stage = [&](int buf, int k0) {
        uint32_t sb = smem + buf * STAGE;
#pragma unroll
        for (int cc = 0; cc < 2; cc++) {
            int ch = tid + cc*256;
            int r = ch >> 2, hb = ch & 3;
            uint32_t so = swz(r, hb);
            size_t ga = (size_t)(m0 + r) * K + k0 + hb*8;
            cp16(sb + so,         Ah + ga, 16);
            cp16(sb + 8192 + so,  Al + ga, 16);
            int bn = n0 + r;
            int sz = (bn < N) ? 16 : 0;
            size_t gb = (size_t)(sz ? bn : 0) * K + k0 + hb*8;
            cp16(sb + 16384 + so, Bh + gb, sz);
            cp16(sb + 24576 + so, Bl + gb, sz);
        }
    };

    auto compute = [&](int buf) {
        uint32_t sb = smem + buf * STAGE;
        const int rl = lane & 15;
        const int hx = lane >> 4;
#pragma unroll
        for (int s = 0; s < 2; s++) {
            const int hb = s*2 + hx;
            unsigned bh[4][2], bl[4][2];
#pragma unroll
            for (int j2 = 0; j2 < 2; j2++) {
                int row = wn*32 + j2*16 + rl;
                uint32_t off = swz(row, hb);
                unsigned r0, r1, r2, r3;
                ldsm4(r0, r1, r2, r3, sb + 16384 + off);
                bh[j2*2][0]=r0; bh[j2*2][1]=r2; bh[j2*2+1][0]=r1; bh[j2*2+1][1]=r3;
                ldsm4(r0, r1, r2, r3, sb + 24576 + off);
                bl[j2*2][0]=r0; bl[j2*2][1]=r2; bl[j2*2+1][0]=r1; bl[j2*2+1][1]=r3;
            }
#pragma unroll
            for (int i = 0; i < 4; i++) {
                int row = wm*64 + i*16 + rl;
                uint32_t off = swz(row, hb);
                unsigned a0,a1,a2,a3, q0,q1,q2,q3;
                ldsm4(a0,a1,a2,a3, sb + off);
                ldsm4(q0,q1,q2,q3, sb + 8192 + off);
#pragma unroll
                for (int j = 0; j < 4; j++) {
                    mma_bf16(c[i][j], a0,a1,a2,a3, bh[j][0], bh[j][1]);
                    mma_bf16(c[i][j], a0,a1,a2,a3, bl[j][0], bl[j][1]);
                    mma_bf16(c[i][j], q0,q1,q2,q3, bh[j][0], bh[j][1]);
                }
            }
        }
    };

    load_stage(0, 0);
    cp_commit();
    load_stage(1, 32);
    cp_commit();
    for (int it = 0; it < kIters; it++) {
        if (it + 1 < kIters)
            asm volatile("cp.async.wait_group 1;\n" ::: "memory");
        else
            asm volatile("cp.async.wait_group 0;\n" ::: "memory");
        __syncthreads();
        compute(it % NSTG);
        __syncthreads();
        if (it + 2 < kIters) {
            load_stage((it+2) % NSTG, (it+2)*32);
            cp_commit();
        }
    }

    /* sigmoid + transposed store via smem staging */
    float (*trans)[132] = reinterpret_cast<float(*)[132]>(dynsm);
#pragma unroll
    for (int chunk = 0; chunk < 4; chunk++) {
        __syncthreads();
        if (wn == chunk) {
#pragma unroll
            for (int i = 0; i < 4; i++) {
                int mm = wm*64 + i*16 + g;
#pragma unroll
                for (int j = 0; j < 4; j++) {
                    int nn  = j*8 + 2*t;
                    int col = n0 + chunk*32 + nn;
                    float b0 = (col     < N) ? bias[col]   : 0.f;
                    float b1 = (col + 1 < N) ? bias[col+1] : 0.f;
                    float v0 = c[i][j][0] + b0, v1 = c[i][j][1] + b1;
                    float v2 = c[i][j][2] + b0, v3 = c[i][j][3] + b1;
                    trans[nn  ][mm  ] = 1.f / (1.f + __expf(-v0));
                    trans[nn+1][mm  ] = 1.f / (1.f + __expf(-v1));
                    trans[nn  ][mm+8] = 1.f / (1.f + __expf(-v2));
                    trans[nn+1][mm+8] = 1.f / (1.f + __expf(-v3));
                }
            }
        }
        __syncthreads();
#pragma unroll
        for (int p = 0; p < 4; p++) {
            int idx  = tid + p*256;
            int rowb = idx >> 5;
            int mc   = (idx & 31) * 4;
            int ngl  = n0 + chunk*32 + rowb;
            if (ngl < N)
                *(float4*)&C[(size_t)ngl * M_TEST + m0 + mc] =
                    *(float4*)&trans[rowb][mc];
        }
    }
}

/* ------------- LayerNorm + ReLU; SPLIT=1 emits bf16 hi only -------------- */
template<int SPLIT>
__global__ void ln_relu(const float* __restrict__ X, float* __restrict__ Y,
                        bf16* __restrict__ Yh,
                        const float* __restrict__ gg, const float* __restrict__ bb)
{
    const int row = blockIdx.x, tid = threadIdx.x;
    const float4 v = ((const float4*)(X + (size_t)row * HID))[tid];
    float s = v.x + v.y + v.z + v.w;
    float q = v.x*v.x + v.y*v.y + v.z*v.z + v.w*v.w;
#pragma unroll
    for (int o = 16; o; o >>= 1) {
        s += __shfl_xor_sync(0xffffffffu, s, o);
        q += __shfl_xor_sync(0xffffffffu, q, o);
    }
    __shared__ float ss[8], qs[8];
    if ((tid & 31) == 0) { ss[tid >> 5] = s; qs[tid >> 5] = q; }
    __syncthreads();
    s = ss[0]+ss[1]+ss[2]+ss[3]+ss[4]+ss[5]+ss[6]+ss[7];
    q = qs[0]+qs[1]+qs[2]+qs[3]+qs[4]+qs[5]+qs[6]+qs[7];
    float mean = s * (1.f/HID);
    float inv  = rsqrtf(q * (1.f/HID) - mean*mean + 1e-5f);
    float4 gv = ((const float4*)gg)[tid];
    float4 bv = ((const float4*)bb)[tid];
    float4 y;
    y.x = fmaxf((v.x - mean)*inv*gv.x + bv.x, 0.f);
    y.y = fmaxf((v.y - mean)*inv*gv.y + bv.y, 0.f);
    y.z = fmaxf((v.z - mean)*inv*gv.z + bv.z, 0.f);
    y.w = fmaxf((v.w - mean)*inv*gv.w + bv.w, 0.f);
    if (SPLIT) {
        __nv_bfloat162* ph = (__nv_bfloat162*)(Yh + (size_t)row * HID);
        ph[tid*2]   = __halves2bfloat162(__float2bfloat16(y.x), __float2bfloat16(y.y));
        ph[tid*2+1] = __halves2bfloat162(__float2bfloat16(y.z), __float2bfloat16(y.w));
    } else {
        ((float4*)(Y + (size_t)row * HID))[tid] = y;
    }
}

/* --------------------- column mean over rows -> ctx ---------------------- */
__global__ void col_partial(const float* __restrict__ X, float* __restrict__ part)
{
    int col   = blockIdx.x * 256 + threadIdx.x;
    int chunk = blockIdx.y;
    float s = 0.f;
    int r0 = chunk * 64;
    for (int r = r0; r < r0 + 64; r++) s += X[(size_t)r * HID + col];
    part[(size_t)chunk * HID + col] = s;
}
__global__ void col_final(const float* __restrict__ part, float* __restrict__ ctx)
{
    int col = blockIdx.x * 256 + threadIdx.x;
    float s = 0.f;
    for (int c = 0; c < 64; c++) s += part[(size_t)c * HID + col];
    ctx[col] = s * (1.f / M_TRAIN);
}

/* ------------------ hypernet matvec: out = W @ ctx + bias ---------------- */
__global__ void matvec(const float* __restrict__ W, const float* __restrict__ bias,
                       const float* __restrict__ ctx, float* __restrict__ out, int rows)
{
    int gw   = (blockIdx.x * blockDim.x + threadIdx.x) >> 5;
    int lane = threadIdx.x & 31;
    if (gw >= rows) return;
    const float4* w4 = (const float4*)(W + (size_t)gw * HID);
    const float4* c4 = (const float4*)ctx;
    float s = 0.f;
#pragma unroll
    for (int i = 0; i < 8; i++) {
        float4 a = w4[lane + 32*i];
        float4 c = __ldg(&c4[lane + 32*i]);
        s += a.x*c.x + a.y*c.y + a.z*c.z + a.w*c.w;
    }
#pragma unroll
    for (int o = 16; o; o >>= 1) s += __shfl_xor_sync(0xffffffffu, s, o);
    if (lane == 0) out[gw] = s + bias[gw];
}

/* ---- matvec emitting split bf16 hi/lo directly (for split_w) ------------ */
__global__ void matvec_split(const float* __restrict__ W, const float* __restrict__ bias,
                             const float* __restrict__ ctx,
                             bf16* __restrict__ oh, bf16* __restrict__ ol, int rows)
{
    int gw   = (blockIdx.x * blockDim.x + threadIdx.x) >> 5;
    int lane = threadIdx.x & 31;
    if (gw >= rows) return;
    const float4* w4 = (const float4*)(W + (size_t)gw * HID);
    const float4* c4 = (const float4*)ctx;
    float s = 0.f;
#pragma unroll
    for (int i = 0; i < 8; i++) {
        float4 a = w4[lane + 32*i];
        float4 c = __ldg(&c4[lane + 32*i]);
        s += a.x*c.x + a.y*c.y + a.z*c.z + a.w*c.w;
    }
#pragma unroll
    for (int o = 16; o; o >>= 1) s += __shfl_xor_sync(0xffffffffu, s, o);
    if (lane == 0) {
        float v = s + bias[gw];
        bf16 h = __float2bfloat16(v);
        oh[gw] = h;
        ol[gw] = __float2bfloat16(v - __bfloat162float(h));
    }
}

/* ---- fold tree_w softmax + leaf softmax into one table W[t,l,c] --------- */
__global__ void make_W(const float* __restrict__ tw, const float* __restrict__ lf,
                       float* __restrict__ Wout)
{
    __shared__ float tws[NTREES];
    int tid = threadIdx.x;
    if (tid == 0) {
        float mx = -1e30f;
        for (int i = 0; i < NTREES; i++) mx = fmaxf(mx, tw[i]);
        float e[NTREES], s = 0.f;
        for (int i = 0; i < NTREES; i++) { e[i] = expf(tw[i] - mx); s += e[i]; }
        for (int i = 0; i < NTREES; i++) tws[i] = e[i] / s;
    }
    __syncthreads();
    if (tid < NTREES * NLEAF) {
        const float* L = lf + tid * NCLS;
        float mx = -1e30f;
        for (int c = 0; c < NCLS; c++) mx = fmaxf(mx, L[c]);
        float e[NCLS], s = 0.f;
        for (int c = 0; c < NCLS; c++) { e[c] = expf(L[c] - mx); s += e[c]; }
        float scale = tws[tid >> 5] / s;
        for (int c = 0; c < NCLS; c++) Wout[tid * NCLS + c] = e[c] * scale;
    }
}

/* ------------- soft tree routing + class combine, thread per row --------- */
__global__ void route_kernel(const float* __restrict__ dec, const float* __restrict__ W,
                             float* __restrict__ out)
{
    __shared__ float Ws[LF_ROWS];
    int tid = threadIdx.x;
    for (int i = tid; i < LF_ROWS; i += 256) Ws[i] = W[i];
    __syncthreads();
    int b = blockIdx.x * 256 + tid;
    float acc[NCLS];
#pragma unroll
    for (int c = 0; c < NCLS; c++) acc[c] = 0.f;

    for (int t = 0; t < NTREES; t++) {
        float d[NINT];
#pragma unroll
        for (int n = 0; n < NINT; n++)
            d[n] = dec[(size_t)(t*NINT + n) * M_TEST + b];
#pragma unroll
        for (int l = 0; l < NLEAF; l++) {
            float p = 1.f;
#pragma unroll
            for (int dd = 0; dd < 5; dd++) {
                int node = (1 << dd) - 1 + (l >> (5 - dd));
                int go   = (l >> (4 - dd)) & 1;
                p *= go ? d[node] : (1.f - d[node]);
            }
            const float* w = &Ws[(t*NLEAF + l) * NCLS];
#pragma unroll
            for (int c = 0; c < NCLS; c++) acc[c] += p * w[c];
        }
    }
#pragma unroll
    for (int c = 0; c < NCLS; c++) out[(size_t)b * NCLS + c] = acc[c];
}

/* ------------------------------- launch ---------------------------------- */
extern "C" void kernel_launch(void* const* d_in, const int* in_sizes, int n_in,
                              void* d_out, int out_size)
{
    const float* X_train = (const float*)d_in[0];
    const float* X_test  = (const float*)d_in[1];
    const float* enc_w1  = (const float*)d_in[2];
    const float* enc_b1  = (const float*)d_in[3];
    const float* ln1_g   = (const float*)d_in[4];
    const float* ln1_b   = (const float*)d_in[5];
    const float* enc_w2  = (const float*)d_in[6];
    const float* enc_b2  = (const float*)d_in[7];
    const float* ln2_g   = (const float*)d_in[8];
    const float* ln2_b   = (const float*)d_in[9];
    const float* sw_w    = (const float*)d_in[10];
    const float* sw_b    = (const float*)d_in[11];
    const float* sb_w    = (const float*)d_in[12];
    const float* sb_b    = (const float*)d_in[13];
    const float* lf_w    = (const float*)d_in[14];
    const float* lf_b    = (const float*)d_in[15];
    const float* tw_w    = (const float*)d_in[16];
    const float* tw_b    = (const float*)d_in[17];

    float *C1, *C2, *part, *ctx, *sb, *lf, *tw, *W, *dec;
    bf16 *H1h, *Xtrh, *W1h, *W1l, *W2h, *W2l, *Xteh, *Xtel, *SWh, *SWl;
    cudaGetSymbolAddress((void**)&C1,   g_C1);
    cudaGetSymbolAddress((void**)&C2,   g_C2);
    cudaGetSymbolAddress((void**)&H1h,  g_H1h);
    cudaGetSymbolAddress((void**)&Xtrh, g_Xtrh);
    cudaGetSymbolAddress((void**)&W1h,  g_W1h);
    cudaGetSymbolAddress((void**)&W1l,  g_W1l);
    cudaGetSymbolAddress((void**)&W2h,  g_W2h);
    cudaGetSymbolAddress((void**)&W2l,  g_W2l);
    cudaGetSymbolAddress((void**)&Xteh, g_Xteh);
    cudaGetSymbolAddress((void**)&Xtel, g_Xtel);
    cudaGetSymbolAddress((void**)&SWh,  g_SWh);
    cudaGetSymbolAddress((void**)&SWl,  g_SWl);
    cudaGetSymbolAddress((void**)&part, g_part);
    cudaGetSymbolAddress((void**)&ctx,  g_ctx);
    cudaGetSymbolAddress((void**)&sb,   g_sb);
    cudaGetSymbolAddress((void**)&lf,   g_lf);
    cudaGetSymbolAddress((void**)&tw,   g_tw);
    cudaGetSymbolAddress((void**)&W,    g_W);
    cudaGetSymbolAddress((void**)&dec,  g_dec);

    cudaFuncSetAttribute((const void*)gemm_enc,
                         cudaFuncAttributeMaxDynamicSharedMemorySize, ENSTG*ESTAGE);
    cudaFuncSetAttribute((const void*)gemm_dec,
                         cudaFuncAttributeMaxDynamicSharedMemorySize, NSTG*STAGE);

    /* pre-split inputs: X_train hi-only; weights and X_test hi+lo */
    split_f32<0><<<(M_TRAIN*DIN/4 + 1023)/1024, 256>>>(X_train, Xtrh, nullptr, M_TRAIN*DIN/4);
    split_f32<1><<<(HID*DIN/4     + 1023)/1024, 256>>>(enc_w1,  W1h,  W1l,  HID*DIN/4);
    split_f32<1><<<(HID*HID/4     + 1023)/1024, 256>>>(enc_w2,  W2h,  W2l,  HID*HID/4);
    split_f32<1><<<(M_TEST*DIN/4  + 1023)/1024, 256>>>(X_test,  Xteh, Xtel, M_TEST*DIN/4);

    /* encoder (2-term bf16 GEMMs, 256x128 tiles) */
    gemm_enc<<<dim3(HID/128, M_TRAIN/256), 256, ENSTG*ESTAGE>>>(
        Xtrh, W1h, W1l, enc_b1, C1, M_TRAIN, HID, DIN);
    ln_relu<1><<<M_TRAIN, 256>>>(C1, nullptr, H1h, ln1_g, ln1_b);
    gemm_enc<<<dim3(HID/128, M_TRAIN/256), 256, ENSTG*ESTAGE>>>(
        H1h, W2h, W2l, enc_b2, C2, M_TRAIN, HID, HID);
    ln_relu<0><<<M_TRAIN, 256>>>(C2, C2, nullptr, ln2_g, ln2_b);

    /* ctx = mean over rows */
    col_partial<<<dim3(HID/256, 64), 256>>>(C2, part);
    col_final<<<HID/256, 256>>>(part, ctx);

    /* hypernet matvecs; sw emits split bf16 directly */
    matvec_split<<<(SW_ROWS*32 + 255)/256, 256>>>(sw_w, sw_b, ctx, SWh, SWl, SW_ROWS);
    matvec<<<(NSPLIT*32 + 255)/256, 256>>>(sb_w, sb_b, ctx, sb, NSPLIT);
    matvec<<<(LF_ROWS*32 + 255)/256, 256>>>(lf_w, lf_b, ctx, lf, LF_ROWS);
    matvec<<<(NTREES*32 + 255)/256, 256>>>(tw_w, tw_b, ctx, tw, NTREES);

    /* dec = sigmoid(X_test @ split_w^T + sb), full bf16x3, stored transposed */
    gemm_dec<<<dim3((NSPLIT + 127)/128, M_TEST/128), 256, NSTG*STAGE>>>(
        Xteh, Xtel, SWh, SWl, sb, dec, M_TEST, NSPLIT, DIN);

    /* fold softmaxes, then route */
    make_W<<<1, 512>>>(tw, lf, W);
    route_kernel<<<M_TEST/256, 256>>>(dec, W, (float*)d_out);
}

// round 8
// speedup vs baseline: 1.8473x; 1.0383x over previous
#include <cuda_runtime.h>
#include <cuda_bf16.h>
#include <math.h>
#include <stdint.h>

typedef __nv_bfloat16 bf16;

#define M_TRAIN 4096
#define M_TEST  16384
#define DIN     128
#define HID     1024
#define NTREES  16
#define NINT    31
#define NLEAF   32
#define NCLS    10
#define NSPLIT  (NTREES*NINT)        /* 496 */
#define SW_ROWS (NTREES*NINT*DIN)    /* 63488 */
#define LF_ROWS (NTREES*NLEAF*NCLS)  /* 5120 */

/* ---------------- scratch (static device memory; no allocs) -------------- */
__device__ float g_C1[M_TRAIN*HID];
__device__ float g_C2[M_TRAIN*HID];
__device__ bf16 g_H1h[M_TRAIN*HID];
__device__ bf16 g_Xtrh[M_TRAIN*DIN];
__device__ bf16 g_W1h[HID*DIN],     g_W1l[HID*DIN];
__device__ bf16 g_W2h[HID*HID],     g_W2l[HID*HID];
__device__ bf16 g_Xteh[M_TEST*DIN];
__device__ bf16 g_SWh[SW_ROWS],     g_SWl[SW_ROWS];
__device__ float g_part[64*HID];
__device__ float g_ctx[HID];
__device__ float g_sb[NSPLIT];
__device__ float g_lf[LF_ROWS];
__device__ float g_tw[NTREES];
__device__ float g_W[LF_ROWS];
__device__ float g_dec[NSPLIT*M_TEST];       /* TRANSPOSED [496][16384] */

/* ------------------------------ PTX helpers ------------------------------ */
__device__ __forceinline__ uint32_t cvta_sm(const void* p) {
    return (uint32_t)__cvta_generic_to_shared(p);
}
__device__ __forceinline__ void cp16(uint32_t dst, const void* src, int sz) {
    asm volatile("cp.async.cg.shared.global [%0], [%1], 16, %2;\n"
                 :: "r"(dst), "l"(src), "r"(sz));
}
__device__ __forceinline__ void cp_commit() {
    asm volatile("cp.async.commit_group;\n");
}
__device__ __forceinline__ void ldsm4(unsigned& r0, unsigned& r1,
                                      unsigned& r2, unsigned& r3, uint32_t a) {
    asm volatile("ldmatrix.sync.aligned.m8n8.x4.shared.b16 {%0,%1,%2,%3}, [%4];"
                 : "=r"(r0), "=r"(r1), "=r"(r2), "=r"(r3) : "r"(a));
}
__device__ __forceinline__ void mma_bf16(float c[4], unsigned a0, unsigned a1,
                                         unsigned a2, unsigned a3,
                                         unsigned b0, unsigned b1)
{
    asm volatile(
        "mma.sync.aligned.m16n8k16.row.col.f32.bf16.bf16.f32 "
        "{%0,%1,%2,%3}, {%4,%5,%6,%7}, {%8,%9}, {%0,%1,%2,%3};"
        : "+f"(c[0]), "+f"(c[1]), "+f"(c[2]), "+f"(c[3])
        : "r"(a0), "r"(a1), "r"(a2), "r"(a3), "r"(b0), "r"(b1));
}
/* swizzled byte offset inside a (rows x 32) bf16 tile, 64B rows */
__device__ __forceinline__ uint32_t swz(int r, int hb) {
    return (uint32_t)(r*64 + ((hb ^ ((r>>1)&3)) << 4));
}

/* ------------- ONE launch: split all static inputs to bf16 --------------- */
/* region sizes are multiples of 1024 float4s -> no bounds checks            */
__global__ void split_all(const float* __restrict__ xtr, const float* __restrict__ w1,
                          const float* __restrict__ w2,  const float* __restrict__ xte,
                          bf16* __restrict__ xtrh,
                          bf16* __restrict__ w1h, bf16* __restrict__ w1l,
                          bf16* __restrict__ w2h, bf16* __restrict__ w2l,
                          bf16* __restrict__ xteh)
{
    int b = blockIdx.x;
    const float* src;
    bf16 *hi, *lo = nullptr;
    int base;
    if (b < 128)      { src = xtr; hi = xtrh;            base = b; }
    else if (b < 160) { src = w1;  hi = w1h;  lo = w1l;  base = b - 128; }
    else if (b < 416) { src = w2;  hi = w2h;  lo = w2l;  base = b - 160; }
    else              { src = xte; hi = xteh;            base = b - 416; }

    int i0 = base * 1024 + threadIdx.x;
    float4 v[4];
#pragma unroll
    for (int u = 0; u < 4; u++) v[u] = ((const float4*)src)[i0 + u*256];
#pragma unroll
    for (int u = 0; u < 4; u++) {
        int i = i0 + u*256;
        bf16 h0=__float2bfloat16(v[u].x), h1=__float2bfloat16(v[u].y);
        bf16 h2=__float2bfloat16(v[u].z), h3=__float2bfloat16(v[u].w);
        ((__nv_bfloat162*)hi)[i*2]   = __halves2bfloat162(h0, h1);
        ((__nv_bfloat162*)hi)[i*2+1] = __halves2bfloat162(h2, h3);
        if (lo) {
            bf16 l0=__float2bfloat16(v[u].x-__bfloat162float(h0));
            bf16 l1=__float2bfloat16(v[u].y-__bfloat162float(h1));
            bf16 l2=__float2bfloat16(v[u].z-__bfloat162float(h2));
            bf16 l3=__float2bfloat16(v[u].w-__bfloat162float(h3));
            ((__nv_bfloat162*)lo)[i*2]   = __halves2bfloat162(l0, l1);
            ((__nv_bfloat162*)lo)[i*2+1] = __halves2bfloat162(l2, l3);
        }
    }
}

/* ---- 128x128 2-term GEMM (A bf16-hi, B split): C = A @ B^T + bias ------- */
/* BK=32, 3-stage. Stage 24KB: A@0 (8K), Bh@8K, Bl@16K.                      */
/* EPI 0: plain row-major store (N multiple of 128).                         */
/* EPI 1: sigmoid + transposed store with N guard (dec).                     */
#define GSTAGE 24576
#define GNSTG  3

template<int EPI>
__global__ void __launch_bounds__(256, 2) gemm128(
    const bf16* __restrict__ Ah,
    const bf16* __restrict__ Bh, const bf16* __restrict__ Bl,
    const float* __restrict__ bias, float* __restrict__ C,
    int M, int N, int K)
{
    extern __shared__ char dynsm[];
    const uint32_t smem = cvta_sm(dynsm);
    const int tid = threadIdx.x, lane = tid & 31, warp = tid >> 5;
    const int g = lane >> 2, t = lane & 3;
    const int wm = warp & 1, wn = warp >> 1;
    const int m0 = blockIdx.y * 128, n0 = blockIdx.x * 128;

    float c[4][4][4];
#pragma unroll
    for (int i = 0; i < 4; i++)
#pragma unroll
        for (int j = 0; j < 4; j++)
#pragma unroll
            for (int r = 0; r < 4; r++) c[i][j][r] = 0.f;

    const int kIters = K >> 5;

    auto load_stage = [&](int buf, int k0) {
        uint32_t sb = smem + buf * GSTAGE;
#pragma unroll
        for (int x = 0; x < 2; x++) {
            int ch = tid + x*256;
            int r = ch >> 2, hb = ch & 3;
            uint32_t so = swz(r, hb);
            cp16(sb + so, Ah + (size_t)(m0 + r) * K + k0 + hb*8, 16);
            int bn = n0 + r;
            int sz = (bn < N) ? 16 : 0;
            size_t gb = (size_t)(sz ? bn : 0) * K + k0 + hb*8;
            cp16(sb + 8192  + so, Bh + gb, sz);
            cp16(sb + 16384 + so, Bl + gb, sz);
        }
    };

    auto compute = [&](int buf) {
        uint32_t sb = smem + buf * GSTAGE;
        const int rl = lane & 15;
        const int hx = lane >> 4;
#pragma unroll
        for (int s = 0; s < 2; s++) {
            const int hb = s*2 + hx;
            unsigned bh[4][2], bl[4][2];
#pragma unroll
            for (int j2 = 0; j2 < 2; j2++) {
                int row = wn*32 + j2*16 + rl;
                uint32_t off = swz(row, hb);
                unsigned r0, r1, r2, r3;
                ldsm4(r0, r1, r2, r3, sb + 8192 + off);
                bh[j2*2][0]=r0; bh[j2*2][1]=r2; bh[j2*2+1][0]=r1; bh[j2*2+1][1]=r3;
                ldsm4(r0, r1, r2, r3, sb + 16384 + off);
                bl[j2*2][0]=r0; bl[j2*2][1]=r2; bl[j2*2+1][0]=r1; bl[j2*2+1][1]=r3;
            }
#pragma unroll
            for (int i = 0; i < 4; i++) {
                int row = wm*64 + i*16 + rl;
                unsigned a0,a1,a2,a3;
                ldsm4(a0,a1,a2,a3, sb + swz(row, hb));
#pragma unroll
                for (int j = 0; j < 4; j++) {
                    mma_bf16(c[i][j], a0,a1,a2,a3, bh[j][0], bh[j][1]);
                    mma_bf16(c[i][j], a0,a1,a2,a3, bl[j][0], bl[j][1]);
                }
            }
        }
    };

    load_stage(0, 0);
    cp_commit();
    load_stage(1, 32);
    cp_commit();
    for (int it = 0; it < kIters; it++) {
        if (it + 1 < kIters)
            asm volatile("cp.async.wait_group 1;\n" ::: "memory");
        else
            asm volatile("cp.async.wait_group 0;\n" ::: "memory");
        __syncthreads();
        compute(it % GNSTG);
        __syncthreads();
        if (it + 2 < kIters) {
            load_stage((it+2) % GNSTG, (it+2)*32);
            cp_commit();
        }
    }

    if (EPI == 0) {
#pragma unroll
        for (int i = 0; i < 4; i++) {
            int r0 = m0 + wm*64 + i*16 + g;
#pragma unroll
            for (int j = 0; j < 4; j++) {
                int col = n0 + wn*32 + j*8 + 2*t;
                float b0 = bias[col], b1 = bias[col+1];
                float2 v0 = make_float2(c[i][j][0] + b0, c[i][j][1] + b1);
                float2 v1 = make_float2(c[i][j][2] + b0, c[i][j][3] + b1);
                *(float2*)&C[(size_t)r0     * N + col] = v0;
                *(float2*)&C[(size_t)(r0+8) * N + col] = v1;
            }
        }
    } else {
        float (*trans)[132] = reinterpret_cast<float(*)[132]>(dynsm);
#pragma unroll
        for (int chunk = 0; chunk < 4; chunk++) {
            __syncthreads();
            if (wn == chunk) {
#pragma unroll
                for (int i = 0; i < 4; i++) {
                    int mm = wm*64 + i*16 + g;
#pragma unroll
                    for (int j = 0; j < 4; j++) {
                        int nn  = j*8 + 2*t;
                        int col = n0 + chunk*32 + nn;
                        float b0 = (col     < N) ? bias[col]   : 0.f;
                        float b1 = (col + 1 < N) ? bias[col+1] : 0.f;
                        float v0 = c[i][j][0] + b0, v1 = c[i][j][1] + b1;
                        float v2 = c[i][j][2] + b0, v3 = c[i][j][3] + b1;
                        trans[nn  ][mm  ] = 1.f / (1.f + __expf(-v0));
                        trans[nn+1][mm  ] = 1.f / (1.f + __expf(-v1));
                        trans[nn  ][mm+8] = 1.f / (1.f + __expf(-v2));
                        trans[nn+1][mm+8] = 1.f / (1.f + __expf(-v3));
                    }
                }
            }
            __syncthreads();
#pragma unroll
            for (int p = 0; p < 4; p++) {
                int idx  = tid + p*256;
                int rowb = idx >> 5;
                int mc   = (idx & 31) * 4;
                int ngl  = n0 + chunk*32 + rowb;
                if (ngl < N)
                    *(float4*)&C[(size_t)ngl * M_TEST + m0 + mc] =
                        *(float4*)&trans[rowb][mc];
            }
        }
    }
}

/* ------- gemm2: 256x128 tile, A bf16-hi, B split (2 MMA) ----------------- */
#define ESTAGE 32768
#define ENSTG  3

__global__ void __launch_bounds__(256, 1) gemm_enc(
    const bf16* __restrict__ Ah,
    const bf16* __restrict__ Bh, const bf16* __restrict__ Bl,
    const float* __restrict__ bias, float* __restrict__ C,
    int M, int N, int K)
{
    extern __shared__ char dynsm[];
    const uint32_t smem = cvta_sm(dynsm);
    const int tid = threadIdx.x, lane = tid & 31, warp = tid >> 5;
    const int g = lane >> 2, t = lane & 3;
    const int wm = warp & 3, wn = warp >> 2;
    const int m0 = blockIdx.y * 256, n0 = blockIdx.x * 128;

    float c[4][8][4];
#pragma unroll
    for (int i = 0; i < 4; i++)
#pragma unroll
        for (int j = 0; j < 8; j++)
#pragma unroll
            for (int r = 0; r < 4; r++) c[i][j][r] = 0.f;

    const int kIters = K >> 5;

    auto load_stage = [&](int buf, int k0) {
        uint32_t sb = smem + buf * ESTAGE;
#pragma unroll
        for (int x = 0; x < 4; x++) {
            int ch = tid + x*256;
            int r = ch >> 2, hb = ch & 3;
            cp16(sb + swz(r, hb), Ah + (size_t)(m0 + r) * K + k0 + hb*8, 16);
        }
#pragma unroll
        for (int x = 0; x < 2; x++) {
            int ch = tid + x*256;
            int r = ch >> 2, hb = ch & 3;
            uint32_t so = swz(r, hb);
            size_t gb = (size_t)(n0 + r) * K + k0 + hb*8;
            cp16(sb + 16384 + so, Bh + gb, 16);
            cp16(sb + 24576 + so, Bl + gb, 16);
        }
    };

    auto compute = [&](int buf) {
        uint32_t sb = smem + buf * ESTAGE;
        const int rl = lane & 15;
        const int hx = lane >> 4;
#pragma unroll
        for (int s = 0; s < 2; s++) {
            const int hb = s*2 + hx;
            unsigned bh[8][2], bl[8][2];
#pragma unroll
            for (int j2 = 0; j2 < 4; j2++) {
                int row = wn*64 + j2*16 + rl;
                uint32_t off = swz(row, hb);
                unsigned r0, r1, r2, r3;
                ldsm4(r0, r1, r2, r3, sb + 16384 + off);
                bh[j2*2][0]=r0; bh[j2*2][1]=r2; bh[j2*2+1][0]=r1; bh[j2*2+1][1]=r3;
                ldsm4(r0, r1, r2, r3, sb + 24576 + off);
                bl[j2*2][0]=r0; bl[j2*2][1]=r2; bl[j2*2+1][0]=r1; bl[j2*2+1][1]=r3;
            }
#pragma unroll
            for (int i = 0; i < 4; i++) {
                int row = wm*64 + i*16 + rl;
                unsigned a0,a1,a2,a3;
                ldsm4(a0,a1,a2,a3, sb + swz(row, hb));
#pragma unroll
                for (int j = 0; j < 8; j++) {
                    mma_bf16(c[i][j], a0,a1,a2,a3, bh[j][0], bh[j][1]);
                    mma_bf16(c[i][j], a0,a1,a2,a3, bl[j][0], bl[j][1]);
                }
            }
        }
    };

    load_stage(0, 0);
    cp_commit();
    load_stage(1, 32);
    cp_commit();
    for (int it = 0; it < kIters; it++) {
        if (it + 1 < kIters)
            asm volatile("cp.async.wait_group 1;\n" ::: "memory");
        else
            asm volatile("cp.async.wait_group 0;\n" ::: "memory");
        __syncthreads();
        compute(it % ENSTG);
        __syncthreads();
        if (it + 2 < kIters) {
            load_stage((it+2) % ENSTG, (it+2)*32);
            cp_commit();
        }
    }

#pragma unroll
    for (int i = 0; i < 4; i++) {
        int r0 = m0 + wm*64 + i*16 + g;
#pragma unroll
        for (int j = 0; j < 8; j++) {
            int col = n0 + wn*64 + j*8 + 2*t;
            float b0 = bias[col], b1 = bias[col+1];
            float2 v0 = make_float2(c[i][j][0] + b0, c[i][j][1] + b1);
            float2 v1 = make_float2(c[i][j][2] + b0, c[i][j][3] + b1);
            *(float2*)&C[(size_t)r0     * N + col] = v0;
            *(float2*)&C[(size_t)(r0+8) * N + col] = v1;
        }
    }
}

/* ------------- LayerNorm + ReLU; SPLIT=1 emits bf16 hi only -------------- */
template<int SPLIT>
__global__ void ln_relu(const float* __restrict__ X, float* __restrict__ Y,
                        bf16* __restrict__ Yh,
                        const float* __restrict__ gg, const float* __restrict__ bb)
{
    const int row = blockIdx.x, tid = threadIdx.x;
    const float4 v = ((const float4*)(X + (size_t)row * HID))[tid];
    float s = v.x + v.y + v.z + v.w;
    float q = v.x*v.x + v.y*v.y + v.z*v.z + v.w*v.w;
#pragma unroll
    for (int o = 16; o; o >>= 1) {
        s += __shfl_xor_sync(0xffffffffu, s, o);
        q += __shfl_xor_sync(0xffffffffu, q, o);
    }
    __shared__ float ss[8], qs[8];
    if ((tid & 31) == 0) { ss[tid >> 5] = s; qs[tid >> 5] = q; }
    __syncthreads();
    s = ss[0]+ss[1]+ss[2]+ss[3]+ss[4]+ss[5]+ss[6]+ss[7];
    q = qs[0]+qs[1]+qs[2]+qs[3]+qs[4]+qs[5]+qs[6]+qs[7];
    float mean = s * (1.f/HID);
    float inv  = rsqrtf(q * (1.f/HID) - mean*mean + 1e-5f);
    float4 gv = ((const float4*)gg)[tid];
    float4 bv = ((const float4*)bb)[tid];
    float4 y;
    y.x = fmaxf((v.x - mean)*inv*gv.x + bv.x, 0.f);
    y.y = fmaxf((v.y - mean)*inv*gv.y + bv.y, 0.f);
    y.z = fmaxf((v.z - mean)*inv*gv.z + bv.z, 0.f);
    y.w = fmaxf((v.w - mean)*inv*gv.w + bv.w, 0.f);
    if (SPLIT) {
        __nv_bfloat162* ph = (__nv_bfloat162*)(Yh + (size_t)row * HID);
        ph[tid*2]   = __halves2bfloat162(__float2bfloat16(y.x), __float2bfloat16(y.y));
        ph[tid*2+1] = __halves2bfloat162(__float2bfloat16(y.z), __float2bfloat16(y.w));
    } else {
        ((float4*)(Y + (size_t)row * HID))[tid] = y;
    }
}

/* --------------------- column mean over rows -> ctx ---------------------- */
__global__ void col_partial(const float* __restrict__ X, float* __restrict__ part)
{
    int col   = blockIdx.x * 256 + threadIdx.x;
    int chunk = blockIdx.y;
    float s = 0.f;
    int r0 = chunk * 64;
    for (int r = r0; r < r0 + 64; r++) s += X[(size_t)r * HID + col];
    part[(size_t)chunk * HID + col] = s;
}
__global__ void col_final(const float* __restrict__ part, float* __restrict__ ctx)
{
    int col = blockIdx.x * 256 + threadIdx.x;
    float s = 0.f;
    for (int c = 0; c < 64; c++) s += part[(size_t)c * HID + col];
    ctx[col] = s * (1.f / M_TRAIN);
}

/* ------------------ hypernet matvec: out = W @ ctx + bias ---------------- */
__global__ void matvec(const float* __restrict__ W, const float* __restrict__ bias,
                       const float* __restrict__ ctx, float* __restrict__ out, int rows)
{
    int gw   = (blockIdx.x * blockDim.x + threadIdx.x) >> 5;
    int lane = threadIdx.x & 31;
    if (gw >= rows) return;
    const float4* w4 = (const float4*)(W + (size_t)gw * HID);
    const float4* c4 = (const float4*)ctx;
    float s = 0.f;
#pragma unroll
    for (int i = 0; i < 8; i++) {
        float4 a = w4[lane + 32*i];
        float4 c = __ldg(&c4[lane + 32*i]);
        s += a.x*c.x + a.y*c.y + a.z*c.z + a.w*c.w;
    }
#pragma unroll
    for (int o = 16; o; o >>= 1) s += __shfl_xor_sync(0xffffffffu, s, o);
    if (lane == 0) out[gw] = s + bias[gw];
}

/* ---- matvec emitting split bf16 hi/lo directly (for split_w) ------------ */
__global__ void matvec_split(const float* __restrict__ W, const float* __restrict__ bias,
                             const float* __restrict__ ctx,
                             bf16* __restrict__ oh, bf16* __restrict__ ol, int rows)
{
    int gw   = (blockIdx.x * blockDim.x + threadIdx.x) >> 5;
    int lane = threadIdx.x & 31;
    if (gw >= rows) return;
    const float4* w4 = (const float4*)(W + (size_t)gw * HID);
    const float4* c4 = (const float4*)ctx;
    float s = 0.f;
#pragma unroll
    for (int i = 0; i < 8; i++) {
        float4 a = w4[lane + 32*i];
        float4 c = __ldg(&c4[lane + 32*i]);
        s += a.x*c.x + a.y*c.y + a.z*c.z + a.w*c.w;
    }
#pragma unroll
    for (int o = 16; o; o >>= 1) s += __shfl_xor_sync(0xffffffffu, s, o);
    if (lane == 0) {
        float v = s + bias[gw];
        bf16 h = __float2bfloat16(v);
        oh[gw] = h;
        ol[gw] = __float2bfloat16(v - __bfloat162float(h));
    }
}

/* ---- fold tree_w softmax + leaf softmax into one table W[t,l,c] --------- */
__global__ void make_W(const float* __restrict__ tw, const float* __restrict__ lf,
                       float* __restrict__ Wout)
{
    __shared__ float tws[NTREES];
    int tid = threadIdx.x;
    if (tid == 0) {
        float mx = -1e30f;
        for (int i = 0; i < NTREES; i++) mx = fmaxf(mx, tw[i]);
        float e[NTREES], s = 0.f;
        for (int i = 0; i < NTREES; i++) { e[i] = expf(tw[i] - mx); s += e[i]; }
        for (int i = 0; i < NTREES; i++) tws[i] = e[i] / s;
    }
    __syncthreads();
    if (tid < NTREES * NLEAF) {
        const float* L = lf + tid * NCLS;
        float mx = -1e30f;
        for (int c = 0; c < NCLS; c++) mx = fmaxf(mx, L[c]);
        float e[NCLS], s = 0.f;
        for (int c = 0; c < NCLS; c++) { e[c] = expf(L[c] - mx); s += e[c]; }
        float scale = tws[tid >> 5] / s;
        for (int c = 0; c < NCLS; c++) Wout[tid * NCLS + c] = e[c] * scale;
    }
}

/* ------------- soft tree routing + class combine, thread per row --------- */
__global__ void route_kernel(const float* __restrict__ dec, const float* __restrict__ W,
                             float* __restrict__ out)
{
    __shared__ float Ws[LF_ROWS];
    int tid = threadIdx.x;
    for (int i = tid; i < LF_ROWS; i += 256) Ws[i] = W[i];
    __syncthreads();
    int b = blockIdx.x * 256 + tid;
    float acc[NCLS];
#pragma unroll
    for (int c = 0; c < NCLS; c++) acc[c] = 0.f;

    for (int t = 0; t < NTREES; t++) {
        float d[NINT];
#pragma unroll
        for (int n = 0; n < NINT; n++)
            d[n] = dec[(size_t)(t*NINT + n) * M_TEST + b];
#pragma unroll
        for (int l = 0; l < NLEAF; l++) {
            float p = 1.f;
#pragma unroll
            for (int dd = 0; dd < 5; dd++) {
                int node = (1 << dd) - 1 + (l >> (5 - dd));
                int go   = (l >> (4 - dd)) & 1;
                p *= go ? d[node] : (1.f - d[node]);
            }
            const float* w = &Ws[(t*NLEAF + l) * NCLS];
#pragma unroll
            for (int c = 0; c < NCLS; c++) acc[c] += p * w[c];
        }
    }
#pragma unroll
    for (int c = 0; c < NCLS; c++) out[(size_t)b * NCLS + c] = acc[c];
}

/* ------------------------------- launch ---------------------------------- */
extern "C" void kernel_launch(void* const* d_in, const int* in_sizes, int n_in,
                              void* d_out, int out_size)
{
    const float* X_train = (const float*)d_in[0];
    const float* X_test  = (const float*)d_in[1];
    const float* enc_w1  = (const float*)d_in[2];
    const float* enc_b1  = (const float*)d_in[3];
    const float* ln1_g   = (const float*)d_in[4];
    const float* ln1_b   = (const float*)d_in[5];
    const float* enc_w2  = (const float*)d_in[6];
    const float* enc_b2  = (const float*)d_in[7];
    const float* ln2_g   = (const float*)d_in[8];
    const float* ln2_b   = (const float*)d_in[9];
    const float* sw_w    = (const float*)d_in[10];
    const float* sw_b    = (const float*)d_in[11];
    const float* sb_w    = (const float*)d_in[12];
    const float* sb_b    = (const float*)d_in[13];
    const float* lf_w    = (const float*)d_in[14];
    const float* lf_b    = (const float*)d_in[15];
    const float* tw_w    = (const float*)d_in[16];
    const float* tw_b    = (const float*)d_in[17];

    float *C1, *C2, *part, *ctx, *sb, *lf, *tw, *W, *dec;
    bf16 *H1h, *Xtrh, *W1h, *W1l, *W2h, *W2l, *Xteh, *SWh, *SWl;
    cudaGetSymbolAddress((void**)&C1,   g_C1);
    cudaGetSymbolAddress((void**)&C2,   g_C2);
    cudaGetSymbolAddress((void**)&H1h,  g_H1h);
    cudaGetSymbolAddress((void**)&Xtrh, g_Xtrh);
    cudaGetSymbolAddress((void**)&W1h,  g_W1h);
    cudaGetSymbolAddress((void**)&W1l,  g_W1l);
    cudaGetSymbolAddress((void**)&W2h,  g_W2h);
    cudaGetSymbolAddress((void**)&W2l,  g_W2l);
    cudaGetSymbolAddress((void**)&Xteh, g_Xteh);
    cudaGetSymbolAddress((void**)&SWh,  g_SWh);
    cudaGetSymbolAddress((void**)&SWl,  g_SWl);
    cudaGetSymbolAddress((void**)&part, g_part);
    cudaGetSymbolAddress((void**)&ctx,  g_ctx);
    cudaGetSymbolAddress((void**)&sb,   g_sb);
    cudaGetSymbolAddress((void**)&lf,   g_lf);
    cudaGetSymbolAddress((void**)&tw,   g_tw);
    cudaGetSymbolAddress((void**)&W,    g_W);
    cudaGetSymbolAddress((void**)&dec,  g_dec);

    cudaFuncSetAttribute((const void*)gemm_enc,
                         cudaFuncAttributeMaxDynamicSharedMemorySize, ENSTG*ESTAGE);
    cudaFuncSetAttribute((const void*)gemm128<0>,
                         cudaFuncAttributeMaxDynamicSharedMemorySize, GNSTG*GSTAGE);
    cudaFuncSetAttribute((const void*)gemm128<1>,
                         cudaFuncAttributeMaxDynamicSharedMemorySize, GNSTG*GSTAGE);

    /* one launch: split everything (X_train/X_test hi-only; weights hi+lo) */
    split_all<<<928, 256>>>(X_train, enc_w1, enc_w2, X_test,
                            Xtrh, W1h, W1l, W2h, W2l, Xteh);

    /* encoder */
    gemm128<0><<<dim3(HID/128, M_TRAIN/128), 256, GNSTG*GSTAGE>>>(
        Xtrh, W1h, W1l, enc_b1, C1, M_TRAIN, HID, DIN);
    ln_relu<1><<<M_TRAIN, 256>>>(C1, nullptr, H1h, ln1_g, ln1_b);
    gemm_enc<<<dim3(HID/128, M_TRAIN/256), 256, ENSTG*ESTAGE>>>(
        H1h, W2h, W2l, enc_b2, C2, M_TRAIN, HID, HID);
    ln_relu<0><<<M_TRAIN, 256>>>(C2, C2, nullptr, ln2_g, ln2_b);

    /* ctx = mean over rows */
    col_partial<<<dim3(HID/256, 64), 256>>>(C2, part);
    col_final<<<HID/256, 256>>>(part, ctx);

    /* hypernet matvecs; sw emits split bf16 directly */
    matvec_split<<<(SW_ROWS*32 + 255)/256, 256>>>(sw_w, sw_b, ctx, SWh, SWl, SW_ROWS);
    matvec<<<(NSPLIT*32 + 255)/256, 256>>>(sb_w, sb_b, ctx, sb, NSPLIT);
    matvec<<<(LF_ROWS*32 + 255)/256, 256>>>(lf_w, lf_b, ctx, lf, LF_ROWS);
    matvec<<<(NTREES*32 + 255)/256, 256>>>(tw_w, tw_b, ctx, tw, NTREES);

    /* dec = sigmoid(X_test-hi @ split_w^T + sb), 2-term, stored transposed */
    gemm128<1><<<dim3((NSPLIT + 127)/128, M_TEST/128), 256, GNSTG*GSTAGE>>>(
        Xteh, SWh, SWl, sb, dec, M_TEST, NSPLIT, DIN);

    /* fold softmaxes, then route */
    make_W<<<1, 512>>>(tw, lf, W);
    route_kernel<<<M_TEST/256, 256>>>(dec, W, (float*)d_out);
}

// round 9
// speedup vs baseline: 1.9338x; 1.0468x over previous
#include <cuda_runtime.h>
#include <cuda_bf16.h>
#include <math.h>
#include <stdint.h>

typedef __nv_bfloat16 bf16;

#define M_TRAIN 4096
#define M_TEST  16384
#define DIN     128
#define HID     1024
#define NTREES  16
#define NINT    31
#define NLEAF   32
#define NCLS    10
#define NSPLIT  (NTREES*NINT)        /* 496 */
#define SW_ROWS (NTREES*NINT*DIN)    /* 63488 */
#define LF_ROWS (NTREES*NLEAF*NCLS)  /* 5120 */
#define MV_ROWS (SW_ROWS + NSPLIT + LF_ROWS + NTREES)  /* 69120 */

/* ---------------- scratch (static device memory; no allocs) -------------- */
__device__ float g_C1[M_TRAIN*HID];
__device__ float g_C2[M_TRAIN*HID];
__device__ bf16 g_H1h[M_TRAIN*HID];
__device__ bf16 g_Xtrh[M_TRAIN*DIN];
__device__ bf16 g_W1h[HID*DIN],     g_W1l[HID*DIN];
__device__ bf16 g_W2h[HID*HID],     g_W2l[HID*HID];
__device__ bf16 g_Xteh[M_TEST*DIN];
__device__ bf16 g_SWh[SW_ROWS],     g_SWl[SW_ROWS];
__device__ float g_part[64*HID];
__device__ float g_ctx[HID];
__device__ float g_sb[NSPLIT];
__device__ float g_lf[LF_ROWS];
__device__ float g_tw[NTREES];
__device__ float g_W[LF_ROWS];
__device__ float g_dec[NSPLIT*M_TEST];       /* TRANSPOSED [496][16384] */

/* ------------------------------ PTX helpers ------------------------------ */
__device__ __forceinline__ uint32_t cvta_sm(const void* p) {
    return (uint32_t)__cvta_generic_to_shared(p);
}
__device__ __forceinline__ void cp16(uint32_t dst, const void* src, int sz) {
    asm volatile("cp.async.cg.shared.global [%0], [%1], 16, %2;\n"
                 :: "r"(dst), "l"(src), "r"(sz));
}
__device__ __forceinline__ void cp_commit() {
    asm volatile("cp.async.commit_group;\n");
}
__device__ __forceinline__ void ldsm4(unsigned& r0, unsigned& r1,
                                      unsigned& r2, unsigned& r3, uint32_t a) {
    asm volatile("ldmatrix.sync.aligned.m8n8.x4.shared.b16 {%0,%1,%2,%3}, [%4];"
                 : "=r"(r0), "=r"(r1), "=r"(r2), "=r"(r3) : "r"(a));
}
__device__ __forceinline__ void mma_bf16(float c[4], unsigned a0, unsigned a1,
                                         unsigned a2, unsigned a3,
                                         unsigned b0, unsigned b1)
{
    asm volatile(
        "mma.sync.aligned.m16n8k16.row.col.f32.bf16.bf16.f32 "
        "{%0,%1,%2,%3}, {%4,%5,%6,%7}, {%8,%9}, {%0,%1,%2,%3};"
        : "+f"(c[0]), "+f"(c[1]), "+f"(c[2]), "+f"(c[3])
        : "r"(a0), "r"(a1), "r"(a2), "r"(a3), "r"(b0), "r"(b1));
}
/* swizzled byte offset inside a (rows x 32) bf16 tile, 64B rows */
__device__ __forceinline__ uint32_t swz(int r, int hb) {
    return (uint32_t)(r*64 + ((hb ^ ((r>>1)&3)) << 4));
}

/* ------------- ONE launch: split all static inputs to bf16 --------------- */
__global__ void split_all(const float* __restrict__ xtr, const float* __restrict__ w1,
                          const float* __restrict__ w2,  const float* __restrict__ xte,
                          bf16* __restrict__ xtrh,
                          bf16* __restrict__ w1h, bf16* __restrict__ w1l,
                          bf16* __restrict__ w2h, bf16* __restrict__ w2l,
                          bf16* __restrict__ xteh)
{
    int b = blockIdx.x;
    const float* src;
    bf16 *hi, *lo = nullptr;
    int base;
    if (b < 128)      { src = xtr; hi = xtrh;            base = b; }
    else if (b < 160) { src = w1;  hi = w1h;  lo = w1l;  base = b - 128; }
    else if (b < 416) { src = w2;  hi = w2h;  lo = w2l;  base = b - 160; }
    else              { src = xte; hi = xteh;            base = b - 416; }

    int i0 = base * 1024 + threadIdx.x;
    float4 v[4];
#pragma unroll
    for (int u = 0; u < 4; u++) v[u] = ((const float4*)src)[i0 + u*256];
#pragma unroll
    for (int u = 0; u < 4; u++) {
        int i = i0 + u*256;
        bf16 h0=__float2bfloat16(v[u].x), h1=__float2bfloat16(v[u].y);
        bf16 h2=__float2bfloat16(v[u].z), h3=__float2bfloat16(v[u].w);
        ((__nv_bfloat162*)hi)[i*2]   = __halves2bfloat162(h0, h1);
        ((__nv_bfloat162*)hi)[i*2+1] = __halves2bfloat162(h2, h3);
        if (lo) {
            bf16 l0=__float2bfloat16(v[u].x-__bfloat162float(h0));
            bf16 l1=__float2bfloat16(v[u].y-__bfloat162float(h1));
            bf16 l2=__float2bfloat16(v[u].z-__bfloat162float(h2));
            bf16 l3=__float2bfloat16(v[u].w-__bfloat162float(h3));
            ((__nv_bfloat162*)lo)[i*2]   = __halves2bfloat162(l0, l1);
            ((__nv_bfloat162*)lo)[i*2+1] = __halves2bfloat162(l2, l3);
        }
    }
}

/* ---- 128x128 2-term GEMM (A bf16-hi, B split): C = A @ B^T + bias ------- */
/* BK=32, 3-stage cp.async, occ 2, one sync per iteration.                   */
#define GSTAGE 24576
#define GNSTG  3

template<int EPI>
__global__ void __launch_bounds__(256, 2) gemm128(
    const bf16* __restrict__ Ah,
    const bf16* __restrict__ Bh, const bf16* __restrict__ Bl,
    const float* __restrict__ bias, float* __restrict__ C,
    int M, int N, int K)
{
    extern __shared__ char dynsm[];
    const uint32_t smem = cvta_sm(dynsm);
    const int tid = threadIdx.x, lane = tid & 31, warp = tid >> 5;
    const int g = lane >> 2, t = lane & 3;
    const int wm = warp & 1, wn = warp >> 1;
    const int m0 = blockIdx.y * 128, n0 = blockIdx.x * 128;

    float c[4][4][4];
#pragma unroll
    for (int i = 0; i < 4; i++)
#pragma unroll
        for (int j = 0; j < 4; j++)
#pragma unroll
            for (int r = 0; r < 4; r++) c[i][j][r] = 0.f;

    const int kIters = K >> 5;

    auto load_stage = [&](int buf, int k0) {
        uint32_t sb = smem + buf * GSTAGE;
#pragma unroll
        for (int x = 0; x < 2; x++) {
            int ch = tid + x*256;
            int r = ch >> 2, hb = ch & 3;
            uint32_t so = swz(r, hb);
            cp16(sb + so, Ah + (size_t)(m0 + r) * K + k0 + hb*8, 16);
            int bn = n0 + r;
            int sz = (bn < N) ? 16 : 0;
            size_t gb = (size_t)(sz ? bn : 0) * K + k0 + hb*8;
            cp16(sb + 8192  + so, Bh + gb, sz);
            cp16(sb + 16384 + so, Bl + gb, sz);
        }
    };

    auto compute = [&](int buf) {
        uint32_t sb = smem + buf * GSTAGE;
        const int rl = lane & 15;
        const int hx = lane >> 4;
#pragma unroll
        for (int s = 0; s < 2; s++) {
            const int hb = s*2 + hx;
            unsigned bh[4][2], bl[4][2];
#pragma unroll
            for (int j2 = 0; j2 < 2; j2++) {
                int row = wn*32 + j2*16 + rl;
                uint32_t off = swz(row, hb);
                unsigned r0, r1, r2, r3;
                ldsm4(r0, r1, r2, r3, sb + 8192 + off);
                bh[j2*2][0]=r0; bh[j2*2][1]=r2; bh[j2*2+1][0]=r1; bh[j2*2+1][1]=r3;
                ldsm4(r0, r1, r2, r3, sb + 16384 + off);
                bl[j2*2][0]=r0; bl[j2*2][1]=r2; bl[j2*2+1][0]=r1; bl[j2*2+1][1]=r3;
            }
#pragma unroll
            for (int i = 0; i < 4; i++) {
                int row = wm*64 + i*16 + rl;
                unsigned a0,a1,a2,a3;
                ldsm4(a0,a1,a2,a3, sb + swz(row, hb));
#pragma unroll
                for (int j = 0; j < 4; j++) {
                    mma_bf16(c[i][j], a0,a1,a2,a3, bh[j][0], bh[j][1]);
                    mma_bf16(c[i][j], a0,a1,a2,a3, bl[j][0], bl[j][1]);
                }
            }
        }
    };

    load_stage(0, 0);
    cp_commit();
    load_stage(1, 32);
    cp_commit();
    for (int it = 0; it < kIters; it++) {
        if (it + 1 < kIters)
            asm volatile("cp.async.wait_group 1;\n" ::: "memory");
        else
            asm volatile("cp.async.wait_group 0;\n" ::: "memory");
        __syncthreads();
        compute(it % GNSTG);
        /* no second sync: load targets (it+2)%3, disjoint from read buf */
        if (it + 2 < kIters) {
            load_stage((it+2) % GNSTG, (it+2)*32);
            cp_commit();
        }
    }

    if (EPI == 0) {
#pragma unroll
        for (int i = 0; i < 4; i++) {
            int r0 = m0 + wm*64 + i*16 + g;
#pragma unroll
            for (int j = 0; j < 4; j++) {
                int col = n0 + wn*32 + j*8 + 2*t;
                float b0 = bias[col], b1 = bias[col+1];
                float2 v0 = make_float2(c[i][j][0] + b0, c[i][j][1] + b1);
                float2 v1 = make_float2(c[i][j][2] + b0, c[i][j][3] + b1);
                *(float2*)&C[(size_t)r0     * N + col] = v0;
                *(float2*)&C[(size_t)(r0+8) * N + col] = v1;
            }
        }
    } else {
        float (*trans)[132] = reinterpret_cast<float(*)[132]>(dynsm);
#pragma unroll
        for (int chunk = 0; chunk < 4; chunk++) {
            __syncthreads();
            if (wn == chunk) {
#pragma unroll
                for (int i = 0; i < 4; i++) {
                    int mm = wm*64 + i*16 + g;
#pragma unroll
                    for (int j = 0; j < 4; j++) {
                        int nn  = j*8 + 2*t;
                        int col = n0 + chunk*32 + nn;
                        float b0 = (col     < N) ? bias[col]   : 0.f;
                        float b1 = (col + 1 < N) ? bias[col+1] : 0.f;
                        float v0 = c[i][j][0] + b0, v1 = c[i][j][1] + b1;
                        float v2 = c[i][j][2] + b0, v3 = c[i][j][3] + b1;
                        trans[nn  ][mm  ] = 1.f / (1.f + __expf(-v0));
                        trans[nn+1][mm  ] = 1.f / (1.f + __expf(-v1));
                        trans[nn  ][mm+8] = 1.f / (1.f + __expf(-v2));
                        trans[nn+1][mm+8] = 1.f / (1.f + __expf(-v3));
                    }
                }
            }
            __syncthreads();
#pragma unroll
            for (int p = 0; p < 4; p++) {
                int idx  = tid + p*256;
                int rowb = idx >> 5;
                int mc   = (idx & 31) * 4;
                int ngl  = n0 + chunk*32 + rowb;
                if (ngl < N)
                    *(float4*)&C[(size_t)ngl * M_TEST + m0 + mc] =
                        *(float4*)&trans[rowb][mc];
            }
        }
    }
}

/* ------------- LayerNorm + ReLU; SPLIT=1 emits bf16 hi only -------------- */
template<int SPLIT>
__global__ void ln_relu(const float* __restrict__ X, float* __restrict__ Y,
                        bf16* __restrict__ Yh,
                        const float* __restrict__ gg, const float* __restrict__ bb)
{
    const int row = blockIdx.x, tid = threadIdx.x;
    const float4 v = ((const float4*)(X + (size_t)row * HID))[tid];
    float s = v.x + v.y + v.z + v.w;
    float q = v.x*v.x + v.y*v.y + v.z*v.z + v.w*v.w;
#pragma unroll
    for (int o = 16; o; o >>= 1) {
        s += __shfl_xor_sync(0xffffffffu, s, o);
        q += __shfl_xor_sync(0xffffffffu, q, o);
    }
    __shared__ float ss[8], qs[8];
    if ((tid & 31) == 0) { ss[tid >> 5] = s; qs[tid >> 5] = q; }
    __syncthreads();
    s = ss[0]+ss[1]+ss[2]+ss[3]+ss[4]+ss[5]+ss[6]+ss[7];
    q = qs[0]+qs[1]+qs[2]+qs[3]+qs[4]+qs[5]+qs[6]+qs[7];
    float mean = s * (1.f/HID);
    float inv  = rsqrtf(q * (1.f/HID) - mean*mean + 1e-5f);
    float4 gv = ((const float4*)gg)[tid];
    float4 bv = ((const float4*)bb)[tid];
    float4 y;
    y.x = fmaxf((v.x - mean)*inv*gv.x + bv.x, 0.f);
    y.y = fmaxf((v.y - mean)*inv*gv.y + bv.y, 0.f);
    y.z = fmaxf((v.z - mean)*inv*gv.z + bv.z, 0.f);
    y.w = fmaxf((v.w - mean)*inv*gv.w + bv.w, 0.f);
    if (SPLIT) {
        __nv_bfloat162* ph = (__nv_bfloat162*)(Yh + (size_t)row * HID);
        ph[tid*2]   = __halves2bfloat162(__float2bfloat16(y.x), __float2bfloat16(y.y));
        ph[tid*2+1] = __halves2bfloat162(__float2bfloat16(y.z), __float2bfloat16(y.w));
    } else {
        ((float4*)(Y + (size_t)row * HID))[tid] = y;
    }
}

/* --------------------- column mean over rows -> ctx ---------------------- */
__global__ void col_partial(const float* __restrict__ X, float* __restrict__ part)
{
    int col   = blockIdx.x * 256 + threadIdx.x;
    int chunk = blockIdx.y;
    float s = 0.f;
    int r0 = chunk * 64;
    for (int r = r0; r < r0 + 64; r++) s += X[(size_t)r * HID + col];
    part[(size_t)chunk * HID + col] = s;
}
__global__ void col_final(const float* __restrict__ part, float* __restrict__ ctx)
{
    int col = blockIdx.x * 256 + threadIdx.x;
    float s = 0.f;
    for (int c = 0; c < 64; c++) s += part[(size_t)c * HID + col];
    ctx[col] = s * (1.f / M_TRAIN);
}

/* ---------- ONE launch: all hypernet matvecs (warp-id dispatch) ----------- */
__global__ void matvec_all(const float* __restrict__ sw_w, const float* __restrict__ sw_b,
                           const float* __restrict__ sb_w, const float* __restrict__ sb_b,
                           const float* __restrict__ lf_w, const float* __restrict__ lf_b,
                           const float* __restrict__ tw_w, const float* __restrict__ tw_b,
                           const float* __restrict__ ctx,
                           bf16* __restrict__ swh, bf16* __restrict__ swl,
                           float* __restrict__ sbo, float* __restrict__ lfo,
                           float* __restrict__ two)
{
    int gw   = (blockIdx.x * blockDim.x + threadIdx.x) >> 5;
    int lane = threadIdx.x & 31;
    if (gw >= MV_ROWS) return;
    const float *W, *bias;
    int row, mode;
    if (gw < SW_ROWS)                  { W=sw_w; bias=sw_b; row=gw;                    mode=0; }
    else if (gw < SW_ROWS+NSPLIT)      { W=sb_w; bias=sb_b; row=gw-SW_ROWS;            mode=1; }
    else if (gw < SW_ROWS+NSPLIT+LF_ROWS) { W=lf_w; bias=lf_b; row=gw-SW_ROWS-NSPLIT;  mode=2; }
    else                               { W=tw_w; bias=tw_b; row=gw-SW_ROWS-NSPLIT-LF_ROWS; mode=3; }

    const float4* w4 = (const float4*)(W + (size_t)row * HID);
    const float4* c4 = (const float4*)ctx;
    float s = 0.f;
#pragma unroll
    for (int i = 0; i < 8; i++) {
        float4 a = w4[lane + 32*i];
        float4 c = __ldg(&c4[lane + 32*i]);
        s += a.x*c.x + a.y*c.y + a.z*c.z + a.w*c.w;
    }
#pragma unroll
    for (int o = 16; o; o >>= 1) s += __shfl_xor_sync(0xffffffffu, s, o);
    if (lane == 0) {
        float v = s + bias[row];
        if (mode == 0) {
            bf16 h = __float2bfloat16(v);
            swh[row] = h;
            swl[row] = __float2bfloat16(v - __bfloat162float(h));
        } else if (mode == 1) sbo[row] = v;
        else if (mode == 2)   lfo[row] = v;
        else                  two[row] = v;
    }
}

/* ---- fold tree_w softmax + leaf softmax into one table W[t,l,c] --------- */
__global__ void make_W(const float* __restrict__ tw, const float* __restrict__ lf,
                       float* __restrict__ Wout)
{
    __shared__ float tws[NTREES];
    int tid = threadIdx.x;
    if (tid == 0) {
        float mx = -1e30f;
        for (int i = 0; i < NTREES; i++) mx = fmaxf(mx, tw[i]);
        float e[NTREES], s = 0.f;
        for (int i = 0; i < NTREES; i++) { e[i] = expf(tw[i] - mx); s += e[i]; }
        for (int i = 0; i < NTREES; i++) tws[i] = e[i] / s;
    }
    __syncthreads();
    if (tid < NTREES * NLEAF) {
        const float* L = lf + tid * NCLS;
        float mx = -1e30f;
        for (int c = 0; c < NCLS; c++) mx = fmaxf(mx, L[c]);
        float e[NCLS], s = 0.f;
        for (int c = 0; c < NCLS; c++) { e[c] = expf(L[c] - mx); s += e[c]; }
        float scale = tws[tid >> 5] / s;
        for (int c = 0; c < NCLS; c++) Wout[tid * NCLS + c] = e[c] * scale;
    }
}

/* ------------- soft tree routing + class combine, thread per row --------- */
__global__ void route_kernel(const float* __restrict__ dec, const float* __restrict__ W,
                             float* __restrict__ out)
{
    __shared__ float Ws[LF_ROWS];
    int tid = threadIdx.x;
    for (int i = tid; i < LF_ROWS; i += 256) Ws[i] = W[i];
    __syncthreads();
    int b = blockIdx.x * 256 + tid;
    float acc[NCLS];
#pragma unroll
    for (int c = 0; c < NCLS; c++) acc[c] = 0.f;

    for (int t = 0; t < NTREES; t++) {
        float d[NINT];
#pragma unroll
        for (int n = 0; n < NINT; n++)
            d[n] = dec[(size_t)(t*NINT + n) * M_TEST + b];
#pragma unroll
        for (int l = 0; l < NLEAF; l++) {
            float p = 1.f;
#pragma unroll
            for (int dd = 0; dd < 5; dd++) {
                int node = (1 << dd) - 1 + (l >> (5 - dd));
                int go   = (l >> (4 - dd)) & 1;
                p *= go ? d[node] : (1.f - d[node]);
            }
            const float* w = &Ws[(t*NLEAF + l) * NCLS];
#pragma unroll
            for (int c = 0; c < NCLS; c++) acc[c] += p * w[c];
        }
    }
#pragma unroll
    for (int c = 0; c < NCLS; c++) out[(size_t)b * NCLS + c] = acc[c];
}

/* ------------------------------- launch ---------------------------------- */
extern "C" void kernel_launch(void* const* d_in, const int* in_sizes, int n_in,
                              void* d_out, int out_size)
{
    const float* X_train = (const float*)d_in[0];
    const float* X_test  = (const float*)d_in[1];
    const float* enc_w1  = (const float*)d_in[2];
    const float* enc_b1  = (const float*)d_in[3];
    const float* ln1_g   = (const float*)d_in[4];
    const float* ln1_b   = (const float*)d_in[5];
    const float* enc_w2  = (const float*)d_in[6];
    const float* enc_b2  = (const float*)d_in[7];
    const float* ln2_g   = (const float*)d_in[8];
    const float* ln2_b   = (const float*)d_in[9];
    const float* sw_w    = (const float*)d_in[10];
    const float* sw_b    = (const float*)d_in[11];
    const float* sb_w    = (const float*)d_in[12];
    const float* sb_b    = (const float*)d_in[13];
    const float* lf_w    = (const float*)d_in[14];
    const float* lf_b    = (const float*)d_in[15];
    const float* tw_w    = (const float*)d_in[16];
    const float* tw_b    = (const float*)d_in[17];

    float *C1, *C2, *part, *ctx, *sb, *lf, *tw, *W, *dec;
    bf16 *H1h, *Xtrh, *W1h, *W1l, *W2h, *W2l, *Xteh, *SWh, *SWl;
    cudaGetSymbolAddress((void**)&C1,   g_C1);
    cudaGetSymbolAddress((void**)&C2,   g_C2);
    cudaGetSymbolAddress((void**)&H1h,  g_H1h);
    cudaGetSymbolAddress((void**)&Xtrh, g_Xtrh);
    cudaGetSymbolAddress((void**)&W1h,  g_W1h);
    cudaGetSymbolAddress((void**)&W1l,  g_W1l);
    cudaGetSymbolAddress((void**)&W2h,  g_W2h);
    cudaGetSymbolAddress((void**)&W2l,  g_W2l);
    cudaGetSymbolAddress((void**)&Xteh, g_Xteh);
    cudaGetSymbolAddress((void**)&SWh,  g_SWh);
    cudaGetSymbolAddress((void**)&SWl,  g_SWl);
    cudaGetSymbolAddress((void**)&part, g_part);
    cudaGetSymbolAddress((void**)&ctx,  g_ctx);
    cudaGetSymbolAddress((void**)&sb,   g_sb);
    cudaGetSymbolAddress((void**)&lf,   g_lf);
    cudaGetSymbolAddress((void**)&tw,   g_tw);
    cudaGetSymbolAddress((void**)&W,    g_W);
    cudaGetSymbolAddress((void**)&dec,  g_dec);

    cudaFuncSetAttribute((const void*)gemm128<0>,
                         cudaFuncAttributeMaxDynamicSharedMemorySize, GNSTG*GSTAGE);
    cudaFuncSetAttribute((const void*)gemm128<1>,
                         cudaFuncAttributeMaxDynamicSharedMemorySize, GNSTG*GSTAGE);

    /* one launch: split everything (X_train/X_test hi-only; weights hi+lo) */
    split_all<<<928, 256>>>(X_train, enc_w1, enc_w2, X_test,
                            Xtrh, W1h, W1l, W2h, W2l, Xteh);

    /* encoder: both GEMMs on the occ-2 128x128 kernel */
    gemm128<0><<<dim3(HID/128, M_TRAIN/128), 256, GNSTG*GSTAGE>>>(
        Xtrh, W1h, W1l, enc_b1, C1, M_TRAIN, HID, DIN);
    ln_relu<1><<<M_TRAIN, 256>>>(C1, nullptr, H1h, ln1_g, ln1_b);
    gemm128<0><<<dim3(HID/128, M_TRAIN/128), 256, GNSTG*GSTAGE>>>(
        H1h, W2h, W2l, enc_b2, C2, M_TRAIN, HID, HID);
    ln_relu<0><<<M_TRAIN, 256>>>(C2, C2, nullptr, ln2_g, ln2_b);

    /* ctx = mean over rows */
    col_partial<<<dim3(HID/256, 64), 256>>>(C2, part);
    col_final<<<HID/256, 256>>>(part, ctx);

    /* ALL hypernet matvecs in one launch (sw emits split bf16 directly) */
    matvec_all<<<(MV_ROWS*32 + 255)/256, 256>>>(
        sw_w, sw_b, sb_w, sb_b, lf_w, lf_b, tw_w, tw_b, ctx,
        SWh, SWl, sb, lf, tw);

    /* dec = sigmoid(X_test-hi @ split_w^T + sb), 2-term, stored transposed */
    gemm128<1><<<dim3((NSPLIT + 127)/128, M_TEST/128), 256, GNSTG*GSTAGE>>>(
        Xteh, SWh, SWl, sb, dec, M_TEST, NSPLIT, DIN);

    /* fold softmaxes, then route */
    make_W<<<1, 512>>>(tw, lf, W);
    route_kernel<<<M_TEST/256, 256>>>(dec, W, (float*)d_out);
}

// round 10
// speedup vs baseline: 1.9479x; 1.0073x over previous
#include <cuda_runtime.h>
#include <cuda_bf16.h>
#include <math.h>
#include <stdint.h>

typedef __nv_bfloat16 bf16;

#define M_TRAIN 4096
#define M_TEST  16384
#define DIN     128
#define HID     1024
#define NTREES  16
#define NINT    31
#define NLEAF   32
#define NCLS    10
#define NSPLIT  (NTREES*NINT)        /* 496 */
#define SW_ROWS (NTREES*NINT*DIN)    /* 63488 */
#define LF_ROWS (NTREES*NLEAF*NCLS)  /* 5120 */
#define MV_ROWS (SW_ROWS + NSPLIT + LF_ROWS + NTREES)  /* 69120 */

/* ---------------- scratch (static device memory; no allocs) -------------- */
__device__ float g_C1[M_TRAIN*HID];
__device__ float g_C2[M_TRAIN*HID];
__device__ bf16 g_H1h[M_TRAIN*HID];
__device__ bf16 g_Xtrh[M_TRAIN*DIN];
__device__ bf16 g_W1h[HID*DIN],     g_W1l[HID*DIN];
__device__ bf16 g_W2h[HID*HID],     g_W2l[HID*HID];
__device__ bf16 g_Xteh[M_TEST*DIN];
__device__ bf16 g_SWh[SW_ROWS],     g_SWl[SW_ROWS];
__device__ float g_part[64*HID];
__device__ float g_ctx[HID];
__device__ float g_sb[NSPLIT];
__device__ float g_lf[LF_ROWS];
__device__ float g_tw[NTREES];
__device__ float g_W[LF_ROWS];
__device__ float g_dec[NSPLIT*M_TEST];       /* TRANSPOSED [496][16384] */

/* ------------------------------ PTX helpers ------------------------------ */
__device__ __forceinline__ uint32_t cvta_sm(const void* p) {
    return (uint32_t)__cvta_generic_to_shared(p);
}
__device__ __forceinline__ void cp16(uint32_t dst, const void* src, int sz) {
    asm volatile("cp.async.cg.shared.global [%0], [%1], 16, %2;\n"
                 :: "r"(dst), "l"(src), "r"(sz));
}
__device__ __forceinline__ void cp_commit() {
    asm volatile("cp.async.commit_group;\n");
}
__device__ __forceinline__ void ldsm4(unsigned& r0, unsigned& r1,
                                      unsigned& r2, unsigned& r3, uint32_t a) {
    asm volatile("ldmatrix.sync.aligned.m8n8.x4.shared.b16 {%0,%1,%2,%3}, [%4];"
                 : "=r"(r0), "=r"(r1), "=r"(r2), "=r"(r3) : "r"(a));
}
__device__ __forceinline__ void mma_bf16(float c[4], unsigned a0, unsigned a1,
                                         unsigned a2, unsigned a3,
                                         unsigned b0, unsigned b1)
{
    asm volatile(
        "mma.sync.aligned.m16n8k16.row.col.f32.bf16.bf16.f32 "
        "{%0,%1,%2,%3}, {%4,%5,%6,%7}, {%8,%9}, {%0,%1,%2,%3};"
        : "+f"(c[0]), "+f"(c[1]), "+f"(c[2]), "+f"(c[3])
        : "r"(a0), "r"(a1), "r"(a2), "r"(a3), "r"(b0), "r"(b1));
}
/* swizzled byte offset inside a (rows x 32) bf16 tile, 64B rows */
__device__ __forceinline__ uint32_t swz(int r, int hb) {
    return (uint32_t)(r*64 + ((hb ^ ((r>>1)&3)) << 4));
}

/* ------------- ONE launch: split all static inputs to bf16 --------------- */
__global__ void split_all(const float* __restrict__ xtr, const float* __restrict__ w1,
                          const float* __restrict__ w2,  const float* __restrict__ xte,
                          bf16* __restrict__ xtrh,
                          bf16* __restrict__ w1h, bf16* __restrict__ w1l,
                          bf16* __restrict__ w2h, bf16* __restrict__ w2l,
                          bf16* __restrict__ xteh)
{
    int b = blockIdx.x;
    const float* src;
    bf16 *hi, *lo = nullptr;
    int base;
    if (b < 128)      { src = xtr; hi = xtrh;            base = b; }
    else if (b < 160) { src = w1;  hi = w1h;  lo = w1l;  base = b - 128; }
    else if (b < 416) { src = w2;  hi = w2h;  lo = w2l;  base = b - 160; }
    else              { src = xte; hi = xteh;            base = b - 416; }

    int i0 = base * 1024 + threadIdx.x;
    float4 v[4];
#pragma unroll
    for (int u = 0; u < 4; u++) v[u] = ((const float4*)src)[i0 + u*256];
#pragma unroll
    for (int u = 0; u < 4; u++) {
        int i = i0 + u*256;
        bf16 h0=__float2bfloat16(v[u].x), h1=__float2bfloat16(v[u].y);
        bf16 h2=__float2bfloat16(v[u].z), h3=__float2bfloat16(v[u].w);
        ((__nv_bfloat162*)hi)[i*2]   = __halves2bfloat162(h0, h1);
        ((__nv_bfloat162*)hi)[i*2+1] = __halves2bfloat162(h2, h3);
        if (lo) {
            bf16 l0=__float2bfloat16(v[u].x-__bfloat162float(h0));
            bf16 l1=__float2bfloat16(v[u].y-__bfloat162float(h1));
            bf16 l2=__float2bfloat16(v[u].z-__bfloat162float(h2));
            bf16 l3=__float2bfloat16(v[u].w-__bfloat162float(h3));
            ((__nv_bfloat162*)lo)[i*2]   = __halves2bfloat162(l0, l1);
            ((__nv_bfloat162*)lo)[i*2+1] = __halves2bfloat162(l2, l3);
        }
    }
}

/* ---- 64x128 2-term GEMM (A bf16-hi, B split): C = A @ B^T + bias -------- */
/* Warp tile 32x32. BK=32, 3-stage cp.async, occ 2.                          */
/* Full fragment batching: all 24 LDSM issued before the 64 MMAs.            */
/* Stage 20KB: A@0 (4K), Bh@4K (8K), Bl@12K (8K).                            */
#define GSTAGE 20480
#define GNSTG  3

template<int EPI>
__global__ void __launch_bounds__(256, 2) gemm64(
    const bf16* __restrict__ Ah,
    const bf16* __restrict__ Bh, const bf16* __restrict__ Bl,
    const float* __restrict__ bias, float* __restrict__ C,
    int M, int N, int K)
{
    extern __shared__ char dynsm[];
    const uint32_t smem = cvta_sm(dynsm);
    const int tid = threadIdx.x, lane = tid & 31, warp = tid >> 5;
    const int g = lane >> 2, t = lane & 3;
    const int wm = warp & 1, wn = warp >> 1;     /* 2(m) x 4(n) warps */
    const int m0 = blockIdx.y * 64, n0 = blockIdx.x * 128;

    float c[2][4][4];
#pragma unroll
    for (int i = 0; i < 2; i++)
#pragma unroll
        for (int j = 0; j < 4; j++)
#pragma unroll
            for (int r = 0; r < 4; r++) c[i][j][r] = 0.f;

    const int kIters = K >> 5;

    auto load_stage = [&](int buf, int k0) {
        uint32_t sb = smem + buf * GSTAGE;
        /* A: 64 rows x 4 chunks = 256 cp16 -> 1/thread */
        {
            int r = tid >> 2, hb = tid & 3;
            cp16(sb + swz(r, hb), Ah + (size_t)(m0 + r) * K + k0 + hb*8, 16);
        }
        /* B: 128 rows x 4 chunks, hi+lo -> 2+2/thread */
#pragma unroll
        for (int x = 0; x < 2; x++) {
            int ch = tid + x*256;
            int r = ch >> 2, hb = ch & 3;
            uint32_t so = swz(r, hb);
            int bn = n0 + r;
            int sz = (bn < N) ? 16 : 0;
            size_t gb = (size_t)(sz ? bn : 0) * K + k0 + hb*8;
            cp16(sb + 4096  + so, Bh + gb, sz);
            cp16(sb + 12288 + so, Bl + gb, sz);
        }
    };

    auto compute = [&](int buf) {
        uint32_t sb = smem + buf * GSTAGE;
        const int rl = lane & 15;
        const int hx = lane >> 4;
        unsigned af[2][2][4], bhf[2][4][2], blf[2][4][2];
        /* batch ALL fragment loads for the whole BK=32 iteration */
#pragma unroll
        for (int s = 0; s < 2; s++) {
            const int hb = s*2 + hx;
#pragma unroll
            for (int j2 = 0; j2 < 2; j2++) {
                int row = wn*32 + j2*16 + rl;
                uint32_t off = swz(row, hb);
                unsigned r0, r1, r2, r3;
                ldsm4(r0, r1, r2, r3, sb + 4096 + off);
                bhf[s][j2*2][0]=r0; bhf[s][j2*2][1]=r2;
                bhf[s][j2*2+1][0]=r1; bhf[s][j2*2+1][1]=r3;
                ldsm4(r0, r1, r2, r3, sb + 12288 + off);
                blf[s][j2*2][0]=r0; blf[s][j2*2][1]=r2;
                blf[s][j2*2+1][0]=r1; blf[s][j2*2+1][1]=r3;
            }
#pragma unroll
            for (int i = 0; i < 2; i++) {
                int row = wm*32 + i*16 + rl;
                ldsm4(af[s][i][0], af[s][i][1], af[s][i][2], af[s][i][3],
                      sb + swz(row, hb));
            }
        }
        /* then run all 64 MMAs back-to-back */
#pragma unroll
        for (int s = 0; s < 2; s++)
#pragma unroll
            for (int i = 0; i < 2; i++)
#pragma unroll
                for (int j = 0; j < 4; j++) {
                    mma_bf16(c[i][j], af[s][i][0],af[s][i][1],af[s][i][2],af[s][i][3],
                             bhf[s][j][0], bhf[s][j][1]);
                    mma_bf16(c[i][j], af[s][i][0],af[s][i][1],af[s][i][2],af[s][i][3],
                             blf[s][j][0], blf[s][j][1]);
                }
    };

    load_stage(0, 0);
    cp_commit();
    load_stage(1, 32);
    cp_commit();
    for (int it = 0; it < kIters; it++) {
        if (it + 1 < kIters)
            asm volatile("cp.async.wait_group 1;\n" ::: "memory");
        else
            asm volatile("cp.async.wait_group 0;\n" ::: "memory");
        __syncthreads();
        compute(it % GNSTG);
        /* no second sync: load targets (it+2)%3, disjoint from read buf */
        if (it + 2 < kIters) {
            load_stage((it+2) % GNSTG, (it+2)*32);
            cp_commit();
        }
    }

    if (EPI == 0) {
#pragma unroll
        for (int i = 0; i < 2; i++) {
            int r0 = m0 + wm*32 + i*16 + g;
#pragma unroll
            for (int j = 0; j < 4; j++) {
                int col = n0 + wn*32 + j*8 + 2*t;
                float b0 = bias[col], b1 = bias[col+1];
                float2 v0 = make_float2(c[i][j][0] + b0, c[i][j][1] + b1);
                float2 v1 = make_float2(c[i][j][2] + b0, c[i][j][3] + b1);
                *(float2*)&C[(size_t)r0     * N + col] = v0;
                *(float2*)&C[(size_t)(r0+8) * N + col] = v1;
            }
        }
    } else {
        /* sigmoid + transposed store via smem staging (32-col chunks) */
        float (*trans)[68] = reinterpret_cast<float(*)[68]>(dynsm);
#pragma unroll
        for (int chunk = 0; chunk < 4; chunk++) {
            __syncthreads();
            if (wn == chunk) {
#pragma unroll
                for (int i = 0; i < 2; i++) {
                    int mm = wm*32 + i*16 + g;
#pragma unroll
                    for (int j = 0; j < 4; j++) {
                        int nn  = j*8 + 2*t;
                        int col = n0 + chunk*32 + nn;
                        float b0 = (col     < N) ? bias[col]   : 0.f;
                        float b1 = (col + 1 < N) ? bias[col+1] : 0.f;
                        float v0 = c[i][j][0] + b0, v1 = c[i][j][1] + b1;
                        float v2 = c[i][j][2] + b0, v3 = c[i][j][3] + b1;
                        trans[nn  ][mm  ] = 1.f / (1.f + __expf(-v0));
                        trans[nn+1][mm  ] = 1.f / (1.f + __expf(-v1));
                        trans[nn  ][mm+8] = 1.f / (1.f + __expf(-v2));
                        trans[nn+1][mm+8] = 1.f / (1.f + __expf(-v3));
                    }
                }
            }
            __syncthreads();
            /* cooperative store: 32 cols x 64 rows = 512 float4 */
#pragma unroll
            for (int p = 0; p < 2; p++) {
                int idx  = tid + p*256;
                int colb = idx >> 4;
                int mq   = (idx & 15) * 4;
                int ngl  = n0 + chunk*32 + colb;
                if (ngl < N)
                    *(float4*)&C[(size_t)ngl * M_TEST + m0 + mq] =
                        *(float4*)&trans[colb][mq];
            }
        }
    }
}

/* ------------- LayerNorm + ReLU; SPLIT=1 emits bf16 hi only -------------- */
template<int SPLIT>
__global__ void ln_relu(const float* __restrict__ X, float* __restrict__ Y,
                        bf16* __restrict__ Yh,
                        const float* __restrict__ gg, const float* __restrict__ bb)
{
    const int row = blockIdx.x, tid = threadIdx.x;
    const float4 v = ((const float4*)(X + (size_t)row * HID))[tid];
    float s = v.x + v.y + v.z + v.w;
    float q = v.x*v.x + v.y*v.y + v.z*v.z + v.w*v.w;
#pragma unroll
    for (int o = 16; o; o >>= 1) {
        s += __shfl_xor_sync(0xffffffffu, s, o);
        q += __shfl_xor_sync(0xffffffffu, q, o);
    }
    __shared__ float ss[8], qs[8];
    if ((tid & 31) == 0) { ss[tid >> 5] = s; qs[tid >> 5] = q; }
    __syncthreads();
    s = ss[0]+ss[1]+ss[2]+ss[3]+ss[4]+ss[5]+ss[6]+ss[7];
    q = qs[0]+qs[1]+qs[2]+qs[3]+qs[4]+qs[5]+qs[6]+qs[7];
    float mean = s * (1.f/HID);
    float inv  = rsqrtf(q * (1.f/HID) - mean*mean + 1e-5f);
    float4 gv = ((const float4*)gg)[tid];
    float4 bv = ((const float4*)bb)[tid];
    float4 y;
    y.x = fmaxf((v.x - mean)*inv*gv.x + bv.x, 0.f);
    y.y = fmaxf((v.y - mean)*inv*gv.y + bv.y, 0.f);
    y.z = fmaxf((v.z - mean)*inv*gv.z + bv.z, 0.f);
    y.w = fmaxf((v.w - mean)*inv*gv.w + bv.w, 0.f);
    if (SPLIT) {
        __nv_bfloat162* ph = (__nv_bfloat162*)(Yh + (size_t)row * HID);
        ph[tid*2]   = __halves2bfloat162(__float2bfloat16(y.x), __float2bfloat16(y.y));
        ph[tid*2+1] = __halves2bfloat162(__float2bfloat16(y.z), __float2bfloat16(y.w));
    } else {
        ((float4*)(Y + (size_t)row * HID))[tid] = y;
    }
}

/* --------------------- column mean over rows -> ctx ---------------------- */
__global__ void col_partial(const float* __restrict__ X, float* __restrict__ part)
{
    int col   = blockIdx.x * 256 + threadIdx.x;
    int chunk = blockIdx.y;
    float s = 0.f;
    int r0 = chunk * 64;
    for (int r = r0; r < r0 + 64; r++) s += X[(size_t)r * HID + col];
    part[(size_t)chunk * HID + col] = s;
}
__global__ void col_final(const float* __restrict__ part, float* __restrict__ ctx)
{
    int col = blockIdx.x * 256 + threadIdx.x;
    float s = 0.f;
    for (int c = 0; c < 64; c++) s += part[(size_t)c * HID + col];
    ctx[col] = s * (1.f / M_TRAIN);
}

/* ---------- ONE launch: all hypernet matvecs (warp-id dispatch) ----------- */
__global__ void matvec_all(const float* __restrict__ sw_w, const float* __restrict__ sw_b,
                           const float* __restrict__ sb_w, const float* __restrict__ sb_b,
                           const float* __restrict__ lf_w, const float* __restrict__ lf_b,
                           const float* __restrict__ tw_w, const float* __restrict__ tw_b,
                           const float* __restrict__ ctx,
                           bf16* __restrict__ swh, bf16* __restrict__ swl,
                           float* __restrict__ sbo, float* __restrict__ lfo,
                           float* __restrict__ two)
{
    int gw   = (blockIdx.x * blockDim.x + threadIdx.x) >> 5;
    int lane = threadIdx.x & 31;
    if (gw >= MV_ROWS) return;
    const float *W, *bias;
    int row, mode;
    if (gw < SW_ROWS)                  { W=sw_w; bias=sw_b; row=gw;                    mode=0; }
    else if (gw < SW_ROWS+NSPLIT)      { W=sb_w; bias=sb_b; row=gw-SW_ROWS;            mode=1; }
    else if (gw < SW_ROWS+NSPLIT+LF_ROWS) { W=lf_w; bias=lf_b; row=gw-SW_ROWS-NSPLIT;  mode=2; }
    else                               { W=tw_w; bias=tw_b; row=gw-SW_ROWS-NSPLIT-LF_ROWS; mode=3; }

    const float4* w4 = (const float4*)(W + (size_t)row * HID);
    const float4* c4 = (const float4*)ctx;
    float s = 0.f;
#pragma unroll
    for (int i = 0; i < 8; i++) {
        float4 a = w4[lane + 32*i];
        float4 c = __ldg(&c4[lane + 32*i]);
        s += a.x*c.x + a.y*c.y + a.z*c.z + a.w*c.w;
    }
#pragma unroll
    for (int o = 16; o; o >>= 1) s += __shfl_xor_sync(0xffffffffu, s, o);
    if (lane == 0) {
        float v = s + bias[row];
        if (mode == 0) {
            bf16 h = __float2bfloat16(v);
            swh[row] = h;
            swl[row] = __float2bfloat16(v - __bfloat162float(h));
        } else if (mode == 1) sbo[row] = v;
        else if (mode == 2)   lfo[row] = v;
        else                  two[row] = v;
    }
}

/* ---- fold tree_w softmax + leaf softmax into one table W[t,l,c] --------- */
__global__ void make_W(const float* __restrict__ tw, const float* __restrict__ lf,
                       float* __restrict__ Wout)
{
    __shared__ float tws[NTREES];
    int tid = threadIdx.x;
    if (tid == 0) {
        float mx = -1e30f;
        for (int i = 0; i < NTREES; i++) mx = fmaxf(mx, tw[i]);
        float e[NTREES], s = 0.f;
        for (int i = 0; i < NTREES; i++) { e[i] = expf(tw[i] - mx); s += e[i]; }
        for (int i = 0; i < NTREES; i++) tws[i] = e[i] / s;
    }
    __syncthreads();
    if (tid < NTREES * NLEAF) {
        const float* L = lf + tid * NCLS;
        float mx = -1e30f;
        for (int c = 0; c < NCLS; c++) mx = fmaxf(mx, L[c]);
        float e[NCLS], s = 0.f;
        for (int c = 0; c < NCLS; c++) { e[c] = expf(L[c] - mx); s += e[c]; }
        float scale = tws[tid >> 5] / s;
        for (int c = 0; c < NCLS; c++) Wout[tid * NCLS + c] = e[c] * scale;
    }
}

/* ------------- soft tree routing + class combine, thread per row --------- */
__global__ void route_kernel(const float* __restrict__ dec, const float* __restrict__ W,
                             float* __restrict__ out)
{
    __shared__ float Ws[LF_ROWS];
    int tid = threadIdx.x;
    for (int i = tid; i < LF_ROWS; i += 256) Ws[i] = W[i];
    __syncthreads();
    int b = blockIdx.x * 256 + tid;
    float acc[NCLS];
#pragma unroll
    for (int c = 0; c < NCLS; c++) acc[c] = 0.f;

    for (int t = 0; t < NTREES; t++) {
        float d[NINT];
#pragma unroll
        for (int n = 0; n < NINT; n++)
            d[n] = dec[(size_t)(t*NINT + n) * M_TEST + b];
#pragma unroll
        for (int l = 0; l < NLEAF; l++) {
            float p = 1.f;
#pragma unroll
            for (int dd = 0; dd < 5; dd++) {
                int node = (1 << dd) - 1 + (l >> (5 - dd));
                int go   = (l >> (4 - dd)) & 1;
                p *= go ? d[node] : (1.f - d[node]);
            }
            const float* w = &Ws[(t*NLEAF + l) * NCLS];
#pragma unroll
            for (int c = 0; c < NCLS; c++) acc[c] += p * w[c];
        }
    }
#pragma unroll
    for (int c = 0; c < NCLS; c++) out[(size_t)b * NCLS + c] = acc[c];
}

/* ------------------------------- launch ---------------------------------- */
extern "C" void kernel_launch(void* const* d_in, const int* in_sizes, int n_in,
                              void* d_out, int out_size)
{
    const float* X_train = (const float*)d_in[0];
    const float* X_test  = (const float*)d_in[1];
    const float* enc_w1  = (const float*)d_in[2];
    const float* enc_b1  = (const float*)d_in[3];
    const float* ln1_g   = (const float*)d_in[4];
    const float* ln1_b   = (const float*)d_in[5];
    const float* enc_w2  = (const float*)d_in[6];
    const float* enc_b2  = (const float*)d_in[7];
    const float* ln2_g   = (const float*)d_in[8];
    const float* ln2_b   = (const float*)d_in[9];
    const float* sw_w    = (const float*)d_in[10];
    const float* sw_b    = (const float*)d_in[11];
    const float* sb_w    = (const float*)d_in[12];
    const float* sb_b    = (const float*)d_in[13];
    const float* lf_w    = (const float*)d_in[14];
    const float* lf_b    = (const float*)d_in[15];
    const float* tw_w    = (const float*)d_in[16];
    const float* tw_b    = (const float*)d_in[17];

    float *C1, *C2, *part, *ctx, *sb, *lf, *tw, *W, *dec;
    bf16 *H1h, *Xtrh, *W1h, *W1l, *W2h, *W2l, *Xteh, *SWh, *SWl;
    cudaGetSymbolAddress((void**)&C1,   g_C1);
    cudaGetSymbolAddress((void**)&C2,   g_C2);
    cudaGetSymbolAddress((void**)&H1h,  g_H1h);
    cudaGetSymbolAddress((void**)&Xtrh, g_Xtrh);
    cudaGetSymbolAddress((void**)&W1h,  g_W1h);
    cudaGetSymbolAddress((void**)&W1l,  g_W1l);
    cudaGetSymbolAddress((void**)&W2h,  g_W2h);
    cudaGetSymbolAddress((void**)&W2l,  g_W2l);
    cudaGetSymbolAddress((void**)&Xteh, g_Xteh);
    cudaGetSymbolAddress((void**)&SWh,  g_SWh);
    cudaGetSymbolAddress((void**)&SWl,  g_SWl);
    cudaGetSymbolAddress((void**)&part, g_part);
    cudaGetSymbolAddress((void**)&ctx,  g_ctx);
    cudaGetSymbolAddress((void**)&sb,   g_sb);
    cudaGetSymbolAddress((void**)&lf,   g_lf);
    cudaGetSymbolAddress((void**)&tw,   g_tw);
    cudaGetSymbolAddress((void**)&W,    g_W);
    cudaGetSymbolAddress((void**)&dec,  g_dec);

    cudaFuncSetAttribute((const void*)gemm64<0>,
                         cudaFuncAttributeMaxDynamicSharedMemorySize, GNSTG*GSTAGE);
    cudaFuncSetAttribute((const void*)gemm64<1>,
                         cudaFuncAttributeMaxDynamicSharedMemorySize, GNSTG*GSTAGE);

    /* one launch: split everything (X_train/X_test hi-only; weights hi+lo) */
    split_all<<<928, 256>>>(X_train, enc_w1, enc_w2, X_test,
                            Xtrh, W1h, W1l, W2h, W2l, Xteh);

    /* encoder: both GEMMs on the 64x128 occ-2 kernel */
    gemm64<0><<<dim3(HID/128, M_TRAIN/64), 256, GNSTG*GSTAGE>>>(
        Xtrh, W1h, W1l, enc_b1, C1, M_TRAIN, HID, DIN);
    ln_relu<1><<<M_TRAIN, 256>>>(C1, nullptr, H1h, ln1_g, ln1_b);
    gemm64<0><<<dim3(HID/128, M_TRAIN/64), 256, GNSTG*GSTAGE>>>(
        H1h, W2h, W2l, enc_b2, C2, M_TRAIN, HID, HID);
    ln_relu<0><<<M_TRAIN, 256>>>(C2, C2, nullptr, ln2_g, ln2_b);

    /* ctx = mean over rows */
    col_partial<<<dim3(HID/256, 64), 256>>>(C2, part);
    col_final<<<HID/256, 256>>>(part, ctx);

    /* ALL hypernet matvecs in one launch (sw emits split bf16 directly) */
    matvec_all<<<(MV_ROWS*32 + 255)/256, 256>>>(
        sw_w, sw_b, sb_w, sb_b, lf_w, lf_b, tw_w, tw_b, ctx,
        SWh, SWl, sb, lf, tw);

    /* dec = sigmoid(X_test-hi @ split_w^T + sb), 2-term, stored transposed */
    gemm64<1><<<dim3((NSPLIT + 127)/128, M_TEST/64), 256, GNSTG*GSTAGE>>>(
        Xteh, SWh, SWl, sb, dec, M_TEST, NSPLIT, DIN);

    /* fold softmaxes, then route */
    make_W<<<1, 512>>>(tw, lf, W);
    route_kernel<<<M_TEST/256, 256>>>(dec, W, (float*)d_out);
}

// round 11
// speedup vs baseline: 2.2198x; 1.1396x over previous
#include <cuda_runtime.h>
#include <cuda_fp16.h>
#include <math.h>
#include <stdint.h>

#define M_TRAIN 4096
#define M_TEST  16384
#define DIN     128
#define HID     1024
#define NTREES  16
#define NINT    31
#define NLEAF   32
#define NCLS    10
#define NSPLIT  (NTREES*NINT)        /* 496 */
#define SW_ROWS (NTREES*NINT*DIN)    /* 63488 */
#define LF_ROWS (NTREES*NLEAF*NCLS)  /* 5120 */
#define MV_ROWS (SW_ROWS + NSPLIT + LF_ROWS + NTREES)  /* 69120 */

/* ---------------- scratch (static device memory; no allocs) -------------- */
__device__ float  g_C1[M_TRAIN*HID];
__device__ float  g_C2[M_TRAIN*HID];
__device__ __half g_H1[M_TRAIN*HID];
__device__ __half g_Xtr[M_TRAIN*DIN];
__device__ __half g_W1[HID*DIN];
__device__ __half g_W2[HID*HID];
__device__ __half g_Xte[M_TEST*DIN];
__device__ __half g_SW[SW_ROWS];
__device__ float  g_part[64*HID];
__device__ float  g_ctx[HID];
__device__ float  g_sb[NSPLIT];
__device__ float  g_lf[LF_ROWS];
__device__ float  g_tw[NTREES];
__device__ float  g_W[LF_ROWS];
__device__ float  g_dec[NSPLIT*M_TEST];      /* TRANSPOSED [496][16384] */

/* ------------------------------ PTX helpers ------------------------------ */
__device__ __forceinline__ uint32_t cvta_sm(const void* p) {
    return (uint32_t)__cvta_generic_to_shared(p);
}
__device__ __forceinline__ void cp16(uint32_t dst, const void* src, int sz) {
    asm volatile("cp.async.cg.shared.global [%0], [%1], 16, %2;\n"
                 :: "r"(dst), "l"(src), "r"(sz));
}
__device__ __forceinline__ void cp_commit() {
    asm volatile("cp.async.commit_group;\n");
}
__device__ __forceinline__ void ldsm4(unsigned& r0, unsigned& r1,
                                      unsigned& r2, unsigned& r3, uint32_t a) {
    asm volatile("ldmatrix.sync.aligned.m8n8.x4.shared.b16 {%0,%1,%2,%3}, [%4];"
                 : "=r"(r0), "=r"(r1), "=r"(r2), "=r"(r3) : "r"(a));
}
__device__ __forceinline__ void mma_f16(float c[4], unsigned a0, unsigned a1,
                                        unsigned a2, unsigned a3,
                                        unsigned b0, unsigned b1)
{
    asm volatile(
        "mma.sync.aligned.m16n8k16.row.col.f32.f16.f16.f32 "
        "{%0,%1,%2,%3}, {%4,%5,%6,%7}, {%8,%9}, {%0,%1,%2,%3};"
        : "+f"(c[0]), "+f"(c[1]), "+f"(c[2]), "+f"(c[3])
        : "r"(a0), "r"(a1), "r"(a2), "r"(a3), "r"(b0), "r"(b1));
}
/* swizzled byte offset inside a (rows x 32) half tile, 64B rows */
__device__ __forceinline__ uint32_t swz(int r, int hb) {
    return (uint32_t)(r*64 + ((hb ^ ((r>>1)&3)) << 4));
}

/* ---------- ONE launch: convert all static inputs to fp16 ---------------- */
__global__ void cvt_all(const float* __restrict__ xtr, const float* __restrict__ w1,
                        const float* __restrict__ w2,  const float* __restrict__ xte,
                        __half* __restrict__ xtrh, __half* __restrict__ w1h,
                        __half* __restrict__ w2h,  __half* __restrict__ xteh)
{
    int b = blockIdx.x;
    const float* src;
    __half* dst;
    int base;
    if (b < 128)      { src = xtr; dst = xtrh; base = b; }
    else if (b < 160) { src = w1;  dst = w1h;  base = b - 128; }
    else if (b < 416) { src = w2;  dst = w2h;  base = b - 160; }
    else              { src = xte; dst = xteh; base = b - 416; }

    int i0 = base * 1024 + threadIdx.x;
    float4 v[4];
#pragma unroll
    for (int u = 0; u < 4; u++) v[u] = ((const float4*)src)[i0 + u*256];
#pragma unroll
    for (int u = 0; u < 4; u++) {
        int i = i0 + u*256;
        ((__half2*)dst)[i*2]   = __halves2half2(__float2half_rn(v[u].x),
                                                __float2half_rn(v[u].y));
        ((__half2*)dst)[i*2+1] = __halves2half2(__float2half_rn(v[u].z),
                                                __float2half_rn(v[u].w));
    }
}

/* ---- 128x128 fp16 single-term GEMM: C = A @ B^T + bias ------------------ */
/* BK=32, 3-stage cp.async, occ 2, one sync per iteration.                   */
/* Stage 16KB: A@0 (8K), B@8K (8K).                                          */
#define GSTAGE 16384
#define GNSTG  3

template<int EPI>
__global__ void __launch_bounds__(256, 2) gemm128(
    const __half* __restrict__ Ah, const __half* __restrict__ Bh,
    const float* __restrict__ bias, float* __restrict__ C,
    int M, int N, int K)
{
    extern __shared__ char dynsm[];
    const uint32_t smem = cvta_sm(dynsm);
    const int tid = threadIdx.x, lane = tid & 31, warp = tid >> 5;
    const int g = lane >> 2, t = lane & 3;
    const int wm = warp & 1, wn = warp >> 1;
    const int m0 = blockIdx.y * 128, n0 = blockIdx.x * 128;

    float c[4][4][4];
#pragma unroll
    for (int i = 0; i < 4; i++)
#pragma unroll
        for (int j = 0; j < 4; j++)
#pragma unroll
            for (int r = 0; r < 4; r++) c[i][j][r] = 0.f;

    const int kIters = K >> 5;

    auto load_stage = [&](int buf, int k0) {
        uint32_t sb = smem + buf * GSTAGE;
#pragma unroll
        for (int x = 0; x < 2; x++) {
            int ch = tid + x*256;
            int r = ch >> 2, hb = ch & 3;
            uint32_t so = swz(r, hb);
            cp16(sb + so, Ah + (size_t)(m0 + r) * K + k0 + hb*8, 16);
            int bn = n0 + r;
            int sz = (bn < N) ? 16 : 0;
            size_t gb = (size_t)(sz ? bn : 0) * K + k0 + hb*8;
            cp16(sb + 8192 + so, Bh + gb, sz);
        }
    };

    auto compute = [&](int buf) {
        uint32_t sb = smem + buf * GSTAGE;
        const int rl = lane & 15;
        const int hx = lane >> 4;
#pragma unroll
        for (int s = 0; s < 2; s++) {
            const int hb = s*2 + hx;
            unsigned bf[4][2];
#pragma unroll
            for (int j2 = 0; j2 < 2; j2++) {
                int row = wn*32 + j2*16 + rl;
                unsigned r0, r1, r2, r3;
                ldsm4(r0, r1, r2, r3, sb + 8192 + swz(row, hb));
                bf[j2*2][0]=r0; bf[j2*2][1]=r2; bf[j2*2+1][0]=r1; bf[j2*2+1][1]=r3;
            }
#pragma unroll
            for (int i = 0; i < 4; i++) {
                int row = wm*64 + i*16 + rl;
                unsigned a0,a1,a2,a3;
                ldsm4(a0,a1,a2,a3, sb + swz(row, hb));
#pragma unroll
                for (int j = 0; j < 4; j++)
                    mma_f16(c[i][j], a0,a1,a2,a3, bf[j][0], bf[j][1]);
            }
        }
    };

    load_stage(0, 0);
    cp_commit();
    load_stage(1, 32);
    cp_commit();
    for (int it = 0; it < kIters; it++) {
        if (it + 1 < kIters)
            asm volatile("cp.async.wait_group 1;\n" ::: "memory");
        else
            asm volatile("cp.async.wait_group 0;\n" ::: "memory");
        __syncthreads();
        compute(it % GNSTG);
        /* no second sync: load targets (it+2)%3, disjoint from read buf */
        if (it + 2 < kIters) {
            load_stage((it+2) % GNSTG, (it+2)*32);
            cp_commit();
        }
    }

    if (EPI == 0) {
#pragma unroll
        for (int i = 0; i < 4; i++) {
            int r0 = m0 + wm*64 + i*16 + g;
#pragma unroll
            for (int j = 0; j < 4; j++) {
                int col = n0 + wn*32 + j*8 + 2*t;
                float b0 = bias[col], b1 = bias[col+1];
                float2 v0 = make_float2(c[i][j][0] + b0, c[i][j][1] + b1);
                float2 v1 = make_float2(c[i][j][2] + b0, c[i][j][3] + b1);
                *(float2*)&C[(size_t)r0     * N + col] = v0;
                *(float2*)&C[(size_t)(r0+8) * N + col] = v1;
            }
        }
    } else {
        float (*trans)[132] = reinterpret_cast<float(*)[132]>(dynsm);
#pragma unroll
        for (int chunk = 0; chunk < 4; chunk++) {
            __syncthreads();
            if (wn == chunk) {
#pragma unroll
                for (int i = 0; i < 4; i++) {
                    int mm = wm*64 + i*16 + g;
#pragma unroll
                    for (int j = 0; j < 4; j++) {
                        int nn  = j*8 + 2*t;
                        int col = n0 + chunk*32 + nn;
                        float b0 = (col     < N) ? bias[col]   : 0.f;
                        float b1 = (col + 1 < N) ? bias[col+1] : 0.f;
                        float v0 = c[i][j][0] + b0, v1 = c[i][j][1] + b1;
                        float v2 = c[i][j][2] + b0, v3 = c[i][j][3] + b1;
                        trans[nn  ][mm  ] = 1.f / (1.f + __expf(-v0));
                        trans[nn+1][mm  ] = 1.f / (1.f + __expf(-v1));
                        trans[nn  ][mm+8] = 1.f / (1.f + __expf(-v2));
                        trans[nn+1][mm+8] = 1.f / (1.f + __expf(-v3));
                    }
                }
            }
            __syncthreads();
#pragma unroll
            for (int p = 0; p < 4; p++) {
                int idx  = tid + p*256;
                int rowb = idx >> 5;
                int mc   = (idx & 31) * 4;
                int ngl  = n0 + chunk*32 + rowb;
                if (ngl < N)
                    *(float4*)&C[(size_t)ngl * M_TEST + m0 + mc] =
                        *(float4*)&trans[rowb][mc];
            }
        }
    }
}

/* ------------- LayerNorm + ReLU; HALF=1 emits fp16 ----------------------- */
template<int HALF>
__global__ void ln_relu(const float* __restrict__ X, float* __restrict__ Y,
                        __half* __restrict__ Yh,
                        const float* __restrict__ gg, const float* __restrict__ bb)
{
    const int row = blockIdx.x, tid = threadIdx.x;
    const float4 v = ((const float4*)(X + (size_t)row * HID))[tid];
    float s = v.x + v.y + v.z + v.w;
    float q = v.x*v.x + v.y*v.y + v.z*v.z + v.w*v.w;
#pragma unroll
    for (int o = 16; o; o >>= 1) {
        s += __shfl_xor_sync(0xffffffffu, s, o);
        q += __shfl_xor_sync(0xffffffffu, q, o);
    }
    __shared__ float ss[8], qs[8];
    if ((tid & 31) == 0) { ss[tid >> 5] = s; qs[tid >> 5] = q; }
    __syncthreads();
    s = ss[0]+ss[1]+ss[2]+ss[3]+ss[4]+ss[5]+ss[6]+ss[7];
    q = qs[0]+qs[1]+qs[2]+qs[3]+qs[4]+qs[5]+qs[6]+qs[7];
    float mean = s * (1.f/HID);
    float inv  = rsqrtf(q * (1.f/HID) - mean*mean + 1e-5f);
    float4 gv = ((const float4*)gg)[tid];
    float4 bv = ((const float4*)bb)[tid];
    float4 y;
    y.x = fmaxf((v.x - mean)*inv*gv.x + bv.x, 0.f);
    y.y = fmaxf((v.y - mean)*inv*gv.y + bv.y, 0.f);
    y.z = fmaxf((v.z - mean)*inv*gv.z + bv.z, 0.f);
    y.w = fmaxf((v.w - mean)*inv*gv.w + bv.w, 0.f);
    if (HALF) {
        __half2* ph = (__half2*)(Yh + (size_t)row * HID);
        ph[tid*2]   = __halves2half2(__float2half_rn(y.x), __float2half_rn(y.y));
        ph[tid*2+1] = __halves2half2(__float2half_rn(y.z), __float2half_rn(y.w));
    } else {
        ((float4*)(Y + (size_t)row * HID))[tid] = y;
    }
}

/* --------------------- column mean over rows -> ctx ---------------------- */
__global__ void col_partial(const float* __restrict__ X, float* __restrict__ part)
{
    int col   = blockIdx.x * 256 + threadIdx.x;
    int chunk = blockIdx.y;
    float s = 0.f;
    int r0 = chunk * 64;
    for (int r = r0; r < r0 + 64; r++) s += X[(size_t)r * HID + col];
    part[(size_t)chunk * HID + col] = s;
}
__global__ void col_final(const float* __restrict__ part, float* __restrict__ ctx)
{
    int col = blockIdx.x * 256 + threadIdx.x;
    float s = 0.f;
    for (int c = 0; c < 64; c++) s += part[(size_t)c * HID + col];
    ctx[col] = s * (1.f / M_TRAIN);
}

/* ---------- ONE launch: all hypernet matvecs (warp-id dispatch) ----------- */
__global__ void matvec_all(const float* __restrict__ sw_w, const float* __restrict__ sw_b,
                           const float* __restrict__ sb_w, const float* __restrict__ sb_b,
                           const float* __restrict__ lf_w, const float* __restrict__ lf_b,
                           const float* __restrict__ tw_w, const float* __restrict__ tw_b,
                           const float* __restrict__ ctx,
                           __half* __restrict__ swh,
                           float* __restrict__ sbo, float* __restrict__ lfo,
                           float* __restrict__ two)
{
    int gw   = (blockIdx.x * blockDim.x + threadIdx.x) >> 5;
    int lane = threadIdx.x & 31;
    if (gw >= MV_ROWS) return;
    const float *W, *bias;
    int row, mode;
    if (gw < SW_ROWS)                  { W=sw_w; bias=sw_b; row=gw;                    mode=0; }
    else if (gw < SW_ROWS+NSPLIT)      { W=sb_w; bias=sb_b; row=gw-SW_ROWS;            mode=1; }
    else if (gw < SW_ROWS+NSPLIT+LF_ROWS) { W=lf_w; bias=lf_b; row=gw-SW_ROWS-NSPLIT;  mode=2; }
    else                               { W=tw_w; bias=tw_b; row=gw-SW_ROWS-NSPLIT-LF_ROWS; mode=3; }

    const float4* w4 = (const float4*)(W + (size_t)row * HID);
    const float4* c4 = (const float4*)ctx;
    float s = 0.f;
#pragma unroll
    for (int i = 0; i < 8; i++) {
        float4 a = w4[lane + 32*i];
        float4 c = __ldg(&c4[lane + 32*i]);
        s += a.x*c.x + a.y*c.y + a.z*c.z + a.w*c.w;
    }
#pragma unroll
    for (int o = 16; o; o >>= 1) s += __shfl_xor_sync(0xffffffffu, s, o);
    if (lane == 0) {
        float v = s + bias[row];
        if (mode == 0)      swh[row] = __float2half_rn(v);
        else if (mode == 1) sbo[row] = v;
        else if (mode == 2) lfo[row] = v;
        else                two[row] = v;
    }
}

/* ---- fold tree_w softmax + leaf softmax into one table W[t,l,c] --------- */
__global__ void make_W(const float* __restrict__ tw, const float* __restrict__ lf,
                       float* __restrict__ Wout)
{
    __shared__ float tws[NTREES];
    int tid = threadIdx.x;
    if (tid == 0) {
        float mx = -1e30f;
        for (int i = 0; i < NTREES; i++) mx = fmaxf(mx, tw[i]);
        float e[NTREES], s = 0.f;
        for (int i = 0; i < NTREES; i++) { e[i] = expf(tw[i] - mx); s += e[i]; }
        for (int i = 0; i < NTREES; i++) tws[i] = e[i] / s;
    }
    __syncthreads();
    if (tid < NTREES * NLEAF) {
        const float* L = lf + tid * NCLS;
        float mx = -1e30f;
        for (int c = 0; c < NCLS; c++) mx = fmaxf(mx, L[c]);
        float e[NCLS], s = 0.f;
        for (int c = 0; c < NCLS; c++) { e[c] = expf(L[c] - mx); s += e[c]; }
        float scale = tws[tid >> 5] / s;
        for (int c = 0; c < NCLS; c++) Wout[tid * NCLS + c] = e[c] * scale;
    }
}

/* ------------- soft tree routing + class combine, thread per row --------- */
__global__ void route_kernel(const float* __restrict__ dec, const float* __restrict__ W,
                             float* __restrict__ out)
{
    __shared__ float Ws[LF_ROWS];
    int tid = threadIdx.x;
    for (int i = tid; i < LF_ROWS; i += 256) Ws[i] = W[i];
    __syncthreads();
    int b = blockIdx.x * 256 + tid;
    float acc[NCLS];
#pragma unroll
    for (int c = 0; c < NCLS; c++) acc[c] = 0.f;

    for (int t = 0; t < NTREES; t++) {
        float d[NINT];
#pragma unroll
        for (int n = 0; n < NINT; n++)
            d[n] = dec[(size_t)(t*NINT + n) * M_TEST + b];
#pragma unroll
        for (int l = 0; l < NLEAF; l++) {
            float p = 1.f;
#pragma unroll
            for (int dd = 0; dd < 5; dd++) {
                int node = (1 << dd) - 1 + (l >> (5 - dd));
                int go   = (l >> (4 - dd)) & 1;
                p *= go ? d[node] : (1.f - d[node]);
            }
            const float* w = &Ws[(t*NLEAF + l) * NCLS];
#pragma unroll
            for (int c = 0; c < NCLS; c++) acc[c] += p * w[c];
        }
    }
#pragma unroll
    for (int c = 0; c < NCLS; c++) out[(size_t)b * NCLS + c] = acc[c];
}

/* ------------------------------- launch ---------------------------------- */
extern "C" void kernel_launch(void* const* d_in, const int* in_sizes, int n_in,
                              void* d_out, int out_size)
{
    const float* X_train = (const float*)d_in[0];
    const float* X_test  = (const float*)d_in[1];
    const float* enc_w1  = (const float*)d_in[2];
    const float* enc_b1  = (const float*)d_in[3];
    const float* ln1_g   = (const float*)d_in[4];
    const float* ln1_b   = (const float*)d_in[5];
    const float* enc_w2  = (const float*)d_in[6];
    const float* enc_b2  = (const float*)d_in[7];
    const float* ln2_g   = (const float*)d_in[8];
    const float* ln2_b   = (const float*)d_in[9];
    const float* sw_w    = (const float*)d_in[10];
    const float* sw_b    = (const float*)d_in[11];
    const float* sb_w    = (const float*)d_in[12];
    const float* sb_b    = (const float*)d_in[13];
    const float* lf_w    = (const float*)d_in[14];
    const float* lf_b    = (const float*)d_in[15];
    const float* tw_w    = (const float*)d_in[16];
    const float* tw_b    = (const float*)d_in[17];

    float *C1, *C2, *part, *ctx, *sb, *lf, *tw, *W, *dec;
    __half *H1, *Xtr, *W1, *W2, *Xte, *SW;
    cudaGetSymbolAddress((void**)&C1,   g_C1);
    cudaGetSymbolAddress((void**)&C2,   g_C2);
    cudaGetSymbolAddress((void**)&H1,   g_H1);
    cudaGetSymbolAddress((void**)&Xtr,  g_Xtr);
    cudaGetSymbolAddress((void**)&W1,   g_W1);
    cudaGetSymbolAddress((void**)&W2,   g_W2);
    cudaGetSymbolAddress((void**)&Xte,  g_Xte);
    cudaGetSymbolAddress((void**)&SW,   g_SW);
    cudaGetSymbolAddress((void**)&part, g_part);
    cudaGetSymbolAddress((void**)&ctx,  g_ctx);
    cudaGetSymbolAddress((void**)&sb,   g_sb);
    cudaGetSymbolAddress((void**)&lf,   g_lf);
    cudaGetSymbolAddress((void**)&tw,   g_tw);
    cudaGetSymbolAddress((void**)&W,    g_W);
    cudaGetSymbolAddress((void**)&dec,  g_dec);

    cudaFuncSetAttribute((const void*)gemm128<0>,
                         cudaFuncAttributeMaxDynamicSharedMemorySize, GNSTG*GSTAGE);
    cudaFuncSetAttribute((const void*)gemm128<1>,
                         cudaFuncAttributeMaxDynamicSharedMemorySize, GNSTG*GSTAGE);

    /* one launch: convert everything to fp16 */
    cvt_all<<<928, 256>>>(X_train, enc_w1, enc_w2, X_test, Xtr, W1, W2, Xte);

    /* encoder: single-term fp16 GEMMs */
    gemm128<0><<<dim3(HID/128, M_TRAIN/128), 256, GNSTG*GSTAGE>>>(
        Xtr, W1, enc_b1, C1, M_TRAIN, HID, DIN);
    ln_relu<1><<<M_TRAIN, 256>>>(C1, nullptr, H1, ln1_g, ln1_b);
    gemm128<0><<<dim3(HID/128, M_TRAIN/128), 256, GNSTG*GSTAGE>>>(
        H1, W2, enc_b2, C2, M_TRAIN, HID, HID);
    ln_relu<0><<<M_TRAIN, 256>>>(C2, C2, nullptr, ln2_g, ln2_b);

    /* ctx = mean over rows */
    col_partial<<<dim3(HID/256, 64), 256>>>(C2, part);
    col_final<<<HID/256, 256>>>(part, ctx);

    /* ALL hypernet matvecs in one launch (sw emits fp16 directly) */
    matvec_all<<<(MV_ROWS*32 + 255)/256, 256>>>(
        sw_w, sw_b, sb_w, sb_b, lf_w, lf_b, tw_w, tw_b, ctx,
        SW, sb, lf, tw);

    /* dec = sigmoid(X_test @ split_w^T + sb), fp16 single-term, transposed */
    gemm128<1><<<dim3((NSPLIT + 127)/128, M_TEST/128), 256, GNSTG*GSTAGE>>>(
        Xte, SW, sb, dec, M_TEST, NSPLIT, DIN);

    /* fold softmaxes, then route */
    make_W<<<1, 512>>>(tw, lf, W);
    route_kernel<<<M_TEST/256, 256>>>(dec, W, (float*)d_out);
}

// round 13
// speedup vs baseline: 3.1017x; 1.3973x over previous
#include <cuda_runtime.h>
#include <cuda_fp16.h>
#include <math.h>
#include <stdint.h>

#define M_TRAIN 4096
#define M_TEST  16384
#define DIN     128
#define HID     1024
#define NTREES  16
#define NINT    31
#define NLEAF   32
#define NCLS    10
#define NSPLIT  (NTREES*NINT)        /* 496 */
#define SW_ROWS (NTREES*NINT*DIN)    /* 63488 */
#define LF_ROWS (NTREES*NLEAF*NCLS)  /* 5120 */
#define MV_ROWS (SW_ROWS + NSPLIT + LF_ROWS + NTREES)  /* 69120 */

/* ---------------- scratch (static device memory; no allocs) -------------- */
__device__ float  g_C1[M_TRAIN*HID];
__device__ float  g_C2[M_TRAIN*HID];
__device__ __half g_H1[M_TRAIN*HID];
__device__ __half g_Xtr[M_TRAIN*DIN];
__device__ __half g_W1[HID*DIN];
__device__ __half g_W2[HID*HID];
__device__ __half g_Xte[M_TEST*DIN];
__device__ __half g_SW[SW_ROWS];
__device__ float  g_part[64*HID];
__device__ float  g_ctx[HID];
__device__ float  g_sb[NSPLIT];
__device__ float  g_lf[LF_ROWS];
__device__ float  g_tw[NTREES];
__device__ float  g_W[LF_ROWS];

/* ------------------------------ PTX helpers ------------------------------ */
__device__ __forceinline__ uint32_t cvta_sm(const void* p) {
    return (uint32_t)__cvta_generic_to_shared(p);
}
__device__ __forceinline__ void cp16(uint32_t dst, const void* src, int sz) {
    asm volatile("cp.async.cg.shared.global [%0], [%1], 16, %2;\n"
                 :: "r"(dst), "l"(src), "r"(sz));
}
__device__ __forceinline__ void cp_commit() {
    asm volatile("cp.async.commit_group;\n");
}
__device__ __forceinline__ void ldsm4(unsigned& r0, unsigned& r1,
                                      unsigned& r2, unsigned& r3, uint32_t a) {
    asm volatile("ldmatrix.sync.aligned.m8n8.x4.shared.b16 {%0,%1,%2,%3}, [%4];"
                 : "=r"(r0), "=r"(r1), "=r"(r2), "=r"(r3) : "r"(a));
}
__device__ __forceinline__ void mma_f16(float c[4], unsigned a0, unsigned a1,
                                        unsigned a2, unsigned a3,
                                        unsigned b0, unsigned b1)
{
    asm volatile(
        "mma.sync.aligned.m16n8k16.row.col.f32.f16.f16.f32 "
        "{%0,%1,%2,%3}, {%4,%5,%6,%7}, {%8,%9}, {%0,%1,%2,%3};"
        : "+f"(c[0]), "+f"(c[1]), "+f"(c[2]), "+f"(c[3])
        : "r"(a0), "r"(a1), "r"(a2), "r"(a3), "r"(b0), "r"(b1));
}
/* swizzled byte offset inside a (rows x 32) half tile, 64B rows */
__device__ __forceinline__ uint32_t swz(int r, int hb) {
    return (uint32_t)(r*64 + ((hb ^ ((r>>1)&3)) << 4));
}

/* ---------- ONE launch: convert all static inputs to fp16 ---------------- */
__global__ void cvt_all(const float* __restrict__ xtr, const float* __restrict__ w1,
                        const float* __restrict__ w2,  const float* __restrict__ xte,
                        __half* __restrict__ xtrh, __half* __restrict__ w1h,
                        __half* __restrict__ w2h,  __half* __restrict__ xteh)
{
    int b = blockIdx.x;
    const float* src;
    __half* dst;
    int base;
    if (b < 128)      { src = xtr; dst = xtrh; base = b; }
    else if (b < 160) { src = w1;  dst = w1h;  base = b - 128; }
    else if (b < 416) { src = w2;  dst = w2h;  base = b - 160; }
    else              { src = xte; dst = xteh; base = b - 416; }

    int i0 = base * 1024 + threadIdx.x;
    float4 v[4];
#pragma unroll
    for (int u = 0; u < 4; u++) v[u] = ((const float4*)src)[i0 + u*256];
#pragma unroll
    for (int u = 0; u < 4; u++) {
        int i = i0 + u*256;
        ((__half2*)dst)[i*2]   = __halves2half2(__float2half_rn(v[u].x),
                                                __float2half_rn(v[u].y));
        ((__half2*)dst)[i*2+1] = __halves2half2(__float2half_rn(v[u].z),
                                                __float2half_rn(v[u].w));
    }
}

/* ---- 128x128 fp16 GEMM: C = A @ B^T + bias (encoder) -------------------- */
#define GSTAGE 16384
#define GNSTG  3

__global__ void __launch_bounds__(256, 2) gemm128(
    const __half* __restrict__ Ah, const __half* __restrict__ Bh,
    const float* __restrict__ bias, float* __restrict__ C,
    int M, int N, int K)
{
    extern __shared__ char dynsm[];
    const uint32_t smem = cvta_sm(dynsm);
    const int tid = threadIdx.x, lane = tid & 31, warp = tid >> 5;
    const int g = lane >> 2, t = lane & 3;
    const int wm = warp & 1, wn = warp >> 1;
    const int m0 = blockIdx.y * 128, n0 = blockIdx.x * 128;

    float c[4][4][4];
#pragma unroll
    for (int i = 0; i < 4; i++)
#pragma unroll
        for (int j = 0; j < 4; j++)
#pragma unroll
            for (int r = 0; r < 4; r++) c[i][j][r] = 0.f;

    const int kIters = K >> 5;

    auto load_stage = [&](int buf, int k0) {
        uint32_t sb = smem + buf * GSTAGE;
#pragma unroll
        for (int x = 0; x < 2; x++) {
            int ch = tid + x*256;
            int r = ch >> 2, hb = ch & 3;
            uint32_t so = swz(r, hb);
            cp16(sb + so,        Ah + (size_t)(m0 + r) * K + k0 + hb*8, 16);
            cp16(sb + 8192 + so, Bh + (size_t)(n0 + r) * K + k0 + hb*8, 16);
        }
    };

    auto compute = [&](int buf) {
        uint32_t sb = smem + buf * GSTAGE;
        const int rl = lane & 15;
        const int hx = lane >> 4;
#pragma unroll
        for (int s = 0; s < 2; s++) {
            const int hb = s*2 + hx;
            unsigned bf[4][2];
#pragma unroll
            for (int j2 = 0; j2 < 2; j2++) {
                int row = wn*32 + j2*16 + rl;
                unsigned r0, r1, r2, r3;
                ldsm4(r0, r1, r2, r3, sb + 8192 + swz(row, hb));
                bf[j2*2][0]=r0; bf[j2*2][1]=r2; bf[j2*2+1][0]=r1; bf[j2*2+1][1]=r3;
            }
#pragma unroll
            for (int i = 0; i < 4; i++) {
                int row = wm*64 + i*16 + rl;
                unsigned a0,a1,a2,a3;
                ldsm4(a0,a1,a2,a3, sb + swz(row, hb));
#pragma unroll
                for (int j = 0; j < 4; j++)
                    mma_f16(c[i][j], a0,a1,a2,a3, bf[j][0], bf[j][1]);
            }
        }
    };

    load_stage(0, 0);
    cp_commit();
    load_stage(1, 32);
    cp_commit();
    for (int it = 0; it < kIters; it++) {
        if (it + 1 < kIters)
            asm volatile("cp.async.wait_group 1;\n" ::: "memory");
        else
            asm volatile("cp.async.wait_group 0;\n" ::: "memory");
        __syncthreads();
        compute(it % GNSTG);
        if (it + 2 < kIters) {
            load_stage((it+2) % GNSTG, (it+2)*32);
            cp_commit();
        }
    }

#pragma unroll
    for (int i = 0; i < 4; i++) {
        int r0 = m0 + wm*64 + i*16 + g;
#pragma unroll
        for (int j = 0; j < 4; j++) {
            int col = n0 + wn*32 + j*8 + 2*t;
            float b0 = bias[col], b1 = bias[col+1];
            float2 v0 = make_float2(c[i][j][0] + b0, c[i][j][1] + b1);
            float2 v1 = make_float2(c[i][j][2] + b0, c[i][j][3] + b1);
            *(float2*)&C[(size_t)r0     * N + col] = v0;
            *(float2*)&C[(size_t)(r0+8) * N + col] = v1;
        }
    }
}

/* ==== FUSED dec GEMM + sigmoid + tree routing + class combine ============ */
/* CTA: 64 test rows x 512 node-cols (496 real). 512 threads (4m x 4n warps).*/
#define DR_STAGE   36864                 /* A 4K + B 32K */
#define DR_SMEM    192768
#define TR_PITCH   513

__global__ void __launch_bounds__(512, 1) dec_route(
    const __half* __restrict__ Xte, const __half* __restrict__ SW,
    const float* __restrict__ sbias, const float* __restrict__ Wtab,
    float* __restrict__ out)
{
    extern __shared__ char dynsm[];
    const uint32_t smem = cvta_sm(dynsm);
    float* trans = (float*)dynsm;                     /* [64][513] */
    float* Wsh   = (float*)(dynsm + 131328);          /* [5120]    */
    float* pt    = (float*)(dynsm + 151808);          /* [64][16][10] */

    const int tid = threadIdx.x, lane = tid & 31, warp = tid >> 5;
    const int g = lane >> 2, t4 = lane & 3;
    const int wm = warp & 3, wn = warp >> 2;
    const int m0 = blockIdx.x * 64;

    /* W table -> smem (region disjoint from stages) */
    for (int i = tid; i < LF_ROWS; i += 512) Wsh[i] = Wtab[i];

    float c[16][4];
#pragma unroll
    for (int j = 0; j < 16; j++)
#pragma unroll
        for (int r = 0; r < 4; r++) c[j][r] = 0.f;

    auto load_stage = [&](int buf, int k0) {
        uint32_t sb = smem + buf * DR_STAGE;
        if (tid < 256) {
            int r = tid >> 2, hb = tid & 3;
            cp16(sb + swz(r, hb), Xte + (size_t)(m0 + r) * DIN + k0 + hb*8, 16);
        }
#pragma unroll
        for (int x = 0; x < 4; x++) {
            int ch = tid + x*512;
            int r = ch >> 2, hb = ch & 3;
            int sz = (r < NSPLIT) ? 16 : 0;
            size_t gb = (size_t)(sz ? r : 0) * DIN + k0 + hb*8;
            cp16(sb + 4096 + swz(r, hb), SW + gb, sz);
        }
    };

    auto compute = [&](int buf) {
        uint32_t sb = smem + buf * DR_STAGE;
        const int rl = lane & 15, hx = lane >> 4;
#pragma unroll
        for (int s = 0; s < 2; s++) {
            const int hb = s*2 + hx;
            unsigned a0,a1,a2,a3;
            {
                int row = wm*16 + rl;
                ldsm4(a0,a1,a2,a3, sb + swz(row, hb));
            }
#pragma unroll
            for (int h2 = 0; h2 < 2; h2++) {
                unsigned bf[8][2];
#pragma unroll
                for (int j2 = 0; j2 < 4; j2++) {
                    int row = wn*128 + h2*64 + j2*16 + rl;
                    unsigned r0,r1,r2,r3;
                    ldsm4(r0,r1,r2,r3, sb + 4096 + swz(row, hb));
                    bf[j2*2][0]=r0; bf[j2*2][1]=r2;
                    bf[j2*2+1][0]=r1; bf[j2*2+1][1]=r3;
                }
#pragma unroll
                for (int j = 0; j < 8; j++)
                    mma_f16(c[h2*8+j], a0,a1,a2,a3, bf[j][0], bf[j][1]);
            }
        }
    };

    const int kIters = DIN >> 5;   /* 4 */
    load_stage(0, 0);
    cp_commit();
    load_stage(1, 32);
    cp_commit();
    for (int it = 0; it < kIters; it++) {
        if (it + 1 < kIters)
            asm volatile("cp.async.wait_group 1;\n" ::: "memory");
        else
            asm volatile("cp.async.wait_group 0;\n" ::: "memory");
        __syncthreads();
        compute(it % 3);
        if (it + 2 < kIters) {
            load_stage((it+2) % 3, (it+2)*32);
            cp_commit();
        }
    }

    /* all warps done with stage smem before trans overwrites it */
    __syncthreads();

    /* sigmoid + stage to trans[row][col] */
    {
        int r0 = wm*16 + g, r1 = r0 + 8;
#pragma unroll
        for (int j = 0; j < 16; j++) {
            int col = wn*128 + j*8 + 2*t4;
            float b0 = (col     < NSPLIT) ? sbias[col]   : 0.f;
            float b1 = (col + 1 < NSPLIT) ? sbias[col+1] : 0.f;
            trans[r0*TR_PITCH + col]   = 1.f/(1.f + __expf(-(c[j][0] + b0)));
            trans[r0*TR_PITCH + col+1] = 1.f/(1.f + __expf(-(c[j][1] + b1)));
            trans[r1*TR_PITCH + col]   = 1.f/(1.f + __expf(-(c[j][2] + b0)));
            trans[r1*TR_PITCH + col+1] = 1.f/(1.f + __expf(-(c[j][3] + b1)));
        }
    }
    __syncthreads();

    /* routing: items (row, tree); 1024 items over 512 threads */
#pragma unroll
    for (int it2 = 0; it2 < 2; it2++) {
        int idx = tid + it2*512;
        int r = idx & 63, t = idx >> 6;
        const float* d = &trans[r*TR_PITCH + t*NINT];
        float acc[NCLS];
#pragma unroll
        for (int cc = 0; cc < NCLS; cc++) acc[cc] = 0.f;
#pragma unroll
        for (int l = 0; l < NLEAF; l++) {
            float p = 1.f;
#pragma unroll
            for (int dd = 0; dd < 5; dd++) {
                int node = (1 << dd) - 1 + (l >> (5 - dd));
                int go   = (l >> (4 - dd)) & 1;
                float dv = d[node];
                p *= go ? dv : (1.f - dv);
            }
            const float* w = &Wsh[(t*NLEAF + l)*NCLS];
#pragma unroll
            for (int cc = 0; cc < NCLS; cc++) acc[cc] += p * w[cc];
        }
#pragma unroll
        for (int cc = 0; cc < NCLS; cc++) pt[(r*16 + t)*NCLS + cc] = acc[cc];
    }
    __syncthreads();

    /* deterministic per-row reduction over 16 trees, write output.
       640 items over 512 threads: FIXED stride loop (was `if (tid < 640)`). */
    for (int idx = tid; idx < 64*NCLS; idx += 512) {
        int r = idx / NCLS, cc = idx % NCLS;
        float s = 0.f;
#pragma unroll
        for (int t = 0; t < 16; t++) s += pt[(r*16 + t)*NCLS + cc];
        out[(size_t)(m0 + r)*NCLS + cc] = s;
    }
}

/* ------------- LayerNorm + ReLU; HALF=1 emits fp16 ----------------------- */
template<int HALF>
__global__ void ln_relu(const float* __restrict__ X, float* __restrict__ Y,
                        __half* __restrict__ Yh,
                        const float* __restrict__ gg, const float* __restrict__ bb)
{
    const int row = blockIdx.x, tid = threadIdx.x;
    const float4 v = ((const float4*)(X + (size_t)row * HID))[tid];
    float s = v.x + v.y + v.z + v.w;
    float q = v.x*v.x + v.y*v.y + v.z*v.z + v.w*v.w;
#pragma unroll
    for (int o = 16; o; o >>= 1) {
        s += __shfl_xor_sync(0xffffffffu, s, o);
        q += __shfl_xor_sync(0xffffffffu, q, o);
    }
    __shared__ float ss[8], qs[8];
    if ((tid & 31) == 0) { ss[tid >> 5] = s; qs[tid >> 5] = q; }
    __syncthreads();
    s = ss[0]+ss[1]+ss[2]+ss[3]+ss[4]+ss[5]+ss[6]+ss[7];
    q = qs[0]+qs[1]+qs[2]+qs[3]+qs[4]+qs[5]+qs[6]+qs[7];
    float mean = s * (1.f/HID);
    float inv  = rsqrtf(q * (1.f/HID) - mean*mean + 1e-5f);
    float4 gv = ((const float4*)gg)[tid];
    float4 bv = ((const float4*)bb)[tid];
    float4 y;
    y.x = fmaxf((v.x - mean)*inv*gv.x + bv.x, 0.f);
    y.y = fmaxf((v.y - mean)*inv*gv.y + bv.y, 0.f);
    y.z = fmaxf((v.z - mean)*inv*gv.z + bv.z, 0.f);
    y.w = fmaxf((v.w - mean)*inv*gv.w + bv.w, 0.f);
    if (HALF) {
        __half2* ph = (__half2*)(Yh + (size_t)row * HID);
        ph[tid*2]   = __halves2half2(__float2half_rn(y.x), __float2half_rn(y.y));
        ph[tid*2+1] = __halves2half2(__float2half_rn(y.z), __float2half_rn(y.w));
    } else {
        ((float4*)(Y + (size_t)row * HID))[tid] = y;
    }
}

/* --------------------- column mean over rows -> ctx ---------------------- */
__global__ void col_partial(const float* __restrict__ X, float* __restrict__ part)
{
    int col   = blockIdx.x * 256 + threadIdx.x;
    int chunk = blockIdx.y;
    float s = 0.f;
    int r0 = chunk * 64;
    for (int r = r0; r < r0 + 64; r++) s += X[(size_t)r * HID + col];
    part[(size_t)chunk * HID + col] = s;
}
__global__ void col_final(const float* __restrict__ part, float* __restrict__ ctx)
{
    int col = blockIdx.x * 256 + threadIdx.x;
    float s = 0.f;
    for (int c = 0; c < 64; c++) s += part[(size_t)c * HID + col];
    ctx[col] = s * (1.f / M_TRAIN);
}

/* ---------- ONE launch: all hypernet matvecs (warp-id dispatch) ----------- */
__global__ void matvec_all(const float* __restrict__ sw_w, const float* __restrict__ sw_b,
                           const float* __restrict__ sb_w, const float* __restrict__ sb_b,
                           const float* __restrict__ lf_w, const float* __restrict__ lf_b,
                           const float* __restrict__ tw_w, const float* __restrict__ tw_b,
                           const float* __restrict__ ctx,
                           __half* __restrict__ swh,
                           float* __restrict__ sbo, float* __restrict__ lfo,
                           float* __restrict__ two)
{
    int gw   = (blockIdx.x * blockDim.x + threadIdx.x) >> 5;
    int lane = threadIdx.x & 31;
    if (gw >= MV_ROWS) return;
    const float *W, *bias;
    int row, mode;
    if (gw < SW_ROWS)                  { W=sw_w; bias=sw_b; row=gw;                    mode=0; }
    else if (gw < SW_ROWS+NSPLIT)      { W=sb_w; bias=sb_b; row=gw-SW_ROWS;            mode=1; }
    else if (gw < SW_ROWS+NSPLIT+LF_ROWS) { W=lf_w; bias=lf_b; row=gw-SW_ROWS-NSPLIT;  mode=2; }
    else                               { W=tw_w; bias=tw_b; row=gw-SW_ROWS-NSPLIT-LF_ROWS; mode=3; }

    const float4* w4 = (const float4*)(W + (size_t)row * HID);
    const float4* c4 = (const float4*)ctx;
    float s = 0.f;
#pragma unroll
    for (int i = 0; i < 8; i++) {
        float4 a = w4[lane + 32*i];
        float4 c = __ldg(&c4[lane + 32*i]);
        s += a.x*c.x + a.y*c.y + a.z*c.z + a.w*c.w;
    }
#pragma unroll
    for (int o = 16; o; o >>= 1) s += __shfl_xor_sync(0xffffffffu, s, o);
    if (lane == 0) {
        float v = s + bias[row];
        if (mode == 0)      swh[row] = __float2half_rn(v);
        else if (mode == 1) sbo[row] = v;
        else if (mode == 2) lfo[row] = v;
        else                two[row] = v;
    }
}

/* ---- fold tree_w softmax + leaf softmax into one table W[t,l,c] --------- */
__global__ void make_W(const float* __restrict__ tw, const float* __restrict__ lf,
                       float* __restrict__ Wout)
{
    __shared__ float tws[NTREES];
    int tid = threadIdx.x;
    if (tid == 0) {
        float mx = -1e30f;
        for (int i = 0; i < NTREES; i++) mx = fmaxf(mx, tw[i]);
        float e[NTREES], s = 0.f;
        for (int i = 0; i < NTREES; i++) { e[i] = expf(tw[i] - mx); s += e[i]; }
        for (int i = 0; i < NTREES; i++) tws[i] = e[i] / s;
    }
    __syncthreads();
    if (tid < NTREES * NLEAF) {
        const float* L = lf + tid * NCLS;
        float mx = -1e30f;
        for (int c = 0; c < NCLS; c++) mx = fmaxf(mx, L[c]);
        float e[NCLS], s = 0.f;
        for (int c = 0; c < NCLS; c++) { e[c] = expf(L[c] - mx); s += e[c]; }
        float scale = tws[tid >> 5] / s;
        for (int c = 0; c < NCLS; c++) Wout[tid * NCLS + c] = e[c] * scale;
    }
}

/* ------------------------------- launch ---------------------------------- */
extern "C" void kernel_launch(void* const* d_in, const int* in_sizes, int n_in,
                              void* d_out, int out_size)
{
    const float* X_train = (const float*)d_in[0];
    const float* X_test  = (const float*)d_in[1];
    const float* enc_w1  = (const float*)d_in[2];
    const float* enc_b1  = (const float*)d_in[3];
    const float* ln1_g   = (const float*)d_in[4];
    const float* ln1_b   = (const float*)d_in[5];
    const float* enc_w2  = (const float*)d_in[6];
    const float* enc_b2  = (const float*)d_in[7];
    const float* ln2_g   = (const float*)d_in[8];
    const float* ln2_b   = (const float*)d_in[9];
    const float* sw_w    = (const float*)d_in[10];
    const float* sw_b    = (const float*)d_in[11];
    const float* sb_w    = (const float*)d_in[12];
    const float* sb_b    = (const float*)d_in[13];
    const float* lf_w    = (const float*)d_in[14];
    const float* lf_b    = (const float*)d_in[15];
    const float* tw_w    = (const float*)d_in[16];
    const float* tw_b    = (const float*)d_in[17];

    float *C1, *C2, *part, *ctx, *sb, *lf, *tw, *W;
    __half *H1, *Xtr, *W1, *W2, *Xte, *SW;
    cudaGetSymbolAddress((void**)&C1,   g_C1);
    cudaGetSymbolAddress((void**)&C2,   g_C2);
    cudaGetSymbolAddress((void**)&H1,   g_H1);
    cudaGetSymbolAddress((void**)&Xtr,  g_Xtr);
    cudaGetSymbolAddress((void**)&W1,   g_W1);
    cudaGetSymbolAddress((void**)&W2,   g_W2);
    cudaGetSymbolAddress((void**)&Xte,  g_Xte);
    cudaGetSymbolAddress((void**)&SW,   g_SW);
    cudaGetSymbolAddress((void**)&part, g_part);
    cudaGetSymbolAddress((void**)&ctx,  g_ctx);
    cudaGetSymbolAddress((void**)&sb,   g_sb);
    cudaGetSymbolAddress((void**)&lf,   g_lf);
    cudaGetSymbolAddress((void**)&tw,   g_tw);
    cudaGetSymbolAddress((void**)&W,    g_W);

    cudaFuncSetAttribute((const void*)gemm128,
                         cudaFuncAttributeMaxDynamicSharedMemorySize, GNSTG*GSTAGE);
    cudaFuncSetAttribute((const void*)dec_route,
                         cudaFuncAttributeMaxDynamicSharedMemorySize, DR_SMEM);

    /* one launch: convert everything to fp16 */
    cvt_all<<<928, 256>>>(X_train, enc_w1, enc_w2, X_test, Xtr, W1, W2, Xte);

    /* encoder: single-term fp16 GEMMs */
    gemm128<<<dim3(HID/128, M_TRAIN/128), 256, GNSTG*GSTAGE>>>(
        Xtr, W1, enc_b1, C1, M_TRAIN, HID, DIN);
    ln_relu<1><<<M_TRAIN, 256>>>(C1, nullptr, H1, ln1_g, ln1_b);
    gemm128<<<dim3(HID/128, M_TRAIN/128), 256, GNSTG*GSTAGE>>>(
        H1, W2, enc_b2, C2, M_TRAIN, HID, HID);
    ln_relu<0><<<M_TRAIN, 256>>>(C2, C2, nullptr, ln2_g, ln2_b);

    /* ctx = mean over rows */
    col_partial<<<dim3(HID/256, 64), 256>>>(C2, part);
    col_final<<<HID/256, 256>>>(part, ctx);

    /* ALL hypernet matvecs in one launch (sw emits fp16 directly) */
    matvec_all<<<(MV_ROWS*32 + 255)/256, 256>>>(
        sw_w, sw_b, sb_w, sb_b, lf_w, lf_b, tw_w, tw_b, ctx,
        SW, sb, lf, tw);

    /* fold softmaxes */
    make_W<<<1, 512>>>(tw, lf, W);

    /* FUSED: dec GEMM + sigmoid + routing + class combine -> final output */
    dec_route<<<M_TEST/64, 512, DR_SMEM>>>(Xte, SW, sb, W, (float*)d_out);
}

// round 14
// speedup vs baseline: 3.1420x; 1.0130x over previous
#include <cuda_runtime.h>
#include <cuda_fp16.h>
#include <math.h>
#include <stdint.h>

#define M_TRAIN 4096
#define M_TEST  16384
#define DIN     128
#define HID     1024
#define NTREES  16
#define NINT    31
#define NLEAF   32
#define NCLS    10
#define NSPLIT  (NTREES*NINT)        /* 496 */
#define SW_ROWS (NTREES*NINT*DIN)    /* 63488 */
#define LF_ROWS (NTREES*NLEAF*NCLS)  /* 5120 */
#define MV_ROWS (SW_ROWS + NSPLIT + LF_ROWS + NTREES)  /* 69120 */

/* ---------------- scratch (static device memory; no allocs) -------------- */
__device__ __half g_C1[M_TRAIN*HID];   /* gemm1 out, fp16 */
__device__ __half g_C2[M_TRAIN*HID];   /* gemm2 out, fp16 */
__device__ __half g_H1[M_TRAIN*HID];   /* ln1 out */
__device__ __half g_Y2[M_TRAIN*HID];   /* ln2 out */
__device__ __half g_Xtr[M_TRAIN*DIN];
__device__ __half g_W1[HID*DIN];
__device__ __half g_W2[HID*HID];
__device__ __half g_Xte[M_TEST*DIN];
__device__ __half g_SW[SW_ROWS];
__device__ float  g_part[64*HID];
__device__ float  g_ctx[HID];
__device__ float  g_sb[NSPLIT];
__device__ float  g_lf[LF_ROWS];
__device__ float  g_tw[NTREES];
__device__ float  g_W[LF_ROWS];

/* ------------------------------ PTX helpers ------------------------------ */
__device__ __forceinline__ uint32_t cvta_sm(const void* p) {
    return (uint32_t)__cvta_generic_to_shared(p);
}
__device__ __forceinline__ void cp16(uint32_t dst, const void* src, int sz) {
    asm volatile("cp.async.cg.shared.global [%0], [%1], 16, %2;\n"
                 :: "r"(dst), "l"(src), "r"(sz));
}
__device__ __forceinline__ void cp_commit() {
    asm volatile("cp.async.commit_group;\n");
}
__device__ __forceinline__ void ldsm4(unsigned& r0, unsigned& r1,
                                      unsigned& r2, unsigned& r3, uint32_t a) {
    asm volatile("ldmatrix.sync.aligned.m8n8.x4.shared.b16 {%0,%1,%2,%3}, [%4];"
                 : "=r"(r0), "=r"(r1), "=r"(r2), "=r"(r3) : "r"(a));
}
__device__ __forceinline__ void mma_f16(float c[4], unsigned a0, unsigned a1,
                                        unsigned a2, unsigned a3,
                                        unsigned b0, unsigned b1)
{
    asm volatile(
        "mma.sync.aligned.m16n8k16.row.col.f32.f16.f16.f32 "
        "{%0,%1,%2,%3}, {%4,%5,%6,%7}, {%8,%9}, {%0,%1,%2,%3};"
        : "+f"(c[0]), "+f"(c[1]), "+f"(c[2]), "+f"(c[3])
        : "r"(a0), "r"(a1), "r"(a2), "r"(a3), "r"(b0), "r"(b1));
}
/* swizzled byte offset inside a (rows x 32) half tile, 64B rows */
__device__ __forceinline__ uint32_t swz(int r, int hb) {
    return (uint32_t)(r*64 + ((hb ^ ((r>>1)&3)) << 4));
}

/* ---------- ONE launch: convert all static inputs to fp16 ---------------- */
__global__ void cvt_all(const float* __restrict__ xtr, const float* __restrict__ w1,
                        const float* __restrict__ w2,  const float* __restrict__ xte,
                        __half* __restrict__ xtrh, __half* __restrict__ w1h,
                        __half* __restrict__ w2h,  __half* __restrict__ xteh)
{
    int b = blockIdx.x;
    const float* src;
    __half* dst;
    int base;
    if (b < 128)      { src = xtr; dst = xtrh; base = b; }
    else if (b < 160) { src = w1;  dst = w1h;  base = b - 128; }
    else if (b < 416) { src = w2;  dst = w2h;  base = b - 160; }
    else              { src = xte; dst = xteh; base = b - 416; }

    int i0 = base * 1024 + threadIdx.x;
    float4 v[4];
#pragma unroll
    for (int u = 0; u < 4; u++) v[u] = ((const float4*)src)[i0 + u*256];
#pragma unroll
    for (int u = 0; u < 4; u++) {
        int i = i0 + u*256;
        ((__half2*)dst)[i*2]   = __halves2half2(__float2half_rn(v[u].x),
                                                __float2half_rn(v[u].y));
        ((__half2*)dst)[i*2+1] = __halves2half2(__float2half_rn(v[u].z),
                                                __float2half_rn(v[u].w));
    }
}

/* ---- 128x128 fp16 GEMM, 512 threads, 32x32 warp tiles, fp16 out --------- */
/* BK=32, 3-stage cp.async, occ 2 (32 warps/SM). Stage 16KB: A@0, B@8K.      */
#define GSTAGE 16384
#define GNSTG  3

__global__ void __launch_bounds__(512, 2) gemm512(
    const __half* __restrict__ Ah, const __half* __restrict__ Bh,
    const float* __restrict__ bias, __half* __restrict__ C,
    int M, int N, int K)
{
    extern __shared__ char dynsm[];
    const uint32_t smem = cvta_sm(dynsm);
    const int tid = threadIdx.x, lane = tid & 31, warp = tid >> 5;
    const int g = lane >> 2, t = lane & 3;
    const int wm = warp & 3, wn = warp >> 2;        /* 4(m) x 4(n) warps */
    const int m0 = blockIdx.y * 128, n0 = blockIdx.x * 128;

    float c[2][4][4];
#pragma unroll
    for (int i = 0; i < 2; i++)
#pragma unroll
        for (int j = 0; j < 4; j++)
#pragma unroll
            for (int r = 0; r < 4; r++) c[i][j][r] = 0.f;

    const int kIters = K >> 5;

    auto load_stage = [&](int buf, int k0) {
        uint32_t sb = smem + buf * GSTAGE;
        int r = tid >> 2, hb = tid & 3;
        uint32_t so = swz(r, hb);
        cp16(sb + so,        Ah + (size_t)(m0 + r) * K + k0 + hb*8, 16);
        cp16(sb + 8192 + so, Bh + (size_t)(n0 + r) * K + k0 + hb*8, 16);
    };

    auto compute = [&](int buf) {
        uint32_t sb = smem + buf * GSTAGE;
        const int rl = lane & 15;
        const int hx = lane >> 4;
#pragma unroll
        for (int s = 0; s < 2; s++) {
            const int hb = s*2 + hx;
            unsigned bf[4][2];
#pragma unroll
            for (int j2 = 0; j2 < 2; j2++) {
                int row = wn*32 + j2*16 + rl;
                unsigned r0, r1, r2, r3;
                ldsm4(r0, r1, r2, r3, sb + 8192 + swz(row, hb));
                bf[j2*2][0]=r0; bf[j2*2][1]=r2; bf[j2*2+1][0]=r1; bf[j2*2+1][1]=r3;
            }
#pragma unroll
            for (int i = 0; i < 2; i++) {
                int row = wm*32 + i*16 + rl;
                unsigned a0,a1,a2,a3;
                ldsm4(a0,a1,a2,a3, sb + swz(row, hb));
#pragma unroll
                for (int j = 0; j < 4; j++)
                    mma_f16(c[i][j], a0,a1,a2,a3, bf[j][0], bf[j][1]);
            }
        }
    };

    load_stage(0, 0);
    cp_commit();
    load_stage(1, 32);
    cp_commit();
    for (int it = 0; it < kIters; it++) {
        if (it + 1 < kIters)
            asm volatile("cp.async.wait_group 1;\n" ::: "memory");
        else
            asm volatile("cp.async.wait_group 0;\n" ::: "memory");
        __syncthreads();
        compute(it % GNSTG);
        if (it + 2 < kIters) {
            load_stage((it+2) % GNSTG, (it+2)*32);
            cp_commit();
        }
    }

    /* fp16 store: half2 per (row, col-pair) */
#pragma unroll
    for (int i = 0; i < 2; i++) {
        int r0 = m0 + wm*32 + i*16 + g;
#pragma unroll
        for (int j = 0; j < 4; j++) {
            int col = n0 + wn*32 + j*8 + 2*t;
            float b0 = bias[col], b1 = bias[col+1];
            *(__half2*)&C[(size_t)r0     * N + col] =
                __halves2half2(__float2half_rn(c[i][j][0] + b0),
                               __float2half_rn(c[i][j][1] + b1));
            *(__half2*)&C[(size_t)(r0+8) * N + col] =
                __halves2half2(__float2half_rn(c[i][j][2] + b0),
                               __float2half_rn(c[i][j][3] + b1));
        }
    }
}

/* ==== FUSED dec GEMM + sigmoid + tree routing + class combine ============ */
#define DR_STAGE   36864
#define DR_SMEM    192768
#define TR_PITCH   513

__global__ void __launch_bounds__(512, 1) dec_route(
    const __half* __restrict__ Xte, const __half* __restrict__ SW,
    const float* __restrict__ sbias, const float* __restrict__ Wtab,
    float* __restrict__ out)
{
    extern __shared__ char dynsm[];
    const uint32_t smem = cvta_sm(dynsm);
    float* trans = (float*)dynsm;                     /* [64][513] */
    float* Wsh   = (float*)(dynsm + 131328);          /* [5120]    */
    float* pt    = (float*)(dynsm + 151808);          /* [64][16][10] */

    const int tid = threadIdx.x, lane = tid & 31, warp = tid >> 5;
    const int g = lane >> 2, t4 = lane & 3;
    const int wm = warp & 3, wn = warp >> 2;
    const int m0 = blockIdx.x * 64;

    for (int i = tid; i < LF_ROWS; i += 512) Wsh[i] = Wtab[i];

    float c[16][4];
#pragma unroll
    for (int j = 0; j < 16; j++)
#pragma unroll
        for (int r = 0; r < 4; r++) c[j][r] = 0.f;

    auto load_stage = [&](int buf, int k0) {
        uint32_t sb = smem + buf * DR_STAGE;
        if (tid < 256) {
            int r = tid >> 2, hb = tid & 3;
            cp16(sb + swz(r, hb), Xte + (size_t)(m0 + r) * DIN + k0 + hb*8, 16);
        }
#pragma unroll
        for (int x = 0; x < 4; x++) {
            int ch = tid + x*512;
            int r = ch >> 2, hb = ch & 3;
            int sz = (r < NSPLIT) ? 16 : 0;
            size_t gb = (size_t)(sz ? r : 0) * DIN + k0 + hb*8;
            cp16(sb + 4096 + swz(r, hb), SW + gb, sz);
        }
    };

    auto compute = [&](int buf) {
        uint32_t sb = smem + buf * DR_STAGE;
        const int rl = lane & 15, hx = lane >> 4;
#pragma unroll
        for (int s = 0; s < 2; s++) {
            const int hb = s*2 + hx;
            unsigned a0,a1,a2,a3;
            {
                int row = wm*16 + rl;
                ldsm4(a0,a1,a2,a3, sb + swz(row, hb));
            }
#pragma unroll
            for (int h2 = 0; h2 < 2; h2++) {
                unsigned bf[8][2];
#pragma unroll
                for (int j2 = 0; j2 < 4; j2++) {
                    int row = wn*128 + h2*64 + j2*16 + rl;
                    unsigned r0,r1,r2,r3;
                    ldsm4(r0,r1,r2,r3, sb + 4096 + swz(row, hb));
                    bf[j2*2][0]=r0; bf[j2*2][1]=r2;
                    bf[j2*2+1][0]=r1; bf[j2*2+1][1]=r3;
                }
#pragma unroll
                for (int j = 0; j < 8; j++)
                    mma_f16(c[h2*8+j], a0,a1,a2,a3, bf[j][0], bf[j][1]);
            }
        }
    };

    const int kIters = DIN >> 5;   /* 4 */
    load_stage(0, 0);
    cp_commit();
    load_stage(1, 32);
    cp_commit();
    for (int it = 0; it < kIters; it++) {
        if (it + 1 < kIters)
            asm volatile("cp.async.wait_group 1;\n" ::: "memory");
        else
            asm volatile("cp.async.wait_group 0;\n" ::: "memory");
        __syncthreads();
        compute(it % 3);
        if (it + 2 < kIters) {
            load_stage((it+2) % 3, (it+2)*32);
            cp_commit();
        }
    }

    __syncthreads();   /* stage smem reuse -> trans */

    {
        int r0 = wm*16 + g, r1 = r0 + 8;
#pragma unroll
        for (int j = 0; j < 16; j++) {
            int col = wn*128 + j*8 + 2*t4;
            float b0 = (col     < NSPLIT) ? sbias[col]   : 0.f;
            float b1 = (col + 1 < NSPLIT) ? sbias[col+1] : 0.f;
            trans[r0*TR_PITCH + col]   = 1.f/(1.f + __expf(-(c[j][0] + b0)));
            trans[r0*TR_PITCH + col+1] = 1.f/(1.f + __expf(-(c[j][1] + b1)));
            trans[r1*TR_PITCH + col]   = 1.f/(1.f + __expf(-(c[j][2] + b0)));
            trans[r1*TR_PITCH + col+1] = 1.f/(1.f + __expf(-(c[j][3] + b1)));
        }
    }
    __syncthreads();

#pragma unroll
    for (int it2 = 0; it2 < 2; it2++) {
        int idx = tid + it2*512;
        int r = idx & 63, t = idx >> 6;
        const float* d = &trans[r*TR_PITCH + t*NINT];
        float acc[NCLS];
#pragma unroll
        for (int cc = 0; cc < NCLS; cc++) acc[cc] = 0.f;
#pragma unroll
        for (int l = 0; l < NLEAF; l++) {
            float p = 1.f;
#pragma unroll
            for (int dd = 0; dd < 5; dd++) {
                int node = (1 << dd) - 1 + (l >> (5 - dd));
                int go   = (l >> (4 - dd)) & 1;
                float dv = d[node];
                p *= go ? dv : (1.f - dv);
            }
            const float* w = &Wsh[(t*NLEAF + l)*NCLS];
#pragma unroll
            for (int cc = 0; cc < NCLS; cc++) acc[cc] += p * w[cc];
        }
#pragma unroll
        for (int cc = 0; cc < NCLS; cc++) pt[(r*16 + t)*NCLS + cc] = acc[cc];
    }
    __syncthreads();

    for (int idx = tid; idx < 64*NCLS; idx += 512) {
        int r = idx / NCLS, cc = idx % NCLS;
        float s = 0.f;
#pragma unroll
        for (int t = 0; t < 16; t++) s += pt[(r*16 + t)*NCLS + cc];
        out[(size_t)(m0 + r)*NCLS + cc] = s;
    }
}

/* ------------- LayerNorm + ReLU, fp16 in -> fp16 out ---------------------- */
__global__ void ln_relu_h(const __half* __restrict__ X, __half* __restrict__ Y,
                          const float* __restrict__ gg, const float* __restrict__ bb)
{
    const int row = blockIdx.x, tid = threadIdx.x;   /* 128 threads */
    const uint4 raw = ((const uint4*)(X + (size_t)row * HID))[tid];
    const __half2* h2 = (const __half2*)&raw;
    float v[8];
#pragma unroll
    for (int k = 0; k < 4; k++) {
        float2 f = __half22float2(h2[k]);
        v[k*2] = f.x; v[k*2+1] = f.y;
    }
    float s = 0.f, q = 0.f;
#pragma unroll
    for (int k = 0; k < 8; k++) { s += v[k]; q += v[k]*v[k]; }
#pragma unroll
    for (int o = 16; o; o >>= 1) {
        s += __shfl_xor_sync(0xffffffffu, s, o);
        q += __shfl_xor_sync(0xffffffffu, q, o);
    }
    __shared__ float ss[4], qs[4];
    if ((tid & 31) == 0) { ss[tid >> 5] = s; qs[tid >> 5] = q; }
    __syncthreads();
    s = ss[0]+ss[1]+ss[2]+ss[3];
    q = qs[0]+qs[1]+qs[2]+qs[3];
    float mean = s * (1.f/HID);
    float inv  = rsqrtf(q * (1.f/HID) - mean*mean + 1e-5f);
    float4 g0 = ((const float4*)gg)[tid*2],   g1 = ((const float4*)gg)[tid*2+1];
    float4 b0 = ((const float4*)bb)[tid*2],   b1 = ((const float4*)bb)[tid*2+1];
    float gv[8] = {g0.x,g0.y,g0.z,g0.w,g1.x,g1.y,g1.z,g1.w};
    float bv[8] = {b0.x,b0.y,b0.z,b0.w,b1.x,b1.y,b1.z,b1.w};
    uint4 outp;
    __half2* o2 = (__half2*)&outp;
#pragma unroll
    for (int k = 0; k < 4; k++) {
        float y0 = fmaxf((v[k*2]   - mean)*inv*gv[k*2]   + bv[k*2],   0.f);
        float y1 = fmaxf((v[k*2+1] - mean)*inv*gv[k*2+1] + bv[k*2+1], 0.f);
        o2[k] = __halves2half2(__float2half_rn(y0), __float2half_rn(y1));
    }
    ((uint4*)(Y + (size_t)row * HID))[tid] = outp;
}

/* --------------------- column mean over rows -> ctx (fp16 in) ------------ */
__global__ void col_partial_h(const __half* __restrict__ X, float* __restrict__ part)
{
    int col2  = blockIdx.x * 256 + threadIdx.x;      /* half2 column index */
    int chunk = blockIdx.y;
    float2 s = make_float2(0.f, 0.f);
    int r0 = chunk * 64;
    for (int r = r0; r < r0 + 64; r++) {
        float2 f = __half22float2(((const __half2*)(X + (size_t)r * HID))[col2]);
        s.x += f.x; s.y += f.y;
    }
    *(float2*)&part[(size_t)chunk * HID + col2*2] = s;
}
__global__ void col_final(const float* __restrict__ part, float* __restrict__ ctx)
{
    int col = blockIdx.x * 256 + threadIdx.x;
    float s = 0.f;
    for (int c = 0; c < 64; c++) s += part[(size_t)c * HID + col];
    ctx[col] = s * (1.f / M_TRAIN);
}

/* ---------- ONE launch: all hypernet matvecs (warp-id dispatch) ----------- */
__global__ void matvec_all(const float* __restrict__ sw_w, const float* __restrict__ sw_b,
                           const float* __restrict__ sb_w, const float* __restrict__ sb_b,
                           const float* __restrict__ lf_w, const float* __restrict__ lf_b,
                           const float* __restrict__ tw_w, const float* __restrict__ tw_b,
                           const float* __restrict__ ctx,
                           __half* __restrict__ swh,
                           float* __restrict__ sbo, float* __restrict__ lfo,
                           float* __restrict__ two)
{
    int gw   = (blockIdx.x * blockDim.x + threadIdx.x) >> 5;
    int lane = threadIdx.x & 31;
    if (gw >= MV_ROWS) return;
    const float *W, *bias;
    int row, mode;
    if (gw < SW_ROWS)                  { W=sw_w; bias=sw_b; row=gw;                    mode=0; }
    else if (gw < SW_ROWS+NSPLIT)      { W=sb_w; bias=sb_b; row=gw-SW_ROWS;            mode=1; }
    else if (gw < SW_ROWS+NSPLIT+LF_ROWS) { W=lf_w; bias=lf_b; row=gw-SW_ROWS-NSPLIT;  mode=2; }
    else                               { W=tw_w; bias=tw_b; row=gw-SW_ROWS-NSPLIT-LF_ROWS; mode=3; }

    const float4* w4 = (const float4*)(W + (size_t)row * HID);
    const float4* c4 = (const float4*)ctx;
    float s = 0.f;
#pragma unroll
    for (int i = 0; i < 8; i++) {
        float4 a = w4[lane + 32*i];
        float4 c = __ldg(&c4[lane + 32*i]);
        s += a.x*c.x + a.y*c.y + a.z*c.z + a.w*c.w;
    }
#pragma unroll
    for (int o = 16; o; o >>= 1) s += __shfl_xor_sync(0xffffffffu, s, o);
    if (lane == 0) {
        float v = s + bias[row];
        if (mode == 0)      swh[row] = __float2half_rn(v);
        else if (mode == 1) sbo[row] = v;
        else if (mode == 2) lfo[row] = v;
        else                two[row] = v;
    }
}

/* ---- fold tree_w softmax + leaf softmax into one table W[t,l,c] --------- */
__global__ void make_W(const float* __restrict__ tw, const float* __restrict__ lf,
                       float* __restrict__ Wout)
{
    __shared__ float tws[NTREES];
    int tid = threadIdx.x;
    if (tid == 0) {
        float mx = -1e30f;
        for (int i = 0; i < NTREES; i++) mx = fmaxf(mx, tw[i]);
        float e[NTREES], s = 0.f;
        for (int i = 0; i < NTREES; i++) { e[i] = expf(tw[i] - mx); s += e[i]; }
        for (int i = 0; i < NTREES; i++) tws[i] = e[i] / s;
    }
    __syncthreads();
    if (tid < NTREES * NLEAF) {
        const float* L = lf + tid * NCLS;
        float mx = -1e30f;
        for (int c = 0; c < NCLS; c++) mx = fmaxf(mx, L[c]);
        float e[NCLS], s = 0.f;
        for (int c = 0; c < NCLS; c++) { e[c] = expf(L[c] - mx); s += e[c]; }
        float scale = tws[tid >> 5] / s;
        for (int c = 0; c < NCLS; c++) Wout[tid * NCLS + c] = e[c] * scale;
    }
}

/* ------------------------------- launch ---------------------------------- */
extern "C" void kernel_launch(void* const* d_in, const int* in_sizes, int n_in,
                              void* d_out, int out_size)
{
    const float* X_train = (const float*)d_in[0];
    const float* X_test  = (const float*)d_in[1];
    const float* enc_w1  = (const float*)d_in[2];
    const float* enc_b1  = (const float*)d_in[3];
    const float* ln1_g   = (const float*)d_in[4];
    const float* ln1_b   = (const float*)d_in[5];
    const float* enc_w2  = (const float*)d_in[6];
    const float* enc_b2  = (const float*)d_in[7];
    const float* ln2_g   = (const float*)d_in[8];
    const float* ln2_b   = (const float*)d_in[9];
    const float* sw_w    = (const float*)d_in[10];
    const float* sw_b    = (const float*)d_in[11];
    const float* sb_w    = (const float*)d_in[12];
    const float* sb_b    = (const float*)d_in[13];
    const float* lf_w    = (const float*)d_in[14];
    const float* lf_b    = (const float*)d_in[15];
    const float* tw_w    = (const float*)d_in[16];
    const float* tw_b    = (const float*)d_in[17];

    float *part, *ctx, *sb, *lf, *tw, *W;
    __half *C1, *C2, *H1, *Y2, *Xtr, *W1, *W2, *Xte, *SW;
    cudaGetSymbolAddress((void**)&C1,   g_C1);
    cudaGetSymbolAddress((void**)&C2,   g_C2);
    cudaGetSymbolAddress((void**)&H1,   g_H1);
    cudaGetSymbolAddress((void**)&Y2,   g_Y2);
    cudaGetSymbolAddress((void**)&Xtr,  g_Xtr);
    cudaGetSymbolAddress((void**)&W1,   g_W1);
    cudaGetSymbolAddress((void**)&W2,   g_W2);
    cudaGetSymbolAddress((void**)&Xte,  g_Xte);
    cudaGetSymbolAddress((void**)&SW,   g_SW);
    cudaGetSymbolAddress((void**)&part, g_part);
    cudaGetSymbolAddress((void**)&ctx,  g_ctx);
    cudaGetSymbolAddress((void**)&sb,   g_sb);
    cudaGetSymbolAddress((void**)&lf,   g_lf);
    cudaGetSymbolAddress((void**)&tw,   g_tw);
    cudaGetSymbolAddress((void**)&W,    g_W);

    cudaFuncSetAttribute((const void*)gemm512,
                         cudaFuncAttributeMaxDynamicSharedMemorySize, GNSTG*GSTAGE);
    cudaFuncSetAttribute((const void*)dec_route,
                         cudaFuncAttributeMaxDynamicSharedMemorySize, DR_SMEM);

    /* one launch: convert everything to fp16 */
    cvt_all<<<928, 256>>>(X_train, enc_w1, enc_w2, X_test, Xtr, W1, W2, Xte);

    /* encoder: fp16 GEMMs with fp16 intermediates */
    gemm512<<<dim3(HID/128, M_TRAIN/128), 512, GNSTG*GSTAGE>>>(
        Xtr, W1, enc_b1, C1, M_TRAIN, HID, DIN);
    ln_relu_h<<<M_TRAIN, 128>>>(C1, H1, ln1_g, ln1_b);
    gemm512<<<dim3(HID/128, M_TRAIN/128), 512, GNSTG*GSTAGE>>>(
        H1, W2, enc_b2, C2, M_TRAIN, HID, HID);
    ln_relu_h<<<M_TRAIN, 128>>>(C2, Y2, ln2_g, ln2_b);

    /* ctx = mean over rows (fp16 input) */
    col_partial_h<<<dim3(HID/512, 64), 256>>>(Y2, part);
    col_final<<<HID/256, 256>>>(part, ctx);

    /* ALL hypernet matvecs in one launch (sw emits fp16 directly) */
    matvec_all<<<(MV_ROWS*32 + 255)/256, 256>>>(
        sw_w, sw_b, sb_w, sb_b, lf_w, lf_b, tw_w, tw_b, ctx,
        SW, sb, lf, tw);

    /* fold softmaxes */
    make_W<<<1, 512>>>(tw, lf, W);

    /* FUSED: dec GEMM + sigmoid + routing + class combine -> final output */
    dec_route<<<M_TEST/64, 512, DR_SMEM>>>(Xte, SW, sb, W, (float*)d_out);
}

// round 15
// speedup vs baseline: 3.1833x; 1.0132x over previous
#include <cuda_runtime.h>
#include <cuda_fp16.h>
#include <math.h>
#include <stdint.h>

#define M_TRAIN 4096
#define M_TEST  16384
#define DIN     128
#define HID     1024
#define NTREES  16
#define NINT    31
#define NLEAF   32
#define NCLS    10
#define NSPLIT  (NTREES*NINT)        /* 496 */
#define SW_ROWS (NTREES*NINT*DIN)    /* 63488 */
#define LF_ROWS (NTREES*NLEAF*NCLS)  /* 5120 */
#define MV_ROWS (SW_ROWS + NSPLIT + LF_ROWS + NTREES)  /* 69120 */

/* ---------------- scratch (static device memory; no allocs) -------------- */
__device__ __half g_C1[M_TRAIN*HID];
__device__ __half g_C2[M_TRAIN*HID];
__device__ __half g_H1[M_TRAIN*HID];
__device__ __half g_Y2[M_TRAIN*HID];
__device__ __half g_Xtr[M_TRAIN*DIN];
__device__ __half g_W1[HID*DIN];
__device__ __half g_W2[HID*HID];
__device__ __half g_Xte[M_TEST*DIN];
__device__ __half g_SW[SW_ROWS];
__device__ float  g_part[64*HID];
__device__ float  g_ctx[HID];
__device__ float  g_sb[NSPLIT];
__device__ float  g_lf[LF_ROWS];
__device__ float  g_tw[NTREES];
__device__ float  g_W[LF_ROWS];

/* ------------------------------ PTX helpers ------------------------------ */
__device__ __forceinline__ uint32_t cvta_sm(const void* p) {
    return (uint32_t)__cvta_generic_to_shared(p);
}
__device__ __forceinline__ void cp16(uint32_t dst, const void* src, int sz) {
    asm volatile("cp.async.cg.shared.global [%0], [%1], 16, %2;\n"
                 :: "r"(dst), "l"(src), "r"(sz));
}
__device__ __forceinline__ void cp_commit() {
    asm volatile("cp.async.commit_group;\n");
}
__device__ __forceinline__ void ldsm4(unsigned& r0, unsigned& r1,
                                      unsigned& r2, unsigned& r3, uint32_t a) {
    asm volatile("ldmatrix.sync.aligned.m8n8.x4.shared.b16 {%0,%1,%2,%3}, [%4];"
                 : "=r"(r0), "=r"(r1), "=r"(r2), "=r"(r3) : "r"(a));
}
__device__ __forceinline__ void mma_f16(float c[4], unsigned a0, unsigned a1,
                                        unsigned a2, unsigned a3,
                                        unsigned b0, unsigned b1)
{
    asm volatile(
        "mma.sync.aligned.m16n8k16.row.col.f32.f16.f16.f32 "
        "{%0,%1,%2,%3}, {%4,%5,%6,%7}, {%8,%9}, {%0,%1,%2,%3};"
        : "+f"(c[0]), "+f"(c[1]), "+f"(c[2]), "+f"(c[3])
        : "r"(a0), "r"(a1), "r"(a2), "r"(a3), "r"(b0), "r"(b1));
}
/* swizzled byte offset inside a (rows x 32) half tile, 64B rows */
__device__ __forceinline__ uint32_t swz(int r, int hb) {
    return (uint32_t)(r*64 + ((hb ^ ((r>>1)&3)) << 4));
}

/* ---------- ONE launch: convert all static inputs to fp16 ---------------- */
__global__ void cvt_all(const float* __restrict__ xtr, const float* __restrict__ w1,
                        const float* __restrict__ w2,  const float* __restrict__ xte,
                        __half* __restrict__ xtrh, __half* __restrict__ w1h,
                        __half* __restrict__ w2h,  __half* __restrict__ xteh)
{
    int b = blockIdx.x;
    const float* src;
    __half* dst;
    int base;
    if (b < 128)      { src = xtr; dst = xtrh; base = b; }
    else if (b < 160) { src = w1;  dst = w1h;  base = b - 128; }
    else if (b < 416) { src = w2;  dst = w2h;  base = b - 160; }
    else              { src = xte; dst = xteh; base = b - 416; }

    int i0 = base * 1024 + threadIdx.x;
    float4 v[4];
#pragma unroll
    for (int u = 0; u < 4; u++) v[u] = ((const float4*)src)[i0 + u*256];
#pragma unroll
    for (int u = 0; u < 4; u++) {
        int i = i0 + u*256;
        ((__half2*)dst)[i*2]   = __halves2half2(__float2half_rn(v[u].x),
                                                __float2half_rn(v[u].y));
        ((__half2*)dst)[i*2+1] = __halves2half2(__float2half_rn(v[u].z),
                                                __float2half_rn(v[u].w));
    }
}

/* ---- 128x128 fp16 GEMM, 512 threads, 32x32 warp tiles, fp16 out --------- */
#define GSTAGE 16384
#define GNSTG  3

__global__ void __launch_bounds__(512, 2) gemm512(
    const __half* __restrict__ Ah, const __half* __restrict__ Bh,
    const float* __restrict__ bias, __half* __restrict__ C,
    int M, int N, int K)
{
    extern __shared__ char dynsm[];
    const uint32_t smem = cvta_sm(dynsm);
    const int tid = threadIdx.x, lane = tid & 31, warp = tid >> 5;
    const int g = lane >> 2, t = lane & 3;
    const int wm = warp & 3, wn = warp >> 2;
    const int m0 = blockIdx.y * 128, n0 = blockIdx.x * 128;

    float c[2][4][4];
#pragma unroll
    for (int i = 0; i < 2; i++)
#pragma unroll
        for (int j = 0; j < 4; j++)
#pragma unroll
            for (int r = 0; r < 4; r++) c[i][j][r] = 0.f;

    const int kIters = K >> 5;

    auto load_stage = [&](int buf, int k0) {
        uint32_t sb = smem + buf * GSTAGE;
        int r = tid >> 2, hb = tid & 3;
        uint32_t so = swz(r, hb);
        cp16(sb + so,        Ah + (size_t)(m0 + r) * K + k0 + hb*8, 16);
        cp16(sb + 8192 + so, Bh + (size_t)(n0 + r) * K + k0 + hb*8, 16);
    };

    auto compute = [&](int buf) {
        uint32_t sb = smem + buf * GSTAGE;
        const int rl = lane & 15;
        const int hx = lane >> 4;
#pragma unroll
        for (int s = 0; s < 2; s++) {
            const int hb = s*2 + hx;
            unsigned bf[4][2];
#pragma unroll
            for (int j2 = 0; j2 < 2; j2++) {
                int row = wn*32 + j2*16 + rl;
                unsigned r0, r1, r2, r3;
                ldsm4(r0, r1, r2, r3, sb + 8192 + swz(row, hb));
                bf[j2*2][0]=r0; bf[j2*2][1]=r2; bf[j2*2+1][0]=r1; bf[j2*2+1][1]=r3;
            }
#pragma unroll
            for (int i = 0; i < 2; i++) {
                int row = wm*32 + i*16 + rl;
                unsigned a0,a1,a2,a3;
                ldsm4(a0,a1,a2,a3, sb + swz(row, hb));
#pragma unroll
                for (int j = 0; j < 4; j++)
                    mma_f16(c[i][j], a0,a1,a2,a3, bf[j][0], bf[j][1]);
            }
        }
    };

    load_stage(0, 0);
    cp_commit();
    load_stage(1, 32);
    cp_commit();
    for (int it = 0; it < kIters; it++) {
        if (it + 1 < kIters)
            asm volatile("cp.async.wait_group 1;\n" ::: "memory");
        else
            asm volatile("cp.async.wait_group 0;\n" ::: "memory");
        __syncthreads();
        compute(it % GNSTG);
        if (it + 2 < kIters) {
            load_stage((it+2) % GNSTG, (it+2)*32);
            cp_commit();
        }
    }

#pragma unroll
    for (int i = 0; i < 2; i++) {
        int r0 = m0 + wm*32 + i*16 + g;
#pragma unroll
        for (int j = 0; j < 4; j++) {
            int col = n0 + wn*32 + j*8 + 2*t;
            float b0 = bias[col], b1 = bias[col+1];
            *(__half2*)&C[(size_t)r0     * N + col] =
                __halves2half2(__float2half_rn(c[i][j][0] + b0),
                               __float2half_rn(c[i][j][1] + b1));
            *(__half2*)&C[(size_t)(r0+8) * N + col] =
                __halves2half2(__float2half_rn(c[i][j][2] + b0),
                               __float2half_rn(c[i][j][3] + b1));
        }
    }
}

/* ==== FUSED dec GEMM + sigmoid + routing, 32-row CTA, occupancy 2 ======== */
/* 512 threads (2m x 8n warps, warp tile 16x64). 512 CTAs.                   */
/* smem: stages 2x34816=[0,69632) reused by trans f32[32][513]=[0,65664);    */
/*       Wsh [69632,+20480); pt [90112,+20480). total 110592 -> occ 2.       */
#define DR_STAGE  34816
#define DR_SMEM   110592
#define TR_PITCH  513

__global__ void __launch_bounds__(512, 2) dec_route(
    const __half* __restrict__ Xte, const __half* __restrict__ SW,
    const float* __restrict__ sbias, const float* __restrict__ Wtab,
    float* __restrict__ out)
{
    extern __shared__ char dynsm[];
    const uint32_t smem = cvta_sm(dynsm);
    float* trans = (float*)dynsm;                     /* [32][513] */
    float* Wsh   = (float*)(dynsm + 69632);           /* [5120]    */
    float* pt    = (float*)(dynsm + 90112);           /* [32][16][10] */

    const int tid = threadIdx.x, lane = tid & 31, warp = tid >> 5;
    const int g = lane >> 2, t4 = lane & 3;
    const int wm = warp & 1, wn = warp >> 1;          /* 2(m) x 8(n) */
    const int m0 = blockIdx.x * 32;

    for (int i = tid; i < LF_ROWS; i += 512) Wsh[i] = Wtab[i];

    float c[8][4];
#pragma unroll
    for (int j = 0; j < 8; j++)
#pragma unroll
        for (int r = 0; r < 4; r++) c[j][r] = 0.f;

    auto load_stage = [&](int buf, int k0) {
        uint32_t sb = smem + buf * DR_STAGE;
        if (tid < 128) {                              /* A: 32 rows x 4 chunks */
            int r = tid >> 2, hb = tid & 3;
            cp16(sb + swz(r, hb), Xte + (size_t)(m0 + r) * DIN + k0 + hb*8, 16);
        }
#pragma unroll
        for (int x = 0; x < 4; x++) {                 /* B: 512 rows x 4 chunks */
            int ch = tid + x*512;
            int r = ch >> 2, hb = ch & 3;
            int sz = (r < NSPLIT) ? 16 : 0;
            size_t gb = (size_t)(sz ? r : 0) * DIN + k0 + hb*8;
            cp16(sb + 2048 + swz(r, hb), SW + gb, sz);
        }
    };

    auto compute = [&](int buf) {
        uint32_t sb = smem + buf * DR_STAGE;
        const int rl = lane & 15, hx = lane >> 4;
#pragma unroll
        for (int s = 0; s < 2; s++) {
            const int hb = s*2 + hx;
            unsigned a0,a1,a2,a3;
            {
                int row = wm*16 + rl;
                ldsm4(a0,a1,a2,a3, sb + swz(row, hb));
            }
            unsigned bf[8][2];
#pragma unroll
            for (int j2 = 0; j2 < 4; j2++) {
                int row = wn*64 + j2*16 + rl;
                unsigned r0,r1,r2,r3;
                ldsm4(r0,r1,r2,r3, sb + 2048 + swz(row, hb));
                bf[j2*2][0]=r0; bf[j2*2][1]=r2;
                bf[j2*2+1][0]=r1; bf[j2*2+1][1]=r3;
            }
#pragma unroll
            for (int j = 0; j < 8; j++)
                mma_f16(c[j], a0,a1,a2,a3, bf[j][0], bf[j][1]);
        }
    };

    const int kIters = DIN >> 5;   /* 4 */
    load_stage(0, 0);
    cp_commit();
    load_stage(1, 32);
    cp_commit();
    for (int it = 0; it < kIters; it++) {
        if (it + 1 < kIters)
            asm volatile("cp.async.wait_group 1;\n" ::: "memory");
        else
            asm volatile("cp.async.wait_group 0;\n" ::: "memory");
        __syncthreads();
        compute(it & 1);
        __syncthreads();               /* 2 stages: guard reuse */
        if (it + 2 < kIters) {
            load_stage(it & 1, (it+2)*32);
            cp_commit();
        }
    }

    __syncthreads();   /* stage smem reuse -> trans */

    /* sigmoid + stage to trans[row][col] */
    {
        int r0 = wm*16 + g, r1 = r0 + 8;
#pragma unroll
        for (int j = 0; j < 8; j++) {
            int col = wn*64 + j*8 + 2*t4;
            float b0 = (col     < NSPLIT) ? sbias[col]   : 0.f;
            float b1 = (col + 1 < NSPLIT) ? sbias[col+1] : 0.f;
            trans[r0*TR_PITCH + col]   = 1.f/(1.f + __expf(-(c[j][0] + b0)));
            trans[r0*TR_PITCH + col+1] = 1.f/(1.f + __expf(-(c[j][1] + b1)));
            trans[r1*TR_PITCH + col]   = 1.f/(1.f + __expf(-(c[j][2] + b0)));
            trans[r1*TR_PITCH + col+1] = 1.f/(1.f + __expf(-(c[j][3] + b1)));
        }
    }
    __syncthreads();

    /* routing: warp = tree (16 warps), lane = row (32 rows).
       Wsh reads broadcast; trans reads conflict-free (pitch 513). */
    {
        const int t = warp, r = lane;
        const float* d = &trans[r*TR_PITCH + t*NINT];
        float acc[NCLS];
#pragma unroll
        for (int cc = 0; cc < NCLS; cc++) acc[cc] = 0.f;
#pragma unroll
        for (int l = 0; l < NLEAF; l++) {
            float p = 1.f;
#pragma unroll
            for (int dd = 0; dd < 5; dd++) {
                int node = (1 << dd) - 1 + (l >> (5 - dd));
                int go   = (l >> (4 - dd)) & 1;
                float dv = d[node];
                p *= go ? dv : (1.f - dv);
            }
            const float* w = &Wsh[(t*NLEAF + l)*NCLS];
#pragma unroll
            for (int cc = 0; cc < NCLS; cc++) acc[cc] += p * w[cc];
        }
#pragma unroll
        for (int cc = 0; cc < NCLS; cc++) pt[(r*16 + t)*NCLS + cc] = acc[cc];
    }
    __syncthreads();

    /* deterministic per-row reduction over 16 trees (320 items) */
    if (tid < 32*NCLS) {
        int r = tid / NCLS, cc = tid % NCLS;
        float s = 0.f;
#pragma unroll
        for (int t = 0; t < 16; t++) s += pt[(r*16 + t)*NCLS + cc];
        out[(size_t)(m0 + r)*NCLS + cc] = s;
    }
}

/* ------------- LayerNorm + ReLU, fp16 in -> fp16 out ---------------------- */
__global__ void ln_relu_h(const __half* __restrict__ X, __half* __restrict__ Y,
                          const float* __restrict__ gg, const float* __restrict__ bb)
{
    const int row = blockIdx.x, tid = threadIdx.x;   /* 128 threads */
    const uint4 raw = ((const uint4*)(X + (size_t)row * HID))[tid];
    const __half2* h2 = (const __half2*)&raw;
    float v[8];
#pragma unroll
    for (int k = 0; k < 4; k++) {
        float2 f = __half22float2(h2[k]);
        v[k*2] = f.x; v[k*2+1] = f.y;
    }
    float s = 0.f, q = 0.f;
#pragma unroll
    for (int k = 0; k < 8; k++) { s += v[k]; q += v[k]*v[k]; }
#pragma unroll
    for (int o = 16; o; o >>= 1) {
        s += __shfl_xor_sync(0xffffffffu, s, o);
        q += __shfl_xor_sync(0xffffffffu, q, o);
    }
    __shared__ float ss[4], qs[4];
    if ((tid & 31) == 0) { ss[tid >> 5] = s; qs[tid >> 5] = q; }
    __syncthreads();
    s = ss[0]+ss[1]+ss[2]+ss[3];
    q = qs[0]+qs[1]+qs[2]+qs[3];
    float mean = s * (1.f/HID);
    float inv  = rsqrtf(q * (1.f/HID) - mean*mean + 1e-5f);
    float4 g0 = ((const float4*)gg)[tid*2],   g1 = ((const float4*)gg)[tid*2+1];
    float4 b0 = ((const float4*)bb)[tid*2],   b1 = ((const float4*)bb)[tid*2+1];
    float gv[8] = {g0.x,g0.y,g0.z,g0.w,g1.x,g1.y,g1.z,g1.w};
    float bv[8] = {b0.x,b0.y,b0.z,b0.w,b1.x,b1.y,b1.z,b1.w};
    uint4 outp;
    __half2* o2 = (__half2*)&outp;
#pragma unroll
    for (int k = 0; k < 4; k++) {
        float y0 = fmaxf((v[k*2]   - mean)*inv*gv[k*2]   + bv[k*2],   0.f);
        float y1 = fmaxf((v[k*2+1] - mean)*inv*gv[k*2+1] + bv[k*2+1], 0.f);
        o2[k] = __halves2half2(__float2half_rn(y0), __float2half_rn(y1));
    }
    ((uint4*)(Y + (size_t)row * HID))[tid] = outp;
}

/* --------------------- column mean over rows -> ctx (fp16 in) ------------ */
__global__ void col_partial_h(const __half* __restrict__ X, float* __restrict__ part)
{
    int col2  = blockIdx.x * 256 + threadIdx.x;
    int chunk = blockIdx.y;
    float2 s = make_float2(0.f, 0.f);
    int r0 = chunk * 64;
    for (int r = r0; r < r0 + 64; r++) {
        float2 f = __half22float2(((const __half2*)(X + (size_t)r * HID))[col2]);
        s.x += f.x; s.y += f.y;
    }
    *(float2*)&part[(size_t)chunk * HID + col2*2] = s;
}
__global__ void col_final(const float* __restrict__ part, float* __restrict__ ctx)
{
    int col = blockIdx.x * 256 + threadIdx.x;
    float s = 0.f;
    for (int c = 0; c < 64; c++) s += part[(size_t)c * HID + col];
    ctx[col] = s * (1.f / M_TRAIN);
}

/* ---------- ONE launch: all hypernet matvecs (warp-id dispatch) ----------- */
__global__ void matvec_all(const float* __restrict__ sw_w, const float* __restrict__ sw_b,
                           const float* __restrict__ sb_w, const float* __restrict__ sb_b,
                           const float* __restrict__ lf_w, const float* __restrict__ lf_b,
                           const float* __restrict__ tw_w, const float* __restrict__ tw_b,
                           const float* __restrict__ ctx,
                           __half* __restrict__ swh,
                           float* __restrict__ sbo, float* __restrict__ lfo,
                           float* __restrict__ two)
{
    int gw   = (blockIdx.x * blockDim.x + threadIdx.x) >> 5;
    int lane = threadIdx.x & 31;
    if (gw >= MV_ROWS) return;
    const float *W, *bias;
    int row, mode;
    if (gw < SW_ROWS)                  { W=sw_w; bias=sw_b; row=gw;                    mode=0; }
    else if (gw < SW_ROWS+NSPLIT)      { W=sb_w; bias=sb_b; row=gw-SW_ROWS;            mode=1; }
    else if (gw < SW_ROWS+NSPLIT+LF_ROWS) { W=lf_w; bias=lf_b; row=gw-SW_ROWS-NSPLIT;  mode=2; }
    else                               { W=tw_w; bias=tw_b; row=gw-SW_ROWS-NSPLIT-LF_ROWS; mode=3; }

    const float4* w4 = (const float4*)(W + (size_t)row * HID);
    const float4* c4 = (const float4*)ctx;
    float s = 0.f;
#pragma unroll
    for (int i = 0; i < 8; i++) {
        float4 a = w4[lane + 32*i];
        float4 c = __ldg(&c4[lane + 32*i]);
        s += a.x*c.x + a.y*c.y + a.z*c.z + a.w*c.w;
    }
#pragma unroll
    for (int o = 16; o; o >>= 1) s += __shfl_xor_sync(0xffffffffu, s, o);
    if (lane == 0) {
        float v = s + bias[row];
        if (mode == 0)      swh[row] = __float2half_rn(v);
        else if (mode == 1) sbo[row] = v;
        else if (mode == 2) lfo[row] = v;
        else                two[row] = v;
    }
}

/* ---- fold tree_w softmax + leaf softmax into one table W[t,l,c] --------- */
__global__ void make_W(const float* __restrict__ tw, const float* __restrict__ lf,
                       float* __restrict__ Wout)
{
    __shared__ float tws[NTREES];
    int tid = threadIdx.x;
    if (tid == 0) {
        float mx = -1e30f;
        for (int i = 0; i < NTREES; i++) mx = fmaxf(mx, tw[i]);
        float e[NTREES], s = 0.f;
        for (int i = 0; i < NTREES; i++) { e[i] = expf(tw[i] - mx); s += e[i]; }
        for (int i = 0; i < NTREES; i++) tws[i] = e[i] / s;
    }
    __syncthreads();
    if (tid < NTREES * NLEAF) {
        const float* L = lf + tid * NCLS;
        float mx = -1e30f;
        for (int c = 0; c < NCLS; c++) mx = fmaxf(mx, L[c]);
        float e[NCLS], s = 0.f;
        for (int c = 0; c < NCLS; c++) { e[c] = expf(L[c] - mx); s += e[c]; }
        float scale = tws[tid >> 5] / s;
        for (int c = 0; c < NCLS; c++) Wout[tid * NCLS + c] = e[c] * scale;
    }
}

/* ------------------------------- launch ---------------------------------- */
extern "C" void kernel_launch(void* const* d_in, const int* in_sizes, int n_in,
                              void* d_out, int out_size)
{
    const float* X_train = (const float*)d_in[0];
    const float* X_test  = (const float*)d_in[1];
    const float* enc_w1  = (const float*)d_in[2];
    const float* enc_b1  = (const float*)d_in[3];
    const float* ln1_g   = (const float*)d_in[4];
    const float* ln1_b   = (const float*)d_in[5];
    const float* enc_w2  = (const float*)d_in[6];
    const float* enc_b2  = (const float*)d_in[7];
    const float* ln2_g   = (const float*)d_in[8];
    const float* ln2_b   = (const float*)d_in[9];
    const float* sw_w    = (const float*)d_in[10];
    const float* sw_b    = (const float*)d_in[11];
    const float* sb_w    = (const float*)d_in[12];
    const float* sb_b    = (const float*)d_in[13];
    const float* lf_w    = (const float*)d_in[14];
    const float* lf_b    = (const float*)d_in[15];
    const float* tw_w    = (const float*)d_in[16];
    const float* tw_b    = (const float*)d_in[17];

    float *part, *ctx, *sb, *lf, *tw, *W;
    __half *C1, *C2, *H1, *Y2, *Xtr, *W1, *W2, *Xte, *SW;
    cudaGetSymbolAddress((void**)&C1,   g_C1);
    cudaGetSymbolAddress((void**)&C2,   g_C2);
    cudaGetSymbolAddress((void**)&H1,   g_H1);
    cudaGetSymbolAddress((void**)&Y2,   g_Y2);
    cudaGetSymbolAddress((void**)&Xtr,  g_Xtr);
    cudaGetSymbolAddress((void**)&W1,   g_W1);
    cudaGetSymbolAddress((void**)&W2,   g_W2);
    cudaGetSymbolAddress((void**)&Xte,  g_Xte);
    cudaGetSymbolAddress((void**)&SW,   g_SW);
    cudaGetSymbolAddress((void**)&part, g_part);
    cudaGetSymbolAddress((void**)&ctx,  g_ctx);
    cudaGetSymbolAddress((void**)&sb,   g_sb);
    cudaGetSymbolAddress((void**)&lf,   g_lf);
    cudaGetSymbolAddress((void**)&tw,   g_tw);
    cudaGetSymbolAddress((void**)&W,    g_W);

    cudaFuncSetAttribute((const void*)gemm512,
                         cudaFuncAttributeMaxDynamicSharedMemorySize, GNSTG*GSTAGE);
    cudaFuncSetAttribute((const void*)dec_route,
                         cudaFuncAttributeMaxDynamicSharedMemorySize, DR_SMEM);

    /* one launch: convert everything to fp16 */
    cvt_all<<<928, 256>>>(X_train, enc_w1, enc_w2, X_test, Xtr, W1, W2, Xte);

    /* encoder: fp16 GEMMs with fp16 intermediates */
    gemm512<<<dim3(HID/128, M_TRAIN/128), 512, GNSTG*GSTAGE>>>(
        Xtr, W1, enc_b1, C1, M_TRAIN, HID, DIN);
    ln_relu_h<<<M_TRAIN, 128>>>(C1, H1, ln1_g, ln1_b);
    gemm512<<<dim3(HID/128, M_TRAIN/128), 512, GNSTG*GSTAGE>>>(
        H1, W2, enc_b2, C2, M_TRAIN, HID, HID);
    ln_relu_h<<<M_TRAIN, 128>>>(C2, Y2, ln2_g, ln2_b);

    /* ctx = mean over rows (fp16 input) */
    col_partial_h<<<dim3(HID/512, 64), 256>>>(Y2, part);
    col_final<<<HID/256, 256>>>(part, ctx);

    /* ALL hypernet matvecs in one launch (sw emits fp16 directly) */
    matvec_all<<<(MV_ROWS*32 + 255)/256, 256>>>(
        sw_w, sw_b, sb_w, sb_b, lf_w, lf_b, tw_w, tw_b, ctx,
        SW, sb, lf, tw);

    /* fold softmaxes */
    make_W<<<1, 512>>>(tw, lf, W);

    /* FUSED: dec GEMM + sigmoid + routing -> final output (occ 2, 512 CTAs) */
    dec_route<<<M_TEST/32, 512, DR_SMEM>>>(Xte, SW, sb, W, (float*)d_out);
}